// round 1
// baseline (speedup 1.0000x reference)
#include <cuda_runtime.h>
#include <math.h>

#define Nn 256
#define Pp 4
#define Sr 40
#define Enn 60
#define Ee 105
#define Dd 1024
#define Hh 8
#define Tt 3
#define DHd 128
#define HT 24           // H*T
#define NEGV -1e30f

// ---------------- scratch (device globals; no allocations allowed) ----------------
static __device__ float g_X [Nn*Ee*Dd];        // concat input      (110 MB)
static __device__ float g_mask[Nn*Ee];
static __device__ float g_R [HT*Nn*256];       // relu(q @ qW1)
static __device__ float g_V [2*HT*Nn*DHd];     // v1 (r=ht), v2 (r=24+ht)
static __device__ float g_U [2*HT*Nn*Dd];      // u = W @ v
static __device__ float g_F [2*HT*Nn*Ee];      // f1, f2
static __device__ float g_WB[Dd*Dd];           // W[:,T-1] repacked (d, h*128+k)
static __device__ float g_HL[Nn*Ee*Dd];        // h_last (pre-mask) (110 MB)

// ---------------- K1: concat x ----------------
__global__ void k_concat(const float* __restrict__ q, const float* __restrict__ para,
                         const float* __restrict__ sent, const float* __restrict__ ent) {
    int idx = blockIdx.x * blockDim.x + threadIdx.x;
    if (idx >= Nn*Ee*Dd) return;
    int d  = idx & (Dd-1);
    int ne = idx >> 10;
    int e  = ne % Ee;
    int n  = ne / Ee;
    float v;
    if (e == 0)              v = q   [n*Dd + d];
    else if (e < 1+Pp)       v = para[(n*Pp  + (e-1))*Dd + d];
    else if (e < 1+Pp+Sr)    v = sent[(n*Sr  + (e-1-Pp))*Dd + d];
    else                     v = ent [(n*Enn + (e-1-Pp-Sr))*Dd + d];
    g_X[idx] = v;
}

__global__ void k_mask(const float* __restrict__ pm, const float* __restrict__ sm_,
                       const float* __restrict__ em) {
    int idx = blockIdx.x * blockDim.x + threadIdx.x;
    if (idx >= Nn*Ee) return;
    int e = idx % Ee, n = idx / Ee;
    float v;
    if (e == 0)            v = 1.f;
    else if (e < 1+Pp)     v = pm[n*Pp  + e-1];
    else if (e < 1+Pp+Sr)  v = sm_[n*Sr + e-1-Pp];
    else                   v = em[n*Enn + e-1-Pp-Sr];
    g_mask[idx] = v;
}

// ---------------- K2a: R = relu(Q @ qW1[ht]),  M=256 N=256 K=1024 ----------------
__global__ __launch_bounds__(256) void k_gemm_qw1(const float* __restrict__ q,
                                                  const float* __restrict__ qW1) {
    int ht = blockIdx.z;
    int m0 = blockIdx.x*64, n0 = blockIdx.y*64;
    __shared__ float As[16][64];
    __shared__ float Bs[16][64];
    int tid = threadIdx.x;
    int tr = tid/16, tc = tid%16;
    int lm = tid/4,  lk4 = (tid%4)*4;
    int lbk = tid/16, lbc4 = (tid%16)*4;
    const float* Bbase = qW1 + ht*Dd*256;
    float acc[4][4] = {};
    for (int k0 = 0; k0 < Dd; k0 += 16) {
        float4 av = *(const float4*)(q + (m0+lm)*Dd + k0 + lk4);
        As[lk4+0][lm]=av.x; As[lk4+1][lm]=av.y; As[lk4+2][lm]=av.z; As[lk4+3][lm]=av.w;
        float4 bv = *(const float4*)(Bbase + (k0+lbk)*256 + n0 + lbc4);
        *(float4*)(&Bs[lbk][lbc4]) = bv;
        __syncthreads();
        #pragma unroll
        for (int kk = 0; kk < 16; kk++) {
            float4 a = *(const float4*)(&As[kk][tr*4]);
            float4 b = *(const float4*)(&Bs[kk][tc*4]);
            float aa[4]={a.x,a.y,a.z,a.w}, bb[4]={b.x,b.y,b.z,b.w};
            #pragma unroll
            for (int i=0;i<4;i++)
                #pragma unroll
                for (int j=0;j<4;j++) acc[i][j] = fmaf(aa[i], bb[j], acc[i][j]);
        }
        __syncthreads();
    }
    float* Cb = g_R + ht*Nn*256;
    #pragma unroll
    for (int i=0;i<4;i++)
        #pragma unroll
        for (int j=0;j<4;j++)
            Cb[(m0+tr*4+i)*256 + n0+tc*4+j] = fmaxf(acc[i][j], 0.f);
}

// ---------------- K2b: S = sigmoid(R @ qW2[ht]); V = S * a  ----------------
__global__ __launch_bounds__(256) void k_gemm_qw2(const float* __restrict__ qW2,
                                                  const float* __restrict__ a_in) {
    int ht = blockIdx.z;
    int m0 = blockIdx.x*64, n0 = blockIdx.y*64;
    __shared__ float As[16][64];
    __shared__ float Bs[16][64];
    int tid = threadIdx.x;
    int tr = tid/16, tc = tid%16;
    int lm = tid/4,  lk4 = (tid%4)*4;
    int lbk = tid/16, lbc4 = (tid%16)*4;
    const float* Ab = g_R + ht*Nn*256;
    const float* Bb = qW2 + ht*256*256;
    float acc[4][4] = {};
    for (int k0 = 0; k0 < 256; k0 += 16) {
        float4 av = *(const float4*)(Ab + (m0+lm)*256 + k0 + lk4);
        As[lk4+0][lm]=av.x; As[lk4+1][lm]=av.y; As[lk4+2][lm]=av.z; As[lk4+3][lm]=av.w;
        float4 bv = *(const float4*)(Bb + (k0+lbk)*256 + n0 + lbc4);
        *(float4*)(&Bs[lbk][lbc4]) = bv;
        __syncthreads();
        #pragma unroll
        for (int kk = 0; kk < 16; kk++) {
            float4 a = *(const float4*)(&As[kk][tr*4]);
            float4 b = *(const float4*)(&Bs[kk][tc*4]);
            float aa[4]={a.x,a.y,a.z,a.w}, bb[4]={b.x,b.y,b.z,b.w};
            #pragma unroll
            for (int i=0;i<4;i++)
                #pragma unroll
                for (int j=0;j<4;j++) acc[i][j] = fmaf(aa[i], bb[j], acc[i][j]);
        }
        __syncthreads();
    }
    const float* av = a_in + ht*256;
    #pragma unroll
    for (int i=0;i<4;i++) {
        int row = m0 + tr*4 + i;
        #pragma unroll
        for (int j=0;j<4;j++) {
            int col = n0 + tc*4 + j;
            float s = 1.f / (1.f + __expf(-acc[i][j]));
            float val = s * av[col];
            if (col < DHd) g_V[ht*Nn*DHd + row*DHd + col] = val;
            else           g_V[HT*Nn*DHd + ht*Nn*DHd + row*DHd + (col-DHd)] = val;
        }
    }
}

// ---------------- K3: U[r][n][d] = sum_k V[r][n][k] * W[ht][d][k]  ----------------
__global__ __launch_bounds__(256) void k_gemm_u(const float* __restrict__ W) {
    int r  = blockIdx.z;
    int ht = r % HT;
    int m0 = blockIdx.x*64, d0 = blockIdx.y*64;
    __shared__ float As[16][64];   // As[k][n]
    __shared__ float Bs[16][64];   // Bs[k][d]
    int tid = threadIdx.x;
    int tr = tid/16, tc = tid%16;
    int lm = tid/4, lk4 = (tid%4)*4;
    const float* Ab = g_V + r*Nn*DHd;
    const float* Wb = W + ht*Dd*DHd;
    float acc[4][4] = {};
    for (int k0 = 0; k0 < DHd; k0 += 16) {
        float4 av = *(const float4*)(Ab + (m0+lm)*DHd + k0 + lk4);
        As[lk4+0][lm]=av.x; As[lk4+1][lm]=av.y; As[lk4+2][lm]=av.z; As[lk4+3][lm]=av.w;
        float4 bv = *(const float4*)(Wb + (d0+lm)*DHd + k0 + lk4);  // lm also indexes d (0..63)
        Bs[lk4+0][lm]=bv.x; Bs[lk4+1][lm]=bv.y; Bs[lk4+2][lm]=bv.z; Bs[lk4+3][lm]=bv.w;
        __syncthreads();
        #pragma unroll
        for (int kk = 0; kk < 16; kk++) {
            float4 a = *(const float4*)(&As[kk][tr*4]);
            float4 b = *(const float4*)(&Bs[kk][tc*4]);
            float aa[4]={a.x,a.y,a.z,a.w}, bb[4]={b.x,b.y,b.z,b.w};
            #pragma unroll
            for (int i=0;i<4;i++)
                #pragma unroll
                for (int j=0;j<4;j++) acc[i][j] = fmaf(aa[i], bb[j], acc[i][j]);
        }
        __syncthreads();
    }
    #pragma unroll
    for (int i=0;i<4;i++) {
        int row = m0 + tr*4 + i;
        float4 v = make_float4(acc[i][0], acc[i][1], acc[i][2], acc[i][3]);
        *(float4*)(&g_U[r*Nn*Dd + row*Dd + d0 + tc*4]) = v;
    }
}

// ---------------- K4: F[r][n][e] = sum_d X[n][e][d] * U[r][n][d] ----------------
__global__ __launch_bounds__(256) void k_f() {
    int n = blockIdx.x;
    __shared__ float Xs[112*65];
    __shared__ float Us[48*65];
    int tid = threadIdx.x;
    int tx = tid % 16, ty = tid / 16;
    float acc[7][3] = {};
    for (int d0 = 0; d0 < Dd; d0 += 64) {
        for (int i = tid; i < 112*64; i += 256) {
            int e = i >> 6, dd = i & 63;
            Xs[e*65+dd] = (e < Ee) ? g_X[(n*Ee+e)*Dd + d0 + dd] : 0.f;
        }
        for (int i = tid; i < 48*64; i += 256) {
            int r = i >> 6, dd = i & 63;
            Us[r*65+dd] = g_U[r*Nn*Dd + n*Dd + d0 + dd];
        }
        __syncthreads();
        for (int dd = 0; dd < 64; dd++) {
            float u0 = Us[(tx*3+0)*65+dd];
            float u1 = Us[(tx*3+1)*65+dd];
            float u2 = Us[(tx*3+2)*65+dd];
            #pragma unroll
            for (int ee = 0; ee < 7; ee++) {
                float xv = Xs[(ty + ee*16)*65 + dd];
                acc[ee][0] = fmaf(xv, u0, acc[ee][0]);
                acc[ee][1] = fmaf(xv, u1, acc[ee][1]);
                acc[ee][2] = fmaf(xv, u2, acc[ee][2]);
            }
        }
        __syncthreads();
    }
    #pragma unroll
    for (int ee = 0; ee < 7; ee++) {
        int e = ty + ee*16;
        if (e < Ee) {
            #pragma unroll
            for (int rr = 0; rr < 3; rr++) {
                int r = tx*3 + rr;
                g_F[r*Nn*Ee + n*Ee + e] = acc[ee][rr];
            }
        }
    }
}

// ---------------- K5a: repack W[:, T-1] into (d, h*128+k) ----------------
__global__ void k_repack(const float* __restrict__ W) {
    int idx = blockIdx.x * blockDim.x + threadIdx.x;
    if (idx >= Dd*Dd) return;
    int col = idx & 1023, d = idx >> 10;
    int h = col >> 7, k = col & 127;
    g_WB[idx] = W[((h*Tt + (Tt-1))*Dd + d)*DHd + k];
}

// ---------------- K5b: HL = X @ WB   (26880 x 1024 x 1024) ----------------
__global__ __launch_bounds__(256) void k_gemm_hl() {
    int m0 = blockIdx.x*128, n0 = blockIdx.y*64;
    __shared__ float As[16][128];
    __shared__ float Bs[16][64];
    int tid = threadIdx.x;
    int tr = tid/16, tc = tid%16;
    int lm = tid/4, lk4 = (tid%4)*4;
    int lbk = tid/16, lbc4 = (tid%16)*4;
    float acc[8][4] = {};
    for (int k0 = 0; k0 < Dd; k0 += 16) {
        #pragma unroll
        for (int half = 0; half < 2; half++) {
            float4 av = *(const float4*)(g_X + (m0+lm+half*64)*Dd + k0 + lk4);
            As[lk4+0][lm+half*64]=av.x; As[lk4+1][lm+half*64]=av.y;
            As[lk4+2][lm+half*64]=av.z; As[lk4+3][lm+half*64]=av.w;
        }
        float4 bv = *(const float4*)(g_WB + (k0+lbk)*Dd + n0 + lbc4);
        *(float4*)(&Bs[lbk][lbc4]) = bv;
        __syncthreads();
        #pragma unroll
        for (int kk = 0; kk < 16; kk++) {
            float4 a0 = *(const float4*)(&As[kk][tr*8]);
            float4 a1 = *(const float4*)(&As[kk][tr*8+4]);
            float4 b  = *(const float4*)(&Bs[kk][tc*4]);
            float aa[8]={a0.x,a0.y,a0.z,a0.w,a1.x,a1.y,a1.z,a1.w};
            float bb[4]={b.x,b.y,b.z,b.w};
            #pragma unroll
            for (int i=0;i<8;i++)
                #pragma unroll
                for (int j=0;j<4;j++) acc[i][j] = fmaf(aa[i], bb[j], acc[i][j]);
        }
        __syncthreads();
    }
    #pragma unroll
    for (int i=0;i<8;i++) {
        float4 v = make_float4(acc[i][0], acc[i][1], acc[i][2], acc[i][3]);
        *(float4*)(&g_HL[(m0+tr*8+i)*Dd + n0 + tc*4]) = v;
    }
}

// ---------------- K6: edge-type score + softmax + aggregate + relu + residual ----------------
__device__ __forceinline__ float k6_score(int t, const float* f1s, const float* f2s, int i, int j) {
    if (t > 0) {
        float v = f1s[(t-1)*Ee + i] + f2s[(t-1)*Ee + j];
        return v > 0.f ? v : 0.2f*v;
    }
    return NEGV;
}

__global__ __launch_bounds__(128) void k6_attn(const int* __restrict__ adj, float* __restrict__ out) {
    int h = blockIdx.x, n = blockIdx.y;
    extern __shared__ float smx[];
    float* HLs  = smx;                   // 105*128
    float* carr = smx + Ee*128;          // 105*4 (16B aligned)
    float* f1s  = carr + Ee*4;           // 3*105
    float* f2s  = f1s + Tt*Ee;           // 3*105
    int tid = threadIdx.x;
    int lane = tid & 31, w = tid >> 5;

    for (int i = tid; i < Tt*Ee; i += 128) {
        int t = i / Ee, e = i % Ee;
        f1s[i] = g_F[(h*Tt+t)*Nn*Ee + n*Ee + e];
        f2s[i] = g_F[HT*Nn*Ee + (h*Tt+t)*Nn*Ee + n*Ee + e];
    }
    for (int j = 0; j < Ee; j++)
        HLs[j*128 + tid] = g_HL[(n*Ee+j)*Dd + h*DHd + tid] * g_mask[n*Ee + j];
    __syncthreads();

    const int* adjn = adj + n*Ee*Ee;
    for (int ig = 0; ig < 27; ig++) {
        int i0 = ig*4;
        int ni = Ee - i0; if (ni > 4) ni = 4;
        if (w < ni) {
            int i = i0 + w;
            const int* arow = adjn + i*Ee;
            float s0 = k6_score(arow[lane],    f1s, f2s, i, lane);
            float s1 = k6_score(arow[lane+32], f1s, f2s, i, lane+32);
            float s2 = k6_score(arow[lane+64], f1s, f2s, i, lane+64);
            float s3 = (lane < 9) ? k6_score(arow[lane+96], f1s, f2s, i, lane+96) : -INFINITY;
            float m = fmaxf(fmaxf(s0, s1), fmaxf(s2, s3));
            #pragma unroll
            for (int o = 16; o > 0; o >>= 1) m = fmaxf(m, __shfl_xor_sync(0xffffffffu, m, o));
            float p0 = __expf(s0 - m), p1 = __expf(s1 - m), p2 = __expf(s2 - m);
            float p3 = (lane < 9) ? __expf(s3 - m) : 0.f;
            float sum = p0 + p1 + p2 + p3;
            #pragma unroll
            for (int o = 16; o > 0; o >>= 1) sum += __shfl_xor_sync(0xffffffffu, sum, o);
            float inv = 1.f / sum;
            carr[lane*4 + w]      = p0 * inv;
            carr[(lane+32)*4 + w] = p1 * inv;
            carr[(lane+64)*4 + w] = p2 * inv;
            if (lane < 9) carr[(lane+96)*4 + w] = p3 * inv;
        } else {
            for (int j = lane; j < Ee; j += 32) carr[j*4 + w] = 0.f;
        }
        __syncthreads();
        float acc0=0.f, acc1=0.f, acc2=0.f, acc3=0.f;
        #pragma unroll 7
        for (int j = 0; j < Ee; j++) {
            float4 c = *(const float4*)(carr + j*4);
            float hl = HLs[j*128 + tid];
            acc0 = fmaf(c.x, hl, acc0);
            acc1 = fmaf(c.y, hl, acc1);
            acc2 = fmaf(c.z, hl, acc2);
            acc3 = fmaf(c.w, hl, acc3);
        }
        int col = h*DHd + tid;
        #pragma unroll
        for (int ii = 0; ii < 4; ii++) {
            if (ii < ni) {
                float a = (ii==0)?acc0:(ii==1)?acc1:(ii==2)?acc2:acc3;
                int i = i0 + ii;
                out[(n*Ee + i)*Dd + col] = fmaxf(a, 0.f) + g_X[(n*Ee + i)*Dd + col];
            }
        }
        __syncthreads();
    }
}

#define K6_SMEM_BYTES ((Ee*128 + Ee*4 + 2*Tt*Ee) * 4)

// ---------------- launch ----------------
extern "C" void kernel_launch(void* const* d_in, const int* in_sizes, int n_in,
                              void* d_out, int out_size) {
    const float* q    = (const float*)d_in[0];
    const float* para = (const float*)d_in[1];
    const float* sent = (const float*)d_in[2];
    const float* ent  = (const float*)d_in[3];
    const float* pm   = (const float*)d_in[4];
    const float* sm_  = (const float*)d_in[5];
    const float* em   = (const float*)d_in[6];
    const int*   adj  = (const int*)  d_in[7];
    const float* W    = (const float*)d_in[8];
    const float* a    = (const float*)d_in[9];
    const float* qW1  = (const float*)d_in[10];
    const float* qW2  = (const float*)d_in[11];
    float* out = (float*)d_out;

    cudaFuncSetAttribute(k6_attn, cudaFuncAttributeMaxDynamicSharedMemorySize, K6_SMEM_BYTES);

    k_concat<<<(Nn*Ee*Dd + 255)/256, 256>>>(q, para, sent, ent);
    k_mask  <<<(Nn*Ee + 255)/256, 256>>>(pm, sm_, em);
    k_gemm_qw1<<<dim3(4,4,HT), 256>>>(q, qW1);
    k_gemm_qw2<<<dim3(4,4,HT), 256>>>(qW2, a);
    k_gemm_u  <<<dim3(4,16,2*HT), 256>>>(W);
    k_f       <<<Nn, 256>>>();
    k_repack  <<<(Dd*Dd + 255)/256, 256>>>(W);
    k_gemm_hl <<<dim3(210,16), 256>>>();
    k6_attn   <<<dim3(Hh,Nn), 128, K6_SMEM_BYTES>>>(adj, out);
}

// round 3
// speedup vs baseline: 1.8899x; 1.8899x over previous
#include <cuda_runtime.h>
#include <cuda_bf16.h>
#include <math.h>
#include <stdint.h>

#define Nn 256
#define Pp 4
#define Sr 40
#define Enn 60
#define Ee 105
#define Dd 1024
#define Hh 8
#define Tt 3
#define DHd 128
#define HT 24           // H*T
#define NEGV -1e30f

// ---------------- scratch (device globals; no allocations allowed) ----------------
static __device__ float g_X [Nn*Ee*Dd];           // concat input fp32 (110 MB)
static __device__ __nv_bfloat16 g_Xh[Nn*Ee*Dd];   // bf16 hi split of X
static __device__ __nv_bfloat16 g_Xl[Nn*Ee*Dd];   // bf16 lo split of X
static __device__ float g_mask[Nn*Ee];
static __device__ float g_R [HT*Nn*256];          // relu(q @ qW1)
static __device__ float g_V [2*HT*Nn*DHd];        // v1 (r=ht), v2 (r=24+ht)
static __device__ float g_U [2*HT*Nn*Dd];         // u = W @ v
static __device__ float g_F [2*HT*Nn*Ee];         // f1, f2
static __device__ __nv_bfloat16 g_WBh[Dd*Dd];     // W[:,T-1]^T as [N=1024][K=1024] bf16 hi
static __device__ __nv_bfloat16 g_WBl[Dd*Dd];     // lo
static __device__ float g_HL[Nn*Ee*Dd];           // h_last (pre-mask) (110 MB)

// ---------------- K1: concat x (fp32 + bf16 hi/lo split) ----------------
__global__ void k_concat(const float* __restrict__ q, const float* __restrict__ para,
                         const float* __restrict__ sent, const float* __restrict__ ent) {
    int idx = blockIdx.x * blockDim.x + threadIdx.x;
    if (idx >= Nn*Ee*Dd) return;
    int d  = idx & (Dd-1);
    int ne = idx >> 10;
    int e  = ne % Ee;
    int n  = ne / Ee;
    float v;
    if (e == 0)              v = q   [n*Dd + d];
    else if (e < 1+Pp)       v = para[(n*Pp  + (e-1))*Dd + d];
    else if (e < 1+Pp+Sr)    v = sent[(n*Sr  + (e-1-Pp))*Dd + d];
    else                     v = ent [(n*Enn + (e-1-Pp-Sr))*Dd + d];
    g_X[idx] = v;
    __nv_bfloat16 hi = __float2bfloat16(v);
    g_Xh[idx] = hi;
    g_Xl[idx] = __float2bfloat16(v - __bfloat162float(hi));
}

__global__ void k_mask(const float* __restrict__ pm, const float* __restrict__ sm_,
                       const float* __restrict__ em) {
    int idx = blockIdx.x * blockDim.x + threadIdx.x;
    if (idx >= Nn*Ee) return;
    int e = idx % Ee, n = idx / Ee;
    float v;
    if (e == 0)            v = 1.f;
    else if (e < 1+Pp)     v = pm[n*Pp  + e-1];
    else if (e < 1+Pp+Sr)  v = sm_[n*Sr + e-1-Pp];
    else                   v = em[n*Enn + e-1-Pp-Sr];
    g_mask[idx] = v;
}

// ---------------- K2a: R = relu(Q @ qW1[ht]),  M=256 N=256 K=1024 ----------------
__global__ __launch_bounds__(256) void k_gemm_qw1(const float* __restrict__ q,
                                                  const float* __restrict__ qW1) {
    int ht = blockIdx.z;
    int m0 = blockIdx.x*64, n0 = blockIdx.y*64;
    __shared__ float As[16][64];
    __shared__ float Bs[16][64];
    int tid = threadIdx.x;
    int tr = tid/16, tc = tid%16;
    int lm = tid/4,  lk4 = (tid%4)*4;
    int lbk = tid/16, lbc4 = (tid%16)*4;
    const float* Bbase = qW1 + ht*Dd*256;
    float acc[4][4] = {};
    for (int k0 = 0; k0 < Dd; k0 += 16) {
        float4 av = *(const float4*)(q + (m0+lm)*Dd + k0 + lk4);
        As[lk4+0][lm]=av.x; As[lk4+1][lm]=av.y; As[lk4+2][lm]=av.z; As[lk4+3][lm]=av.w;
        float4 bv = *(const float4*)(Bbase + (k0+lbk)*256 + n0 + lbc4);
        *(float4*)(&Bs[lbk][lbc4]) = bv;
        __syncthreads();
        #pragma unroll
        for (int kk = 0; kk < 16; kk++) {
            float4 a = *(const float4*)(&As[kk][tr*4]);
            float4 b = *(const float4*)(&Bs[kk][tc*4]);
            float aa[4]={a.x,a.y,a.z,a.w}, bb[4]={b.x,b.y,b.z,b.w};
            #pragma unroll
            for (int i=0;i<4;i++)
                #pragma unroll
                for (int j=0;j<4;j++) acc[i][j] = fmaf(aa[i], bb[j], acc[i][j]);
        }
        __syncthreads();
    }
    float* Cb = g_R + ht*Nn*256;
    #pragma unroll
    for (int i=0;i<4;i++)
        #pragma unroll
        for (int j=0;j<4;j++)
            Cb[(m0+tr*4+i)*256 + n0+tc*4+j] = fmaxf(acc[i][j], 0.f);
}

// ---------------- K2b: S = sigmoid(R @ qW2[ht]); V = S * a  ----------------
__global__ __launch_bounds__(256) void k_gemm_qw2(const float* __restrict__ qW2,
                                                  const float* __restrict__ a_in) {
    int ht = blockIdx.z;
    int m0 = blockIdx.x*64, n0 = blockIdx.y*64;
    __shared__ float As[16][64];
    __shared__ float Bs[16][64];
    int tid = threadIdx.x;
    int tr = tid/16, tc = tid%16;
    int lm = tid/4,  lk4 = (tid%4)*4;
    int lbk = tid/16, lbc4 = (tid%16)*4;
    const float* Ab = g_R + ht*Nn*256;
    const float* Bb = qW2 + ht*256*256;
    float acc[4][4] = {};
    for (int k0 = 0; k0 < 256; k0 += 16) {
        float4 av = *(const float4*)(Ab + (m0+lm)*256 + k0 + lk4);
        As[lk4+0][lm]=av.x; As[lk4+1][lm]=av.y; As[lk4+2][lm]=av.z; As[lk4+3][lm]=av.w;
        float4 bv = *(const float4*)(Bb + (k0+lbk)*256 + n0 + lbc4);
        *(float4*)(&Bs[lbk][lbc4]) = bv;
        __syncthreads();
        #pragma unroll
        for (int kk = 0; kk < 16; kk++) {
            float4 a = *(const float4*)(&As[kk][tr*4]);
            float4 b = *(const float4*)(&Bs[kk][tc*4]);
            float aa[4]={a.x,a.y,a.z,a.w}, bb[4]={b.x,b.y,b.z,b.w};
            #pragma unroll
            for (int i=0;i<4;i++)
                #pragma unroll
                for (int j=0;j<4;j++) acc[i][j] = fmaf(aa[i], bb[j], acc[i][j]);
        }
        __syncthreads();
    }
    const float* av = a_in + ht*256;
    #pragma unroll
    for (int i=0;i<4;i++) {
        int row = m0 + tr*4 + i;
        #pragma unroll
        for (int j=0;j<4;j++) {
            int col = n0 + tc*4 + j;
            float s = 1.f / (1.f + __expf(-acc[i][j]));
            float val = s * av[col];
            if (col < DHd) g_V[ht*Nn*DHd + row*DHd + col] = val;
            else           g_V[HT*Nn*DHd + ht*Nn*DHd + row*DHd + (col-DHd)] = val;
        }
    }
}

// ---------------- K3: U[r][n][d] = sum_k V[r][n][k] * W[ht][d][k]  ----------------
__global__ __launch_bounds__(256) void k_gemm_u(const float* __restrict__ W) {
    int r  = blockIdx.z;
    int ht = r % HT;
    int m0 = blockIdx.x*64, d0 = blockIdx.y*64;
    __shared__ float As[16][64];   // As[k][n]
    __shared__ float Bs[16][64];   // Bs[k][d]
    int tid = threadIdx.x;
    int tr = tid/16, tc = tid%16;
    int lm = tid/4, lk4 = (tid%4)*4;
    const float* Ab = g_V + r*Nn*DHd;
    const float* Wb = W + ht*Dd*DHd;
    float acc[4][4] = {};
    for (int k0 = 0; k0 < DHd; k0 += 16) {
        float4 av = *(const float4*)(Ab + (m0+lm)*DHd + k0 + lk4);
        As[lk4+0][lm]=av.x; As[lk4+1][lm]=av.y; As[lk4+2][lm]=av.z; As[lk4+3][lm]=av.w;
        float4 bv = *(const float4*)(Wb + (d0+lm)*DHd + k0 + lk4);
        Bs[lk4+0][lm]=bv.x; Bs[lk4+1][lm]=bv.y; Bs[lk4+2][lm]=bv.z; Bs[lk4+3][lm]=bv.w;
        __syncthreads();
        #pragma unroll
        for (int kk = 0; kk < 16; kk++) {
            float4 a = *(const float4*)(&As[kk][tr*4]);
            float4 b = *(const float4*)(&Bs[kk][tc*4]);
            float aa[4]={a.x,a.y,a.z,a.w}, bb[4]={b.x,b.y,b.z,b.w};
            #pragma unroll
            for (int i=0;i<4;i++)
                #pragma unroll
                for (int j=0;j<4;j++) acc[i][j] = fmaf(aa[i], bb[j], acc[i][j]);
        }
        __syncthreads();
    }
    #pragma unroll
    for (int i=0;i<4;i++) {
        int row = m0 + tr*4 + i;
        float4 v = make_float4(acc[i][0], acc[i][1], acc[i][2], acc[i][3]);
        *(float4*)(&g_U[r*Nn*Dd + row*Dd + d0 + tc*4]) = v;
    }
}

// ---------------- K4: F[r][n][e] = sum_d X[n][e][d] * U[r][n][d] ----------------
__global__ __launch_bounds__(256) void k_f() {
    int n = blockIdx.x;
    __shared__ float Xs[112*65];
    __shared__ float Us[48*65];
    int tid = threadIdx.x;
    int tx = tid % 16, ty = tid / 16;
    float acc[7][3] = {};
    for (int d0 = 0; d0 < Dd; d0 += 64) {
        for (int i = tid; i < 112*64; i += 256) {
            int e = i >> 6, dd = i & 63;
            Xs[e*65+dd] = (e < Ee) ? g_X[(n*Ee+e)*Dd + d0 + dd] : 0.f;
        }
        for (int i = tid; i < 48*64; i += 256) {
            int r = i >> 6, dd = i & 63;
            Us[r*65+dd] = g_U[r*Nn*Dd + n*Dd + d0 + dd];
        }
        __syncthreads();
        for (int dd = 0; dd < 64; dd++) {
            float u0 = Us[(tx*3+0)*65+dd];
            float u1 = Us[(tx*3+1)*65+dd];
            float u2 = Us[(tx*3+2)*65+dd];
            #pragma unroll
            for (int ee = 0; ee < 7; ee++) {
                float xv = Xs[(ty + ee*16)*65 + dd];
                acc[ee][0] = fmaf(xv, u0, acc[ee][0]);
                acc[ee][1] = fmaf(xv, u1, acc[ee][1]);
                acc[ee][2] = fmaf(xv, u2, acc[ee][2]);
            }
        }
        __syncthreads();
    }
    #pragma unroll
    for (int ee = 0; ee < 7; ee++) {
        int e = ty + ee*16;
        if (e < Ee) {
            #pragma unroll
            for (int rr = 0; rr < 3; rr++) {
                int r = tx*3 + rr;
                g_F[r*Nn*Ee + n*Ee + e] = acc[ee][rr];
            }
        }
    }
}

// ---------------- K5a: repack W[:, T-1]^T into [N=1024 (h*128+k)][K=1024 (d)] bf16 hi/lo ----
__global__ void k_repack_bf(const float* __restrict__ W) {
    int idx = blockIdx.x * blockDim.x + threadIdx.x;
    if (idx >= Dd*Dd) return;
    int d = idx & 1023, col = idx >> 10;         // out[col][d]
    int h = col >> 7, k = col & 127;
    float v = W[((h*Tt + (Tt-1))*Dd + d)*DHd + k];
    __nv_bfloat16 hi = __float2bfloat16(v);
    g_WBh[idx] = hi;
    g_WBl[idx] = __float2bfloat16(v - __bfloat162float(hi));
}

// ---------------- K5b: HL = X @ WB^T via mma.sync bf16, 3-term split ----------------
// CTA 256 threads (8 warps, 4x2), tile M=128 x N=128, K chunks of 64.
// smem tiles pitch 72 bf16 elems -> fragment LDS hits all 32 banks.
#define HLP 72
#define HL_TILE_ELEMS (128*HLP)
#define HL_SMEM_BYTES (4*HL_TILE_ELEMS*2)

__device__ __forceinline__ void mma16816(float* c, const uint32_t* a, uint32_t b0, uint32_t b1) {
    asm volatile(
        "mma.sync.aligned.m16n8k16.row.col.f32.bf16.bf16.f32 "
        "{%0,%1,%2,%3}, {%4,%5,%6,%7}, {%8,%9}, {%0,%1,%2,%3};"
        : "+f"(c[0]), "+f"(c[1]), "+f"(c[2]), "+f"(c[3])
        : "r"(a[0]), "r"(a[1]), "r"(a[2]), "r"(a[3]), "r"(b0), "r"(b1));
}

__global__ __launch_bounds__(256) void k_hl_mma() {
    extern __shared__ __nv_bfloat16 sm[];
    __nv_bfloat16* sAh = sm;
    __nv_bfloat16* sAl = sm + HL_TILE_ELEMS;
    __nv_bfloat16* sBh = sm + 2*HL_TILE_ELEMS;
    __nv_bfloat16* sBl = sm + 3*HL_TILE_ELEMS;
    int tid = threadIdx.x;
    int warp = tid >> 5, lane = tid & 31;
    int wm = warp & 3, wn = warp >> 2;          // warp tile: rows wm*32.., cols wn*64..
    int g = lane >> 2, tg = lane & 3;
    int n0 = blockIdx.x * 128;
    int m0 = blockIdx.y * 128;

    float acc[2][8][4];
    #pragma unroll
    for (int i=0;i<2;i++)
        #pragma unroll
        for (int j=0;j<8;j++)
            #pragma unroll
            for (int q=0;q<4;q++) acc[i][j][q] = 0.f;

    int sr = tid >> 3;            // staging row 0..31 (stride 32 rows over 4 iters)
    int sc = (tid & 7) * 8;       // staging col (bf16 elems)

    for (int kc = 0; kc < 16; kc++) {
        const __nv_bfloat16* Ah = g_Xh  + (size_t)m0 * Dd + kc*64;
        const __nv_bfloat16* Al = g_Xl  + (size_t)m0 * Dd + kc*64;
        const __nv_bfloat16* Bh = g_WBh + (size_t)n0 * Dd + kc*64;
        const __nv_bfloat16* Bl = g_WBl + (size_t)n0 * Dd + kc*64;
        #pragma unroll
        for (int it = 0; it < 4; it++) {
            int r = sr + it*32;
            size_t go = (size_t)r * Dd + sc;
            int so = r * HLP + sc;
            *(uint4*)(sAh + so) = *(const uint4*)(Ah + go);
            *(uint4*)(sAl + so) = *(const uint4*)(Al + go);
            *(uint4*)(sBh + so) = *(const uint4*)(Bh + go);
            *(uint4*)(sBl + so) = *(const uint4*)(Bl + go);
        }
        __syncthreads();
        #pragma unroll
        for (int ks = 0; ks < 4; ks++) {
            int kb = ks * 16;
            uint32_t ah[2][4], al[2][4];
            #pragma unroll
            for (int mi = 0; mi < 2; mi++) {
                int row = wm*32 + mi*16 + g;
                const __nv_bfloat16* p0 = sAh + row*HLP + kb + tg*2;
                const __nv_bfloat16* p1 = sAh + (row+8)*HLP + kb + tg*2;
                ah[mi][0] = *(const uint32_t*)(p0);
                ah[mi][1] = *(const uint32_t*)(p1);
                ah[mi][2] = *(const uint32_t*)(p0 + 8);
                ah[mi][3] = *(const uint32_t*)(p1 + 8);
                const __nv_bfloat16* q0 = sAl + row*HLP + kb + tg*2;
                const __nv_bfloat16* q1 = sAl + (row+8)*HLP + kb + tg*2;
                al[mi][0] = *(const uint32_t*)(q0);
                al[mi][1] = *(const uint32_t*)(q1);
                al[mi][2] = *(const uint32_t*)(q0 + 8);
                al[mi][3] = *(const uint32_t*)(q1 + 8);
            }
            #pragma unroll
            for (int nj = 0; nj < 8; nj++) {
                int col = wn*64 + nj*8 + g;     // B row = output col
                const __nv_bfloat16* pb = sBh + col*HLP + kb + tg*2;
                const __nv_bfloat16* pl = sBl + col*HLP + kb + tg*2;
                uint32_t bh0 = *(const uint32_t*)(pb);
                uint32_t bh1 = *(const uint32_t*)(pb + 8);
                uint32_t bl0 = *(const uint32_t*)(pl);
                uint32_t bl1 = *(const uint32_t*)(pl + 8);
                #pragma unroll
                for (int mi = 0; mi < 2; mi++) {
                    mma16816(acc[mi][nj], ah[mi], bh0, bh1);
                    mma16816(acc[mi][nj], ah[mi], bl0, bl1);
                    mma16816(acc[mi][nj], al[mi], bh0, bh1);
                }
            }
        }
        __syncthreads();
    }

    // epilogue: direct float2 stores
    #pragma unroll
    for (int mi = 0; mi < 2; mi++) {
        int row = m0 + wm*32 + mi*16 + g;
        #pragma unroll
        for (int nj = 0; nj < 8; nj++) {
            int col = n0 + wn*64 + nj*8 + tg*2;
            *(float2*)(&g_HL[(size_t)row * Dd + col])     = make_float2(acc[mi][nj][0], acc[mi][nj][1]);
            *(float2*)(&g_HL[(size_t)(row+8) * Dd + col]) = make_float2(acc[mi][nj][2], acc[mi][nj][3]);
        }
    }
}

// ---------------- K6: edge-type score + softmax + aggregate + relu + residual ----------------
__device__ __forceinline__ float k6_score(int t, const float* f1s, const float* f2s, int i, int j) {
    if (t > 0) {
        float v = f1s[(t-1)*Ee + i] + f2s[(t-1)*Ee + j];
        return v > 0.f ? v : 0.2f*v;
    }
    return NEGV;
}

__global__ __launch_bounds__(128) void k6_attn(const int* __restrict__ adj, float* __restrict__ out) {
    int h = blockIdx.x, n = blockIdx.y;
    extern __shared__ float smx[];
    float* HLs  = smx;                   // 105*128
    float* carr = smx + Ee*128;          // 105*4
    float* f1s  = carr + Ee*4;           // 3*105
    float* f2s  = f1s + Tt*Ee;           // 3*105
    int tid = threadIdx.x;
    int lane = tid & 31, w = tid >> 5;

    for (int i = tid; i < Tt*Ee; i += 128) {
        int t = i / Ee, e = i % Ee;
        f1s[i] = g_F[(h*Tt+t)*Nn*Ee + n*Ee + e];
        f2s[i] = g_F[HT*Nn*Ee + (h*Tt+t)*Nn*Ee + n*Ee + e];
    }
    for (int j = 0; j < Ee; j++)
        HLs[j*128 + tid] = g_HL[(size_t)(n*Ee+j)*Dd + h*DHd + tid] * g_mask[n*Ee + j];
    __syncthreads();

    const int* adjn = adj + n*Ee*Ee;
    for (int ig = 0; ig < 27; ig++) {
        int i0 = ig*4;
        int ni = Ee - i0; if (ni > 4) ni = 4;
        if (w < ni) {
            int i = i0 + w;
            const int* arow = adjn + i*Ee;
            float s0 = k6_score(arow[lane],    f1s, f2s, i, lane);
            float s1 = k6_score(arow[lane+32], f1s, f2s, i, lane+32);
            float s2 = k6_score(arow[lane+64], f1s, f2s, i, lane+64);
            float s3 = (lane < 9) ? k6_score(arow[lane+96], f1s, f2s, i, lane+96) : -INFINITY;
            float m = fmaxf(fmaxf(s0, s1), fmaxf(s2, s3));
            #pragma unroll
            for (int o = 16; o > 0; o >>= 1) m = fmaxf(m, __shfl_xor_sync(0xffffffffu, m, o));
            float p0 = __expf(s0 - m), p1 = __expf(s1 - m), p2 = __expf(s2 - m);
            float p3 = (lane < 9) ? __expf(s3 - m) : 0.f;
            float sum = p0 + p1 + p2 + p3;
            #pragma unroll
            for (int o = 16; o > 0; o >>= 1) sum += __shfl_xor_sync(0xffffffffu, sum, o);
            float inv = 1.f / sum;
            carr[lane*4 + w]      = p0 * inv;
            carr[(lane+32)*4 + w] = p1 * inv;
            carr[(lane+64)*4 + w] = p2 * inv;
            if (lane < 9) carr[(lane+96)*4 + w] = p3 * inv;
        } else {
            for (int j = lane; j < Ee; j += 32) carr[j*4 + w] = 0.f;
        }
        __syncthreads();
        float acc0=0.f, acc1=0.f, acc2=0.f, acc3=0.f;
        #pragma unroll 7
        for (int j = 0; j < Ee; j++) {
            float4 c = *(const float4*)(carr + j*4);
            float hl = HLs[j*128 + tid];
            acc0 = fmaf(c.x, hl, acc0);
            acc1 = fmaf(c.y, hl, acc1);
            acc2 = fmaf(c.z, hl, acc2);
            acc3 = fmaf(c.w, hl, acc3);
        }
        int col = h*DHd + tid;
        #pragma unroll
        for (int ii = 0; ii < 4; ii++) {
            if (ii < ni) {
                float a = (ii==0)?acc0:(ii==1)?acc1:(ii==2)?acc2:acc3;
                int i = i0 + ii;
                out[(size_t)(n*Ee + i)*Dd + col] = fmaxf(a, 0.f) + g_X[(size_t)(n*Ee + i)*Dd + col];
            }
        }
        __syncthreads();
    }
}

#define K6_SMEM_BYTES ((Ee*128 + Ee*4 + 2*Tt*Ee) * 4)

// ---------------- launch ----------------
extern "C" void kernel_launch(void* const* d_in, const int* in_sizes, int n_in,
                              void* d_out, int out_size) {
    const float* q    = (const float*)d_in[0];
    const float* para = (const float*)d_in[1];
    const float* sent = (const float*)d_in[2];
    const float* ent  = (const float*)d_in[3];
    const float* pm   = (const float*)d_in[4];
    const float* sm_  = (const float*)d_in[5];
    const float* em   = (const float*)d_in[6];
    const int*   adj  = (const int*)  d_in[7];
    const float* W    = (const float*)d_in[8];
    const float* a    = (const float*)d_in[9];
    const float* qW1  = (const float*)d_in[10];
    const float* qW2  = (const float*)d_in[11];
    float* out = (float*)d_out;

    cudaFuncSetAttribute(k6_attn, cudaFuncAttributeMaxDynamicSharedMemorySize, K6_SMEM_BYTES);
    cudaFuncSetAttribute(k_hl_mma, cudaFuncAttributeMaxDynamicSharedMemorySize, HL_SMEM_BYTES);

    k_concat<<<(Nn*Ee*Dd + 255)/256, 256>>>(q, para, sent, ent);
    k_mask  <<<(Nn*Ee + 255)/256, 256>>>(pm, sm_, em);
    k_gemm_qw1<<<dim3(4,4,HT), 256>>>(q, qW1);
    k_gemm_qw2<<<dim3(4,4,HT), 256>>>(qW2, a);
    k_gemm_u  <<<dim3(4,16,2*HT), 256>>>(W);
    k_f       <<<Nn, 256>>>();
    k_repack_bf<<<(Dd*Dd + 255)/256, 256>>>(W);
    k_hl_mma  <<<dim3(8,210), 256, HL_SMEM_BYTES>>>();
    k6_attn   <<<dim3(Hh,Nn), 128, K6_SMEM_BYTES>>>(adj, out);
}

// round 8
// speedup vs baseline: 1.9463x; 1.0298x over previous
#include <cuda_runtime.h>
#include <cuda_bf16.h>
#include <math.h>
#include <stdint.h>

#define Nn 256
#define Pp 4
#define Sr 40
#define Enn 60
#define Ee 105
#define Dd 1024
#define Hh 8
#define Tt 3
#define DHd 128
#define HT 24           // H*T
#define NEGV -1e30f

// ---------------- scratch (device globals; no allocations allowed) ----------------
static __device__ float g_X [Nn*Ee*Dd];           // concat input fp32 (110 MB)
static __device__ __nv_bfloat16 g_Xh[Nn*Ee*Dd];   // bf16 hi split of X
static __device__ __nv_bfloat16 g_Xl[Nn*Ee*Dd];   // bf16 lo split of X
static __device__ float g_mask[Nn*Ee];
static __device__ float g_R [HT*Nn*256];          // relu(q @ qW1)
static __device__ float g_V [2*HT*Nn*DHd];        // v1 (r=ht), v2 (r=24+ht)  fp32
static __device__ float g_U [2*HT*Nn*Dd];         // u = W @ v (fp32)
static __device__ float g_F [2*HT*Nn*Ee];         // f1, f2  [r][n][e]
static __device__ __nv_bfloat16 g_WBh[Dd*Dd];     // W[:,T-1]^T as [N=1024][K=1024] bf16 hi
static __device__ __nv_bfloat16 g_WBl[Dd*Dd];     // lo
static __device__ float g_HL[Nn*Ee*Dd];           // h_last (pre-mask) (110 MB)

// ---------------- K1: concat x (fp32 + bf16 hi/lo split) ----------------
__global__ void k_concat(const float* __restrict__ q, const float* __restrict__ para,
                         const float* __restrict__ sent, const float* __restrict__ ent) {
    int idx = blockIdx.x * blockDim.x + threadIdx.x;
    if (idx >= Nn*Ee*Dd) return;
    int d  = idx & (Dd-1);
    int ne = idx >> 10;
    int e  = ne % Ee;
    int n  = ne / Ee;
    float v;
    if (e == 0)              v = q   [n*Dd + d];
    else if (e < 1+Pp)       v = para[(n*Pp  + (e-1))*Dd + d];
    else if (e < 1+Pp+Sr)    v = sent[(n*Sr  + (e-1-Pp))*Dd + d];
    else                     v = ent [(n*Enn + (e-1-Pp-Sr))*Dd + d];
    g_X[idx] = v;
    __nv_bfloat16 hi = __float2bfloat16(v);
    g_Xh[idx] = hi;
    g_Xl[idx] = __float2bfloat16(v - __bfloat162float(hi));
}

__global__ void k_mask(const float* __restrict__ pm, const float* __restrict__ sm_,
                       const float* __restrict__ em) {
    int idx = blockIdx.x * blockDim.x + threadIdx.x;
    if (idx >= Nn*Ee) return;
    int e = idx % Ee, n = idx / Ee;
    float v;
    if (e == 0)            v = 1.f;
    else if (e < 1+Pp)     v = pm[n*Pp  + e-1];
    else if (e < 1+Pp+Sr)  v = sm_[n*Sr + e-1-Pp];
    else                   v = em[n*Enn + e-1-Pp-Sr];
    g_mask[idx] = v;
}

// ---------------- K2a: R = relu(Q @ qW1[ht]),  M=256 N=256 K=1024 ----------------
__global__ __launch_bounds__(256) void k_gemm_qw1(const float* __restrict__ q,
                                                  const float* __restrict__ qW1) {
    int ht = blockIdx.z;
    int m0 = blockIdx.x*64, n0 = blockIdx.y*64;
    __shared__ float As[16][64];
    __shared__ float Bs[16][64];
    int tid = threadIdx.x;
    int tr = tid/16, tc = tid%16;
    int lm = tid/4,  lk4 = (tid%4)*4;
    int lbk = tid/16, lbc4 = (tid%16)*4;
    const float* Bbase = qW1 + (size_t)ht*Dd*256;
    float acc[4][4] = {};
    for (int k0 = 0; k0 < Dd; k0 += 16) {
        float4 av = *(const float4*)(q + (m0+lm)*Dd + k0 + lk4);
        As[lk4+0][lm]=av.x; As[lk4+1][lm]=av.y; As[lk4+2][lm]=av.z; As[lk4+3][lm]=av.w;
        float4 bv = *(const float4*)(Bbase + (size_t)(k0+lbk)*256 + n0 + lbc4);
        *(float4*)(&Bs[lbk][lbc4]) = bv;
        __syncthreads();
        #pragma unroll
        for (int kk = 0; kk < 16; kk++) {
            float4 a = *(const float4*)(&As[kk][tr*4]);
            float4 b = *(const float4*)(&Bs[kk][tc*4]);
            float aa[4]={a.x,a.y,a.z,a.w}, bb[4]={b.x,b.y,b.z,b.w};
            #pragma unroll
            for (int i=0;i<4;i++)
                #pragma unroll
                for (int j=0;j<4;j++) acc[i][j] = fmaf(aa[i], bb[j], acc[i][j]);
        }
        __syncthreads();
    }
    float* Cb = g_R + (size_t)ht*Nn*256;
    #pragma unroll
    for (int i=0;i<4;i++)
        #pragma unroll
        for (int j=0;j<4;j++)
            Cb[(m0+tr*4+i)*256 + n0+tc*4+j] = fmaxf(acc[i][j], 0.f);
}

// ---------------- K2b: S = sigmoid(R @ qW2[ht]); V = S * a (fp32, round-3 proven) --------
__global__ __launch_bounds__(256) void k_gemm_qw2(const float* __restrict__ qW2,
                                                  const float* __restrict__ a_in) {
    int ht = blockIdx.z;
    int m0 = blockIdx.x*64, n0 = blockIdx.y*64;
    __shared__ float As[16][64];
    __shared__ float Bs[16][64];
    int tid = threadIdx.x;
    int tr = tid/16, tc = tid%16;
    int lm = tid/4,  lk4 = (tid%4)*4;
    int lbk = tid/16, lbc4 = (tid%16)*4;
    const float* Ab = g_R + (size_t)ht*Nn*256;
    const float* Bb = qW2 + (size_t)ht*256*256;
    float acc[4][4] = {};
    for (int k0 = 0; k0 < 256; k0 += 16) {
        float4 av = *(const float4*)(Ab + (m0+lm)*256 + k0 + lk4);
        As[lk4+0][lm]=av.x; As[lk4+1][lm]=av.y; As[lk4+2][lm]=av.z; As[lk4+3][lm]=av.w;
        float4 bv = *(const float4*)(Bb + (size_t)(k0+lbk)*256 + n0 + lbc4);
        *(float4*)(&Bs[lbk][lbc4]) = bv;
        __syncthreads();
        #pragma unroll
        for (int kk = 0; kk < 16; kk++) {
            float4 a = *(const float4*)(&As[kk][tr*4]);
            float4 b = *(const float4*)(&Bs[kk][tc*4]);
            float aa[4]={a.x,a.y,a.z,a.w}, bb[4]={b.x,b.y,b.z,b.w};
            #pragma unroll
            for (int i=0;i<4;i++)
                #pragma unroll
                for (int j=0;j<4;j++) acc[i][j] = fmaf(aa[i], bb[j], acc[i][j]);
        }
        __syncthreads();
    }
    const float* av = a_in + ht*256;
    #pragma unroll
    for (int i=0;i<4;i++) {
        int row = m0 + tr*4 + i;
        #pragma unroll
        for (int j=0;j<4;j++) {
            int col = n0 + tc*4 + j;
            float s = 1.f / (1.f + __expf(-acc[i][j]));
            float val = s * av[col];
            if (col < DHd) g_V[(size_t)ht*Nn*DHd + row*DHd + col] = val;
            else           g_V[(size_t)HT*Nn*DHd + (size_t)ht*Nn*DHd + row*DHd + (col-DHd)] = val;
        }
    }
}

// ---------------- shared mma bits ----------------
#define HLP 72
#define HL_TILE_ELEMS (128*HLP)
#define HL_SMEM_BYTES (4*HL_TILE_ELEMS*2)

__device__ __forceinline__ void mma16816(float* c, const uint32_t* a, uint32_t b0, uint32_t b1) {
    asm volatile(
        "mma.sync.aligned.m16n8k16.row.col.f32.bf16.bf16.f32 "
        "{%0,%1,%2,%3}, {%4,%5,%6,%7}, {%8,%9}, {%0,%1,%2,%3};"
        : "+f"(c[0]), "+f"(c[1]), "+f"(c[2]), "+f"(c[3])
        : "r"(a[0]), "r"(a[1]), "r"(a[2]), "r"(a[3]), "r"(b0), "r"(b1));
}

__device__ __forceinline__ void split2(float x, float y, __nv_bfloat162* ph, __nv_bfloat162* pl) {
    __nv_bfloat162 h, l;
    h.x = __float2bfloat16(x);
    h.y = __float2bfloat16(y);
    l.x = __float2bfloat16(x - __bfloat162float(h.x));
    l.y = __float2bfloat16(y - __bfloat162float(h.y));
    *ph = h; *pl = l;
}

// ---------------- K3: U[r] = V[r] @ W[ht]^T via mma (hardcoded clone of proven k_hl_mma) --
// M=256 (n), N=1024 (d), K=128. Inline fp32->bf16 hi/lo split during staging.
__global__ __launch_bounds__(256) void k_u_mma(const float* __restrict__ W) {
    extern __shared__ __nv_bfloat16 sm[];
    __nv_bfloat16* sAh = sm;
    __nv_bfloat16* sAl = sm + HL_TILE_ELEMS;
    __nv_bfloat16* sBh = sm + 2*HL_TILE_ELEMS;
    __nv_bfloat16* sBl = sm + 3*HL_TILE_ELEMS;
    int tid = threadIdx.x;
    int warp = tid >> 5, lane = tid & 31;
    int wm = warp & 3, wn = warp >> 2;          // warp tile: rows wm*32.., cols wn*64..
    int g = lane >> 2, tg = lane & 3;
    int n0 = blockIdx.x * 128;                  // d tile
    int m0 = blockIdx.y * 128;                  // n tile
    int r  = blockIdx.z;                        // 0..47
    int ht = r % HT;

    const float* Ab = g_V + (size_t)r*Nn*DHd + (size_t)m0*DHd;    // V[r][m0+.][k]
    const float* Bb = W   + (size_t)ht*Dd*DHd + (size_t)n0*DHd;   // W[ht][n0+.][k]

    float acc[2][8][4];
    #pragma unroll
    for (int i=0;i<2;i++)
        #pragma unroll
        for (int j=0;j<8;j++)
            #pragma unroll
            for (int q=0;q<4;q++) acc[i][j][q] = 0.f;

    int sr = tid >> 3;            // staging row 0..31 (stride 32 over 4 iters)
    int sc = (tid & 7) * 8;       // staging col (elements)

    for (int kc = 0; kc < 2; kc++) {
        #pragma unroll
        for (int it = 0; it < 4; it++) {
            int rr = sr + it*32;
            const float* pa = Ab + (size_t)rr*DHd + kc*64 + sc;
            const float* pb = Bb + (size_t)rr*DHd + kc*64 + sc;
            int so = rr * HLP + sc;
            #pragma unroll
            for (int jj = 0; jj < 8; jj += 4) {
                float4 va = *(const float4*)(pa + jj);
                split2(va.x, va.y, (__nv_bfloat162*)(sAh + so + jj),     (__nv_bfloat162*)(sAl + so + jj));
                split2(va.z, va.w, (__nv_bfloat162*)(sAh + so + jj + 2), (__nv_bfloat162*)(sAl + so + jj + 2));
                float4 vb = *(const float4*)(pb + jj);
                split2(vb.x, vb.y, (__nv_bfloat162*)(sBh + so + jj),     (__nv_bfloat162*)(sBl + so + jj));
                split2(vb.z, vb.w, (__nv_bfloat162*)(sBh + so + jj + 2), (__nv_bfloat162*)(sBl + so + jj + 2));
            }
        }
        __syncthreads();
        #pragma unroll
        for (int ks = 0; ks < 4; ks++) {
            int kb = ks * 16;
            uint32_t ah[2][4], al[2][4];
            #pragma unroll
            for (int mi = 0; mi < 2; mi++) {
                int row = wm*32 + mi*16 + g;
                const __nv_bfloat16* p0 = sAh + row*HLP + kb + tg*2;
                const __nv_bfloat16* p1 = sAh + (row+8)*HLP + kb + tg*2;
                ah[mi][0] = *(const uint32_t*)(p0);
                ah[mi][1] = *(const uint32_t*)(p1);
                ah[mi][2] = *(const uint32_t*)(p0 + 8);
                ah[mi][3] = *(const uint32_t*)(p1 + 8);
                const __nv_bfloat16* q0 = sAl + row*HLP + kb + tg*2;
                const __nv_bfloat16* q1 = sAl + (row+8)*HLP + kb + tg*2;
                al[mi][0] = *(const uint32_t*)(q0);
                al[mi][1] = *(const uint32_t*)(q1);
                al[mi][2] = *(const uint32_t*)(q0 + 8);
                al[mi][3] = *(const uint32_t*)(q1 + 8);
            }
            #pragma unroll
            for (int nj = 0; nj < 8; nj++) {
                int col = wn*64 + nj*8 + g;     // B row = output col
                const __nv_bfloat16* pb = sBh + col*HLP + kb + tg*2;
                const __nv_bfloat16* pl = sBl + col*HLP + kb + tg*2;
                uint32_t bh0 = *(const uint32_t*)(pb);
                uint32_t bh1 = *(const uint32_t*)(pb + 8);
                uint32_t bl0 = *(const uint32_t*)(pl);
                uint32_t bl1 = *(const uint32_t*)(pl + 8);
                #pragma unroll
                for (int mi = 0; mi < 2; mi++) {
                    mma16816(acc[mi][nj], ah[mi], bh0, bh1);
                    mma16816(acc[mi][nj], ah[mi], bl0, bl1);
                    mma16816(acc[mi][nj], al[mi], bh0, bh1);
                }
            }
        }
        __syncthreads();
    }

    #pragma unroll
    for (int mi = 0; mi < 2; mi++) {
        int row = m0 + wm*32 + mi*16 + g;
        #pragma unroll
        for (int nj = 0; nj < 8; nj++) {
            int col = n0 + wn*64 + nj*8 + tg*2;
            *(float2*)(&g_U[(size_t)r*Nn*Dd + (size_t)row*Dd + col])     = make_float2(acc[mi][nj][0], acc[mi][nj][1]);
            *(float2*)(&g_U[(size_t)r*Nn*Dd + (size_t)(row+8)*Dd + col]) = make_float2(acc[mi][nj][2], acc[mi][nj][3]);
        }
    }
}

// ---------------- K4: F[r][n][e] = sum_d X[n][e][d] * U[r][n][d] (round-3 proven) --------
__global__ __launch_bounds__(256) void k_f() {
    int n = blockIdx.x;
    __shared__ float Xs[112*65];
    __shared__ float Us[48*65];
    int tid = threadIdx.x;
    int tx = tid % 16, ty = tid / 16;
    float acc[7][3] = {};
    for (int d0 = 0; d0 < Dd; d0 += 64) {
        for (int i = tid; i < 112*64; i += 256) {
            int e = i >> 6, dd = i & 63;
            Xs[e*65+dd] = (e < Ee) ? g_X[(size_t)(n*Ee+e)*Dd + d0 + dd] : 0.f;
        }
        for (int i = tid; i < 48*64; i += 256) {
            int r = i >> 6, dd = i & 63;
            Us[r*65+dd] = g_U[(size_t)r*Nn*Dd + (size_t)n*Dd + d0 + dd];
        }
        __syncthreads();
        for (int dd = 0; dd < 64; dd++) {
            float u0 = Us[(tx*3+0)*65+dd];
            float u1 = Us[(tx*3+1)*65+dd];
            float u2 = Us[(tx*3+2)*65+dd];
            #pragma unroll
            for (int ee = 0; ee < 7; ee++) {
                float xv = Xs[(ty + ee*16)*65 + dd];
                acc[ee][0] = fmaf(xv, u0, acc[ee][0]);
                acc[ee][1] = fmaf(xv, u1, acc[ee][1]);
                acc[ee][2] = fmaf(xv, u2, acc[ee][2]);
            }
        }
        __syncthreads();
    }
    #pragma unroll
    for (int ee = 0; ee < 7; ee++) {
        int e = ty + ee*16;
        if (e < Ee) {
            #pragma unroll
            for (int rr = 0; rr < 3; rr++) {
                int r = tx*3 + rr;
                g_F[(size_t)r*Nn*Ee + n*Ee + e] = acc[ee][rr];
            }
        }
    }
}

// ---------------- K5a: repack W[:, T-1]^T into [N=1024 (h*128+k)][K=1024 (d)] bf16 hi/lo ----
__global__ void k_repack_bf(const float* __restrict__ W) {
    int idx = blockIdx.x * blockDim.x + threadIdx.x;
    if (idx >= Dd*Dd) return;
    int d = idx & 1023, col = idx >> 10;         // out[col][d]
    int h = col >> 7, k = col & 127;
    float v = W[((size_t)(h*Tt + (Tt-1))*Dd + d)*DHd + k];
    __nv_bfloat16 hi = __float2bfloat16(v);
    g_WBh[idx] = hi;
    g_WBl[idx] = __float2bfloat16(v - __bfloat162float(hi));
}

// ---------------- K5b: HL = X @ WB^T via mma.sync bf16 (round-3 proven) ----------------
__global__ __launch_bounds__(256) void k_hl_mma() {
    extern __shared__ __nv_bfloat16 sm[];
    __nv_bfloat16* sAh = sm;
    __nv_bfloat16* sAl = sm + HL_TILE_ELEMS;
    __nv_bfloat16* sBh = sm + 2*HL_TILE_ELEMS;
    __nv_bfloat16* sBl = sm + 3*HL_TILE_ELEMS;
    int tid = threadIdx.x;
    int warp = tid >> 5, lane = tid & 31;
    int wm = warp & 3, wn = warp >> 2;
    int g = lane >> 2, tg = lane & 3;
    int n0 = blockIdx.x * 128;
    int m0 = blockIdx.y * 128;

    float acc[2][8][4];
    #pragma unroll
    for (int i=0;i<2;i++)
        #pragma unroll
        for (int j=0;j<8;j++)
            #pragma unroll
            for (int q=0;q<4;q++) acc[i][j][q] = 0.f;

    int sr = tid >> 3;
    int sc = (tid & 7) * 8;

    for (int kc = 0; kc < 16; kc++) {
        const __nv_bfloat16* Ah = g_Xh  + (size_t)m0 * Dd + kc*64;
        const __nv_bfloat16* Al = g_Xl  + (size_t)m0 * Dd + kc*64;
        const __nv_bfloat16* Bh = g_WBh + (size_t)n0 * Dd + kc*64;
        const __nv_bfloat16* Bl = g_WBl + (size_t)n0 * Dd + kc*64;
        #pragma unroll
        for (int it = 0; it < 4; it++) {
            int r = sr + it*32;
            size_t go = (size_t)r * Dd + sc;
            int so = r * HLP + sc;
            *(uint4*)(sAh + so) = *(const uint4*)(Ah + go);
            *(uint4*)(sAl + so) = *(const uint4*)(Al + go);
            *(uint4*)(sBh + so) = *(const uint4*)(Bh + go);
            *(uint4*)(sBl + so) = *(const uint4*)(Bl + go);
        }
        __syncthreads();
        #pragma unroll
        for (int ks = 0; ks < 4; ks++) {
            int kb = ks * 16;
            uint32_t ah[2][4], al[2][4];
            #pragma unroll
            for (int mi = 0; mi < 2; mi++) {
                int row = wm*32 + mi*16 + g;
                const __nv_bfloat16* p0 = sAh + row*HLP + kb + tg*2;
                const __nv_bfloat16* p1 = sAh + (row+8)*HLP + kb + tg*2;
                ah[mi][0] = *(const uint32_t*)(p0);
                ah[mi][1] = *(const uint32_t*)(p1);
                ah[mi][2] = *(const uint32_t*)(p0 + 8);
                ah[mi][3] = *(const uint32_t*)(p1 + 8);
                const __nv_bfloat16* q0 = sAl + row*HLP + kb + tg*2;
                const __nv_bfloat16* q1 = sAl + (row+8)*HLP + kb + tg*2;
                al[mi][0] = *(const uint32_t*)(q0);
                al[mi][1] = *(const uint32_t*)(q1);
                al[mi][2] = *(const uint32_t*)(q0 + 8);
                al[mi][3] = *(const uint32_t*)(q1 + 8);
            }
            #pragma unroll
            for (int nj = 0; nj < 8; nj++) {
                int col = wn*64 + nj*8 + g;
                const __nv_bfloat16* pb = sBh + col*HLP + kb + tg*2;
                const __nv_bfloat16* pl = sBl + col*HLP + kb + tg*2;
                uint32_t bh0 = *(const uint32_t*)(pb);
                uint32_t bh1 = *(const uint32_t*)(pb + 8);
                uint32_t bl0 = *(const uint32_t*)(pl);
                uint32_t bl1 = *(const uint32_t*)(pl + 8);
                #pragma unroll
                for (int mi = 0; mi < 2; mi++) {
                    mma16816(acc[mi][nj], ah[mi], bh0, bh1);
                    mma16816(acc[mi][nj], ah[mi], bl0, bl1);
                    mma16816(acc[mi][nj], al[mi], bh0, bh1);
                }
            }
        }
        __syncthreads();
    }

    #pragma unroll
    for (int mi = 0; mi < 2; mi++) {
        int row = m0 + wm*32 + mi*16 + g;
        #pragma unroll
        for (int nj = 0; nj < 8; nj++) {
            int col = n0 + wn*64 + nj*8 + tg*2;
            *(float2*)(&g_HL[(size_t)row * Dd + col])     = make_float2(acc[mi][nj][0], acc[mi][nj][1]);
            *(float2*)(&g_HL[(size_t)(row+8) * Dd + col]) = make_float2(acc[mi][nj][2], acc[mi][nj][3]);
        }
    }
}

// ---------------- K6: edge-type score + softmax + aggregate + relu + residual ----------------
__device__ __forceinline__ float k6_score(int t, const float* f1s, const float* f2s, int i, int j) {
    if (t > 0) {
        float v = f1s[(t-1)*Ee + i] + f2s[(t-1)*Ee + j];
        return v > 0.f ? v : 0.2f*v;
    }
    return NEGV;
}

__global__ __launch_bounds__(128) void k6_attn(const int* __restrict__ adj, float* __restrict__ out) {
    int h = blockIdx.x, n = blockIdx.y;
    extern __shared__ float smx[];
    float* HLs  = smx;                   // 105*128
    float* carr = smx + Ee*128;          // 105*4
    float* f1s  = carr + Ee*4;           // 3*105
    float* f2s  = f1s + Tt*Ee;           // 3*105
    int tid = threadIdx.x;
    int lane = tid & 31, w = tid >> 5;

    for (int i = tid; i < Tt*Ee; i += 128) {
        int t = i / Ee, e = i % Ee;
        f1s[i] = g_F[(size_t)(h*Tt+t)*Nn*Ee + n*Ee + e];
        f2s[i] = g_F[(size_t)HT*Nn*Ee + (size_t)(h*Tt+t)*Nn*Ee + n*Ee + e];
    }
    for (int j = 0; j < Ee; j++)
        HLs[j*128 + tid] = g_HL[(size_t)(n*Ee+j)*Dd + h*DHd + tid] * g_mask[n*Ee + j];
    __syncthreads();

    const int* adjn = adj + n*Ee*Ee;
    for (int ig = 0; ig < 27; ig++) {
        int i0 = ig*4;
        int ni = Ee - i0; if (ni > 4) ni = 4;
        if (w < ni) {
            int i = i0 + w;
            const int* arow = adjn + i*Ee;
            float s0 = k6_score(arow[lane],    f1s, f2s, i, lane);
            float s1 = k6_score(arow[lane+32], f1s, f2s, i, lane+32);
            float s2 = k6_score(arow[lane+64], f1s, f2s, i, lane+64);
            float s3 = (lane < 9) ? k6_score(arow[lane+96], f1s, f2s, i, lane+96) : -INFINITY;
            float m = fmaxf(fmaxf(s0, s1), fmaxf(s2, s3));
            #pragma unroll
            for (int o = 16; o > 0; o >>= 1) m = fmaxf(m, __shfl_xor_sync(0xffffffffu, m, o));
            float p0 = __expf(s0 - m), p1 = __expf(s1 - m), p2 = __expf(s2 - m);
            float p3 = (lane < 9) ? __expf(s3 - m) : 0.f;
            float sum = p0 + p1 + p2 + p3;
            #pragma unroll
            for (int o = 16; o > 0; o >>= 1) sum += __shfl_xor_sync(0xffffffffu, sum, o);
            float inv = 1.f / sum;
            carr[lane*4 + w]      = p0 * inv;
            carr[(lane+32)*4 + w] = p1 * inv;
            carr[(lane+64)*4 + w] = p2 * inv;
            if (lane < 9) carr[(lane+96)*4 + w] = p3 * inv;
        } else {
            for (int j = lane; j < Ee; j += 32) carr[j*4 + w] = 0.f;
        }
        __syncthreads();
        float acc0=0.f, acc1=0.f, acc2=0.f, acc3=0.f;
        #pragma unroll 7
        for (int j = 0; j < Ee; j++) {
            float4 c = *(const float4*)(carr + j*4);
            float hl = HLs[j*128 + tid];
            acc0 = fmaf(c.x, hl, acc0);
            acc1 = fmaf(c.y, hl, acc1);
            acc2 = fmaf(c.z, hl, acc2);
            acc3 = fmaf(c.w, hl, acc3);
        }
        int col = h*DHd + tid;
        #pragma unroll
        for (int ii = 0; ii < 4; ii++) {
            if (ii < ni) {
                float a = (ii==0)?acc0:(ii==1)?acc1:(ii==2)?acc2:acc3;
                int i = i0 + ii;
                out[(size_t)(n*Ee + i)*Dd + col] = fmaxf(a, 0.f) + g_X[(size_t)(n*Ee + i)*Dd + col];
            }
        }
        __syncthreads();
    }
}

#define K6_SMEM_BYTES ((Ee*128 + Ee*4 + 2*Tt*Ee) * 4)

// ---------------- launch ----------------
extern "C" void kernel_launch(void* const* d_in, const int* in_sizes, int n_in,
                              void* d_out, int out_size) {
    const float* q    = (const float*)d_in[0];
    const float* para = (const float*)d_in[1];
    const float* sent = (const float*)d_in[2];
    const float* ent  = (const float*)d_in[3];
    const float* pm   = (const float*)d_in[4];
    const float* sm_  = (const float*)d_in[5];
    const float* em   = (const float*)d_in[6];
    const int*   adj  = (const int*)  d_in[7];
    const float* W    = (const float*)d_in[8];
    const float* a    = (const float*)d_in[9];
    const float* qW1  = (const float*)d_in[10];
    const float* qW2  = (const float*)d_in[11];
    float* out = (float*)d_out;

    cudaFuncSetAttribute(k6_attn,  cudaFuncAttributeMaxDynamicSharedMemorySize, K6_SMEM_BYTES);
    cudaFuncSetAttribute(k_hl_mma, cudaFuncAttributeMaxDynamicSharedMemorySize, HL_SMEM_BYTES);
    cudaFuncSetAttribute(k_u_mma,  cudaFuncAttributeMaxDynamicSharedMemorySize, HL_SMEM_BYTES);

    k_concat<<<(Nn*Ee*Dd + 255)/256, 256>>>(q, para, sent, ent);
    k_mask  <<<(Nn*Ee + 255)/256, 256>>>(pm, sm_, em);
    k_gemm_qw1<<<dim3(4,4,HT), 256>>>(q, qW1);
    k_gemm_qw2<<<dim3(4,4,HT), 256>>>(qW2, a);
    k_u_mma  <<<dim3(8,2,2*HT), 256, HL_SMEM_BYTES>>>(W);
    k_f      <<<Nn, 256>>>();
    k_repack_bf<<<(Dd*Dd + 255)/256, 256>>>(W);
    k_hl_mma <<<dim3(8,210), 256, HL_SMEM_BYTES>>>();
    k6_attn  <<<dim3(Hh,Nn), 128, K6_SMEM_BYTES>>>(adj, out);
}

// round 9
// speedup vs baseline: 2.2001x; 1.1304x over previous
#include <cuda_runtime.h>
#include <cuda_bf16.h>
#include <math.h>
#include <stdint.h>

#define Nn 256
#define Pp 4
#define Sr 40
#define Enn 60
#define Ee 105
#define Dd 1024
#define Hh 8
#define Tt 3
#define DHd 128
#define HT 24           // H*T
#define NEGV -1e30f

// ---------------- scratch (device globals; no allocations allowed) ----------------
static __device__ float g_X [Nn*Ee*Dd];           // concat input fp32 (110 MB)
static __device__ __nv_bfloat16 g_Xh[Nn*Ee*Dd];   // bf16 hi split of X
static __device__ __nv_bfloat16 g_Xl[Nn*Ee*Dd];   // bf16 lo split of X
static __device__ float g_mask[Nn*Ee];
static __device__ __nv_bfloat16 g_qh[Nn*Dd];      // q split
static __device__ __nv_bfloat16 g_ql[Nn*Dd];
static __device__ __nv_bfloat16 g_q1h[HT*256*Dd]; // qW1^T split: [ht][n=256][k=1024]
static __device__ __nv_bfloat16 g_q1l[HT*256*Dd];
static __device__ float g_R [HT*Nn*256];          // relu(q @ qW1)
static __device__ float g_V [2*HT*Nn*DHd];        // v1 (r=ht), v2 (r=24+ht)  fp32
static __device__ float g_U [2*HT*Nn*Dd];         // u = W @ v (fp32)
static __device__ float g_F [2*HT*Nn*Ee];         // f1, f2  [r][n][e]
static __device__ __nv_bfloat16 g_WBh[Dd*Dd];     // W[:,T-1]^T as [N=1024][K=1024] bf16 hi
static __device__ __nv_bfloat16 g_WBl[Dd*Dd];     // lo
static __device__ float g_HL[Nn*Ee*Dd];           // h_last (pre-mask) (110 MB)

// ---------------- K1: concat x (fp32 + bf16 hi/lo split) ----------------
__global__ void k_concat(const float* __restrict__ q, const float* __restrict__ para,
                         const float* __restrict__ sent, const float* __restrict__ ent) {
    int idx = blockIdx.x * blockDim.x + threadIdx.x;
    if (idx >= Nn*Ee*Dd) return;
    int d  = idx & (Dd-1);
    int ne = idx >> 10;
    int e  = ne % Ee;
    int n  = ne / Ee;
    float v;
    if (e == 0)              v = q   [n*Dd + d];
    else if (e < 1+Pp)       v = para[(n*Pp  + (e-1))*Dd + d];
    else if (e < 1+Pp+Sr)    v = sent[(n*Sr  + (e-1-Pp))*Dd + d];
    else                     v = ent [(n*Enn + (e-1-Pp-Sr))*Dd + d];
    g_X[idx] = v;
    __nv_bfloat16 hi = __float2bfloat16(v);
    g_Xh[idx] = hi;
    g_Xl[idx] = __float2bfloat16(v - __bfloat162float(hi));
}

__global__ void k_mask(const float* __restrict__ pm, const float* __restrict__ sm_,
                       const float* __restrict__ em) {
    int idx = blockIdx.x * blockDim.x + threadIdx.x;
    if (idx >= Nn*Ee) return;
    int e = idx % Ee, n = idx / Ee;
    float v;
    if (e == 0)            v = 1.f;
    else if (e < 1+Pp)     v = pm[n*Pp  + e-1];
    else if (e < 1+Pp+Sr)  v = sm_[n*Sr + e-1-Pp];
    else                   v = em[n*Enn + e-1-Pp-Sr];
    g_mask[idx] = v;
}

__global__ void k_split_q(const float* __restrict__ q) {
    int idx = blockIdx.x * blockDim.x + threadIdx.x;
    if (idx >= Nn*Dd) return;
    float v = q[idx];
    __nv_bfloat16 hi = __float2bfloat16(v);
    g_qh[idx] = hi;
    g_ql[idx] = __float2bfloat16(v - __bfloat162float(hi));
}

// transpose+split qW1: [ht][k=1024][n=256] -> [ht][n=256][k=1024]
__global__ void k_tsplit_qw1(const float* __restrict__ qW1) {
    __shared__ float t[32][33];
    int ht = blockIdx.z;
    int k0 = blockIdx.x*32, n0 = blockIdx.y*32;
    int tx = threadIdx.x, ty = threadIdx.y;     // 32x8
    const float* src = qW1 + (size_t)ht*Dd*256;
    #pragma unroll
    for (int j = 0; j < 4; j++)
        t[ty+8*j][tx] = src[(size_t)(k0+ty+8*j)*256 + n0 + tx];
    __syncthreads();
    #pragma unroll
    for (int j = 0; j < 4; j++) {
        int nrow = n0 + ty + 8*j;
        int kcol = k0 + tx;
        float v = t[tx][ty+8*j];
        __nv_bfloat16 hi = __float2bfloat16(v);
        size_t o = (size_t)ht*256*Dd + (size_t)nrow*Dd + kcol;
        g_q1h[o] = hi;
        g_q1l[o] = __float2bfloat16(v - __bfloat162float(hi));
    }
}

// ---------------- shared mma bits ----------------
#define HLP 72
#define HL_TILE_ELEMS (128*HLP)
#define HL_SMEM_BYTES (4*HL_TILE_ELEMS*2)

__device__ __forceinline__ void mma16816(float* c, const uint32_t* a, uint32_t b0, uint32_t b1) {
    asm volatile(
        "mma.sync.aligned.m16n8k16.row.col.f32.bf16.bf16.f32 "
        "{%0,%1,%2,%3}, {%4,%5,%6,%7}, {%8,%9}, {%0,%1,%2,%3};"
        : "+f"(c[0]), "+f"(c[1]), "+f"(c[2]), "+f"(c[3])
        : "r"(a[0]), "r"(a[1]), "r"(a[2]), "r"(a[3]), "r"(b0), "r"(b1));
}

__device__ __forceinline__ void split2(float x, float y, __nv_bfloat162* ph, __nv_bfloat162* pl) {
    __nv_bfloat162 h, l;
    h.x = __float2bfloat16(x);
    h.y = __float2bfloat16(y);
    l.x = __float2bfloat16(x - __bfloat162float(h.x));
    l.y = __float2bfloat16(y - __bfloat162float(h.y));
    *ph = h; *pl = l;
}

// ---------------- K2a: R = relu(q @ qW1[ht]^T) via mma clone ----------------
// grid (2, 2, 24): n0 = x*128 (out col), m0 = y*128 (n row), ht = z
__global__ __launch_bounds__(256) void k_qw1_mma() {
    extern __shared__ __nv_bfloat16 sm[];
    __nv_bfloat16* sAh = sm;
    __nv_bfloat16* sAl = sm + HL_TILE_ELEMS;
    __nv_bfloat16* sBh = sm + 2*HL_TILE_ELEMS;
    __nv_bfloat16* sBl = sm + 3*HL_TILE_ELEMS;
    int tid = threadIdx.x;
    int warp = tid >> 5, lane = tid & 31;
    int wm = warp & 3, wn = warp >> 2;
    int g = lane >> 2, tg = lane & 3;
    int n0 = blockIdx.x * 128;
    int m0 = blockIdx.y * 128;
    int ht = blockIdx.z;

    const __nv_bfloat16* Ahb = g_qh + (size_t)m0 * Dd;
    const __nv_bfloat16* Alb = g_ql + (size_t)m0 * Dd;
    const __nv_bfloat16* Bhb = g_q1h + (size_t)ht*256*Dd + (size_t)n0 * Dd;
    const __nv_bfloat16* Blb = g_q1l + (size_t)ht*256*Dd + (size_t)n0 * Dd;

    float acc[2][8][4];
    #pragma unroll
    for (int i=0;i<2;i++)
        #pragma unroll
        for (int j=0;j<8;j++)
            #pragma unroll
            for (int q=0;q<4;q++) acc[i][j][q] = 0.f;

    int sr = tid >> 3;
    int sc = (tid & 7) * 8;

    for (int kc = 0; kc < 16; kc++) {
        #pragma unroll
        for (int it = 0; it < 4; it++) {
            int r = sr + it*32;
            size_t go = (size_t)r * Dd + kc*64 + sc;
            int so = r * HLP + sc;
            *(uint4*)(sAh + so) = *(const uint4*)(Ahb + go);
            *(uint4*)(sAl + so) = *(const uint4*)(Alb + go);
            *(uint4*)(sBh + so) = *(const uint4*)(Bhb + go);
            *(uint4*)(sBl + so) = *(const uint4*)(Blb + go);
        }
        __syncthreads();
        #pragma unroll
        for (int ks = 0; ks < 4; ks++) {
            int kb = ks * 16;
            uint32_t ah[2][4], al[2][4];
            #pragma unroll
            for (int mi = 0; mi < 2; mi++) {
                int row = wm*32 + mi*16 + g;
                const __nv_bfloat16* p0 = sAh + row*HLP + kb + tg*2;
                const __nv_bfloat16* p1 = sAh + (row+8)*HLP + kb + tg*2;
                ah[mi][0] = *(const uint32_t*)(p0);
                ah[mi][1] = *(const uint32_t*)(p1);
                ah[mi][2] = *(const uint32_t*)(p0 + 8);
                ah[mi][3] = *(const uint32_t*)(p1 + 8);
                const __nv_bfloat16* q0 = sAl + row*HLP + kb + tg*2;
                const __nv_bfloat16* q1 = sAl + (row+8)*HLP + kb + tg*2;
                al[mi][0] = *(const uint32_t*)(q0);
                al[mi][1] = *(const uint32_t*)(q1);
                al[mi][2] = *(const uint32_t*)(q0 + 8);
                al[mi][3] = *(const uint32_t*)(q1 + 8);
            }
            #pragma unroll
            for (int nj = 0; nj < 8; nj++) {
                int col = wn*64 + nj*8 + g;
                const __nv_bfloat16* pb = sBh + col*HLP + kb + tg*2;
                const __nv_bfloat16* pl = sBl + col*HLP + kb + tg*2;
                uint32_t bh0 = *(const uint32_t*)(pb);
                uint32_t bh1 = *(const uint32_t*)(pb + 8);
                uint32_t bl0 = *(const uint32_t*)(pl);
                uint32_t bl1 = *(const uint32_t*)(pl + 8);
                #pragma unroll
                for (int mi = 0; mi < 2; mi++) {
                    mma16816(acc[mi][nj], ah[mi], bh0, bh1);
                    mma16816(acc[mi][nj], ah[mi], bl0, bl1);
                    mma16816(acc[mi][nj], al[mi], bh0, bh1);
                }
            }
        }
        __syncthreads();
    }

    float* Cb = g_R + (size_t)ht*Nn*256;
    #pragma unroll
    for (int mi = 0; mi < 2; mi++) {
        int row = m0 + wm*32 + mi*16 + g;
        #pragma unroll
        for (int nj = 0; nj < 8; nj++) {
            int col = n0 + wn*64 + nj*8 + tg*2;
            *(float2*)(&Cb[(size_t)row*256 + col]) =
                make_float2(fmaxf(acc[mi][nj][0], 0.f), fmaxf(acc[mi][nj][1], 0.f));
            *(float2*)(&Cb[(size_t)(row+8)*256 + col]) =
                make_float2(fmaxf(acc[mi][nj][2], 0.f), fmaxf(acc[mi][nj][3], 0.f));
        }
    }
}

// ---------------- K2b: S = sigmoid(R @ qW2[ht]); V = S * a (fp32, round-3 proven) --------
__global__ __launch_bounds__(256) void k_gemm_qw2(const float* __restrict__ qW2,
                                                  const float* __restrict__ a_in) {
    int ht = blockIdx.z;
    int m0 = blockIdx.x*64, n0 = blockIdx.y*64;
    __shared__ float As[16][64];
    __shared__ float Bs[16][64];
    int tid = threadIdx.x;
    int tr = tid/16, tc = tid%16;
    int lm = tid/4,  lk4 = (tid%4)*4;
    int lbk = tid/16, lbc4 = (tid%16)*4;
    const float* Ab = g_R + (size_t)ht*Nn*256;
    const float* Bb = qW2 + (size_t)ht*256*256;
    float acc[4][4] = {};
    for (int k0 = 0; k0 < 256; k0 += 16) {
        float4 av = *(const float4*)(Ab + (m0+lm)*256 + k0 + lk4);
        As[lk4+0][lm]=av.x; As[lk4+1][lm]=av.y; As[lk4+2][lm]=av.z; As[lk4+3][lm]=av.w;
        float4 bv = *(const float4*)(Bb + (size_t)(k0+lbk)*256 + n0 + lbc4);
        *(float4*)(&Bs[lbk][lbc4]) = bv;
        __syncthreads();
        #pragma unroll
        for (int kk = 0; kk < 16; kk++) {
            float4 a = *(const float4*)(&As[kk][tr*4]);
            float4 b = *(const float4*)(&Bs[kk][tc*4]);
            float aa[4]={a.x,a.y,a.z,a.w}, bb[4]={b.x,b.y,b.z,b.w};
            #pragma unroll
            for (int i=0;i<4;i++)
                #pragma unroll
                for (int j=0;j<4;j++) acc[i][j] = fmaf(aa[i], bb[j], acc[i][j]);
        }
        __syncthreads();
    }
    const float* av = a_in + ht*256;
    #pragma unroll
    for (int i=0;i<4;i++) {
        int row = m0 + tr*4 + i;
        #pragma unroll
        for (int j=0;j<4;j++) {
            int col = n0 + tc*4 + j;
            float s = 1.f / (1.f + __expf(-acc[i][j]));
            float val = s * av[col];
            if (col < DHd) g_V[(size_t)ht*Nn*DHd + row*DHd + col] = val;
            else           g_V[(size_t)HT*Nn*DHd + (size_t)ht*Nn*DHd + row*DHd + (col-DHd)] = val;
        }
    }
}

// ---------------- K3: U[r] = V[r] @ W[ht]^T via mma (round-8 proven clone) ----------------
__global__ __launch_bounds__(256) void k_u_mma(const float* __restrict__ W) {
    extern __shared__ __nv_bfloat16 sm[];
    __nv_bfloat16* sAh = sm;
    __nv_bfloat16* sAl = sm + HL_TILE_ELEMS;
    __nv_bfloat16* sBh = sm + 2*HL_TILE_ELEMS;
    __nv_bfloat16* sBl = sm + 3*HL_TILE_ELEMS;
    int tid = threadIdx.x;
    int warp = tid >> 5, lane = tid & 31;
    int wm = warp & 3, wn = warp >> 2;
    int g = lane >> 2, tg = lane & 3;
    int n0 = blockIdx.x * 128;
    int m0 = blockIdx.y * 128;
    int r  = blockIdx.z;
    int ht = r % HT;

    const float* Ab = g_V + (size_t)r*Nn*DHd + (size_t)m0*DHd;
    const float* Bb = W   + (size_t)ht*Dd*DHd + (size_t)n0*DHd;

    float acc[2][8][4];
    #pragma unroll
    for (int i=0;i<2;i++)
        #pragma unroll
        for (int j=0;j<8;j++)
            #pragma unroll
            for (int q=0;q<4;q++) acc[i][j][q] = 0.f;

    int sr = tid >> 3;
    int sc = (tid & 7) * 8;

    for (int kc = 0; kc < 2; kc++) {
        #pragma unroll
        for (int it = 0; it < 4; it++) {
            int rr = sr + it*32;
            const float* pa = Ab + (size_t)rr*DHd + kc*64 + sc;
            const float* pb = Bb + (size_t)rr*DHd + kc*64 + sc;
            int so = rr * HLP + sc;
            #pragma unroll
            for (int jj = 0; jj < 8; jj += 4) {
                float4 va = *(const float4*)(pa + jj);
                split2(va.x, va.y, (__nv_bfloat162*)(sAh + so + jj),     (__nv_bfloat162*)(sAl + so + jj));
                split2(va.z, va.w, (__nv_bfloat162*)(sAh + so + jj + 2), (__nv_bfloat162*)(sAl + so + jj + 2));
                float4 vb = *(const float4*)(pb + jj);
                split2(vb.x, vb.y, (__nv_bfloat162*)(sBh + so + jj),     (__nv_bfloat162*)(sBl + so + jj));
                split2(vb.z, vb.w, (__nv_bfloat162*)(sBh + so + jj + 2), (__nv_bfloat162*)(sBl + so + jj + 2));
            }
        }
        __syncthreads();
        #pragma unroll
        for (int ks = 0; ks < 4; ks++) {
            int kb = ks * 16;
            uint32_t ah[2][4], al[2][4];
            #pragma unroll
            for (int mi = 0; mi < 2; mi++) {
                int row = wm*32 + mi*16 + g;
                const __nv_bfloat16* p0 = sAh + row*HLP + kb + tg*2;
                const __nv_bfloat16* p1 = sAh + (row+8)*HLP + kb + tg*2;
                ah[mi][0] = *(const uint32_t*)(p0);
                ah[mi][1] = *(const uint32_t*)(p1);
                ah[mi][2] = *(const uint32_t*)(p0 + 8);
                ah[mi][3] = *(const uint32_t*)(p1 + 8);
                const __nv_bfloat16* q0 = sAl + row*HLP + kb + tg*2;
                const __nv_bfloat16* q1 = sAl + (row+8)*HLP + kb + tg*2;
                al[mi][0] = *(const uint32_t*)(q0);
                al[mi][1] = *(const uint32_t*)(q1);
                al[mi][2] = *(const uint32_t*)(q0 + 8);
                al[mi][3] = *(const uint32_t*)(q1 + 8);
            }
            #pragma unroll
            for (int nj = 0; nj < 8; nj++) {
                int col = wn*64 + nj*8 + g;
                const __nv_bfloat16* pb = sBh + col*HLP + kb + tg*2;
                const __nv_bfloat16* pl = sBl + col*HLP + kb + tg*2;
                uint32_t bh0 = *(const uint32_t*)(pb);
                uint32_t bh1 = *(const uint32_t*)(pb + 8);
                uint32_t bl0 = *(const uint32_t*)(pl);
                uint32_t bl1 = *(const uint32_t*)(pl + 8);
                #pragma unroll
                for (int mi = 0; mi < 2; mi++) {
                    mma16816(acc[mi][nj], ah[mi], bh0, bh1);
                    mma16816(acc[mi][nj], ah[mi], bl0, bl1);
                    mma16816(acc[mi][nj], al[mi], bh0, bh1);
                }
            }
        }
        __syncthreads();
    }

    #pragma unroll
    for (int mi = 0; mi < 2; mi++) {
        int row = m0 + wm*32 + mi*16 + g;
        #pragma unroll
        for (int nj = 0; nj < 8; nj++) {
            int col = n0 + wn*64 + nj*8 + tg*2;
            *(float2*)(&g_U[(size_t)r*Nn*Dd + (size_t)row*Dd + col])     = make_float2(acc[mi][nj][0], acc[mi][nj][1]);
            *(float2*)(&g_U[(size_t)r*Nn*Dd + (size_t)(row+8)*Dd + col]) = make_float2(acc[mi][nj][2], acc[mi][nj][3]);
        }
    }
}

// ---------------- K4: F via mma: per n, C[e][r] = X[n] (105x1024) @ U[.,n,.]^T (48 rows) --
__global__ __launch_bounds__(256) void k_f_mma() {
    extern __shared__ __nv_bfloat16 sm[];
    __nv_bfloat16* sAh = sm;
    __nv_bfloat16* sAl = sm + HL_TILE_ELEMS;
    __nv_bfloat16* sBh = sm + 2*HL_TILE_ELEMS;
    __nv_bfloat16* sBl = sm + 3*HL_TILE_ELEMS;
    int n = blockIdx.x;
    int tid = threadIdx.x;
    int warp = tid >> 5, lane = tid & 31;
    int wm = warp & 3, wn = warp >> 2;      // rows 32*wm (e), cols 24*wn (r)
    int g = lane >> 2, tg = lane & 3;

    float acc[2][3][4];
    #pragma unroll
    for (int i=0;i<2;i++)
        #pragma unroll
        for (int j=0;j<3;j++)
            #pragma unroll
            for (int q=0;q<4;q++) acc[i][j][q] = 0.f;

    int sr = tid >> 3;
    int sc = (tid & 7) * 8;
    const __nv_bfloat16* Ahb = g_Xh + (size_t)n * Ee * Dd;
    const __nv_bfloat16* Alb = g_Xl + (size_t)n * Ee * Dd;

    for (int kc = 0; kc < 16; kc++) {
        // A: 128 rows (e, clamped) x 64 cols from precomputed bf16 splits
        #pragma unroll
        for (int it = 0; it < 4; it++) {
            int r = sr + it*32;
            int rc = (r < Ee) ? r : (Ee-1);
            size_t go = (size_t)rc * Dd + kc*64 + sc;
            int so = r * HLP + sc;
            *(uint4*)(sAh + so) = *(const uint4*)(Ahb + go);
            *(uint4*)(sAl + so) = *(const uint4*)(Alb + go);
        }
        // B: 48 rows (r) x 64 cols, inline split of fp32 U
        for (int i = tid; i < 384; i += 256) {
            int r = i >> 3, c = (i & 7) * 8;
            const float* pb = g_U + (size_t)r*(Nn*Dd) + (size_t)n*Dd + kc*64 + c;
            int so = r * HLP + c;
            #pragma unroll
            for (int jj = 0; jj < 8; jj += 4) {
                float4 vb = *(const float4*)(pb + jj);
                split2(vb.x, vb.y, (__nv_bfloat162*)(sBh + so + jj),     (__nv_bfloat162*)(sBl + so + jj));
                split2(vb.z, vb.w, (__nv_bfloat162*)(sBh + so + jj + 2), (__nv_bfloat162*)(sBl + so + jj + 2));
            }
        }
        __syncthreads();
        #pragma unroll
        for (int ks = 0; ks < 4; ks++) {
            int kb = ks * 16;
            uint32_t ah[2][4], al[2][4];
            #pragma unroll
            for (int mi = 0; mi < 2; mi++) {
                int row = wm*32 + mi*16 + g;
                const __nv_bfloat16* p0 = sAh + row*HLP + kb + tg*2;
                const __nv_bfloat16* p1 = sAh + (row+8)*HLP + kb + tg*2;
                ah[mi][0] = *(const uint32_t*)(p0);
                ah[mi][1] = *(const uint32_t*)(p1);
                ah[mi][2] = *(const uint32_t*)(p0 + 8);
                ah[mi][3] = *(const uint32_t*)(p1 + 8);
                const __nv_bfloat16* q0 = sAl + row*HLP + kb + tg*2;
                const __nv_bfloat16* q1 = sAl + (row+8)*HLP + kb + tg*2;
                al[mi][0] = *(const uint32_t*)(q0);
                al[mi][1] = *(const uint32_t*)(q1);
                al[mi][2] = *(const uint32_t*)(q0 + 8);
                al[mi][3] = *(const uint32_t*)(q1 + 8);
            }
            #pragma unroll
            for (int nj = 0; nj < 3; nj++) {
                int col = wn*24 + nj*8 + g;
                const __nv_bfloat16* pb = sBh + col*HLP + kb + tg*2;
                const __nv_bfloat16* pl = sBl + col*HLP + kb + tg*2;
                uint32_t bh0 = *(const uint32_t*)(pb);
                uint32_t bh1 = *(const uint32_t*)(pb + 8);
                uint32_t bl0 = *(const uint32_t*)(pl);
                uint32_t bl1 = *(const uint32_t*)(pl + 8);
                #pragma unroll
                for (int mi = 0; mi < 2; mi++) {
                    mma16816(acc[mi][nj], ah[mi], bh0, bh1);
                    mma16816(acc[mi][nj], ah[mi], bl0, bl1);
                    mma16816(acc[mi][nj], al[mi], bh0, bh1);
                }
            }
        }
        __syncthreads();
    }

    // epilogue: g_F[r][n][e]
    #pragma unroll
    for (int mi = 0; mi < 2; mi++) {
        int e0 = wm*32 + mi*16 + g;
        #pragma unroll
        for (int nj = 0; nj < 3; nj++) {
            int r = wn*24 + nj*8 + tg*2;
            if (e0 < Ee) {
                g_F[(size_t)r*Nn*Ee + n*Ee + e0]     = acc[mi][nj][0];
                g_F[(size_t)(r+1)*Nn*Ee + n*Ee + e0] = acc[mi][nj][1];
            }
            if (e0 + 8 < Ee) {
                g_F[(size_t)r*Nn*Ee + n*Ee + e0 + 8]     = acc[mi][nj][2];
                g_F[(size_t)(r+1)*Nn*Ee + n*Ee + e0 + 8] = acc[mi][nj][3];
            }
        }
    }
}

// ---------------- K5a: repack W[:, T-1]^T into [N=1024 (h*128+k)][K=1024 (d)] bf16 hi/lo ----
__global__ void k_repack_bf(const float* __restrict__ W) {
    int idx = blockIdx.x * blockDim.x + threadIdx.x;
    if (idx >= Dd*Dd) return;
    int d = idx & 1023, col = idx >> 10;         // out[col][d]
    int h = col >> 7, k = col & 127;
    float v = W[((size_t)(h*Tt + (Tt-1))*Dd + d)*DHd + k];
    __nv_bfloat16 hi = __float2bfloat16(v);
    g_WBh[idx] = hi;
    g_WBl[idx] = __float2bfloat16(v - __bfloat162float(hi));
}

// ---------------- K5b: HL = X @ WB^T via mma.sync bf16 (round-3 proven) ----------------
__global__ __launch_bounds__(256) void k_hl_mma() {
    extern __shared__ __nv_bfloat16 sm[];
    __nv_bfloat16* sAh = sm;
    __nv_bfloat16* sAl = sm + HL_TILE_ELEMS;
    __nv_bfloat16* sBh = sm + 2*HL_TILE_ELEMS;
    __nv_bfloat16* sBl = sm + 3*HL_TILE_ELEMS;
    int tid = threadIdx.x;
    int warp = tid >> 5, lane = tid & 31;
    int wm = warp & 3, wn = warp >> 2;
    int g = lane >> 2, tg = lane & 3;
    int n0 = blockIdx.x * 128;
    int m0 = blockIdx.y * 128;

    float acc[2][8][4];
    #pragma unroll
    for (int i=0;i<2;i++)
        #pragma unroll
        for (int j=0;j<8;j++)
            #pragma unroll
            for (int q=0;q<4;q++) acc[i][j][q] = 0.f;

    int sr = tid >> 3;
    int sc = (tid & 7) * 8;

    for (int kc = 0; kc < 16; kc++) {
        const __nv_bfloat16* Ah = g_Xh  + (size_t)m0 * Dd + kc*64;
        const __nv_bfloat16* Al = g_Xl  + (size_t)m0 * Dd + kc*64;
        const __nv_bfloat16* Bh = g_WBh + (size_t)n0 * Dd + kc*64;
        const __nv_bfloat16* Bl = g_WBl + (size_t)n0 * Dd + kc*64;
        #pragma unroll
        for (int it = 0; it < 4; it++) {
            int r = sr + it*32;
            size_t go = (size_t)r * Dd + sc;
            int so = r * HLP + sc;
            *(uint4*)(sAh + so) = *(const uint4*)(Ah + go);
            *(uint4*)(sAl + so) = *(const uint4*)(Al + go);
            *(uint4*)(sBh + so) = *(const uint4*)(Bh + go);
            *(uint4*)(sBl + so) = *(const uint4*)(Bl + go);
        }
        __syncthreads();
        #pragma unroll
        for (int ks = 0; ks < 4; ks++) {
            int kb = ks * 16;
            uint32_t ah[2][4], al[2][4];
            #pragma unroll
            for (int mi = 0; mi < 2; mi++) {
                int row = wm*32 + mi*16 + g;
                const __nv_bfloat16* p0 = sAh + row*HLP + kb + tg*2;
                const __nv_bfloat16* p1 = sAh + (row+8)*HLP + kb + tg*2;
                ah[mi][0] = *(const uint32_t*)(p0);
                ah[mi][1] = *(const uint32_t*)(p1);
                ah[mi][2] = *(const uint32_t*)(p0 + 8);
                ah[mi][3] = *(const uint32_t*)(p1 + 8);
                const __nv_bfloat16* q0 = sAl + row*HLP + kb + tg*2;
                const __nv_bfloat16* q1 = sAl + (row+8)*HLP + kb + tg*2;
                al[mi][0] = *(const uint32_t*)(q0);
                al[mi][1] = *(const uint32_t*)(q1);
                al[mi][2] = *(const uint32_t*)(q0 + 8);
                al[mi][3] = *(const uint32_t*)(q1 + 8);
            }
            #pragma unroll
            for (int nj = 0; nj < 8; nj++) {
                int col = wn*64 + nj*8 + g;
                const __nv_bfloat16* pb = sBh + col*HLP + kb + tg*2;
                const __nv_bfloat16* pl = sBl + col*HLP + kb + tg*2;
                uint32_t bh0 = *(const uint32_t*)(pb);
                uint32_t bh1 = *(const uint32_t*)(pb + 8);
                uint32_t bl0 = *(const uint32_t*)(pl);
                uint32_t bl1 = *(const uint32_t*)(pl + 8);
                #pragma unroll
                for (int mi = 0; mi < 2; mi++) {
                    mma16816(acc[mi][nj], ah[mi], bh0, bh1);
                    mma16816(acc[mi][nj], ah[mi], bl0, bl1);
                    mma16816(acc[mi][nj], al[mi], bh0, bh1);
                }
            }
        }
        __syncthreads();
    }

    #pragma unroll
    for (int mi = 0; mi < 2; mi++) {
        int row = m0 + wm*32 + mi*16 + g;
        #pragma unroll
        for (int nj = 0; nj < 8; nj++) {
            int col = n0 + wn*64 + nj*8 + tg*2;
            *(float2*)(&g_HL[(size_t)row * Dd + col])     = make_float2(acc[mi][nj][0], acc[mi][nj][1]);
            *(float2*)(&g_HL[(size_t)(row+8) * Dd + col]) = make_float2(acc[mi][nj][2], acc[mi][nj][3]);
        }
    }
}

// ---------------- K6: edge-type score + softmax + aggregate + relu + residual ----------------
__device__ __forceinline__ float k6_score(int t, const float* f1s, const float* f2s, int i, int j) {
    if (t > 0) {
        float v = f1s[(t-1)*Ee + i] + f2s[(t-1)*Ee + j];
        return v > 0.f ? v : 0.2f*v;
    }
    return NEGV;
}

__global__ __launch_bounds__(128) void k6_attn(const int* __restrict__ adj, float* __restrict__ out) {
    int h = blockIdx.x, n = blockIdx.y;
    extern __shared__ float smx[];
    float* HLs  = smx;                   // 105*128
    float* carr = smx + Ee*128;          // 105*4
    float* f1s  = carr + Ee*4;           // 3*105
    float* f2s  = f1s + Tt*Ee;           // 3*105
    int tid = threadIdx.x;
    int lane = tid & 31, w = tid >> 5;

    for (int i = tid; i < Tt*Ee; i += 128) {
        int t = i / Ee, e = i % Ee;
        f1s[i] = g_F[(size_t)(h*Tt+t)*Nn*Ee + n*Ee + e];
        f2s[i] = g_F[(size_t)HT*Nn*Ee + (size_t)(h*Tt+t)*Nn*Ee + n*Ee + e];
    }
    for (int j = 0; j < Ee; j++)
        HLs[j*128 + tid] = g_HL[(size_t)(n*Ee+j)*Dd + h*DHd + tid] * g_mask[n*Ee + j];
    __syncthreads();

    const int* adjn = adj + n*Ee*Ee;
    for (int ig = 0; ig < 27; ig++) {
        int i0 = ig*4;
        int ni = Ee - i0; if (ni > 4) ni = 4;
        if (w < ni) {
            int i = i0 + w;
            const int* arow = adjn + i*Ee;
            float s0 = k6_score(arow[lane],    f1s, f2s, i, lane);
            float s1 = k6_score(arow[lane+32], f1s, f2s, i, lane+32);
            float s2 = k6_score(arow[lane+64], f1s, f2s, i, lane+64);
            float s3 = (lane < 9) ? k6_score(arow[lane+96], f1s, f2s, i, lane+96) : -INFINITY;
            float m = fmaxf(fmaxf(s0, s1), fmaxf(s2, s3));
            #pragma unroll
            for (int o = 16; o > 0; o >>= 1) m = fmaxf(m, __shfl_xor_sync(0xffffffffu, m, o));
            float p0 = __expf(s0 - m), p1 = __expf(s1 - m), p2 = __expf(s2 - m);
            float p3 = (lane < 9) ? __expf(s3 - m) : 0.f;
            float sum = p0 + p1 + p2 + p3;
            #pragma unroll
            for (int o = 16; o > 0; o >>= 1) sum += __shfl_xor_sync(0xffffffffu, sum, o);
            float inv = 1.f / sum;
            carr[lane*4 + w]      = p0 * inv;
            carr[(lane+32)*4 + w] = p1 * inv;
            carr[(lane+64)*4 + w] = p2 * inv;
            if (lane < 9) carr[(lane+96)*4 + w] = p3 * inv;
        } else {
            for (int j = lane; j < Ee; j += 32) carr[j*4 + w] = 0.f;
        }
        __syncthreads();
        float acc0=0.f, acc1=0.f, acc2=0.f, acc3=0.f;
        #pragma unroll 7
        for (int j = 0; j < Ee; j++) {
            float4 c = *(const float4*)(carr + j*4);
            float hl = HLs[j*128 + tid];
            acc0 = fmaf(c.x, hl, acc0);
            acc1 = fmaf(c.y, hl, acc1);
            acc2 = fmaf(c.z, hl, acc2);
            acc3 = fmaf(c.w, hl, acc3);
        }
        int col = h*DHd + tid;
        #pragma unroll
        for (int ii = 0; ii < 4; ii++) {
            if (ii < ni) {
                float a = (ii==0)?acc0:(ii==1)?acc1:(ii==2)?acc2:acc3;
                int i = i0 + ii;
                out[(size_t)(n*Ee + i)*Dd + col] = fmaxf(a, 0.f) + g_X[(size_t)(n*Ee + i)*Dd + col];
            }
        }
        __syncthreads();
    }
}

#define K6_SMEM_BYTES ((Ee*128 + Ee*4 + 2*Tt*Ee) * 4)

// ---------------- launch ----------------
extern "C" void kernel_launch(void* const* d_in, const int* in_sizes, int n_in,
                              void* d_out, int out_size) {
    const float* q    = (const float*)d_in[0];
    const float* para = (const float*)d_in[1];
    const float* sent = (const float*)d_in[2];
    const float* ent  = (const float*)d_in[3];
    const float* pm   = (const float*)d_in[4];
    const float* sm_  = (const float*)d_in[5];
    const float* em   = (const float*)d_in[6];
    const int*   adj  = (const int*)  d_in[7];
    const float* W    = (const float*)d_in[8];
    const float* a    = (const float*)d_in[9];
    const float* qW1  = (const float*)d_in[10];
    const float* qW2  = (const float*)d_in[11];
    float* out = (float*)d_out;

    cudaFuncSetAttribute(k6_attn,   cudaFuncAttributeMaxDynamicSharedMemorySize, K6_SMEM_BYTES);
    cudaFuncSetAttribute(k_hl_mma,  cudaFuncAttributeMaxDynamicSharedMemorySize, HL_SMEM_BYTES);
    cudaFuncSetAttribute(k_u_mma,   cudaFuncAttributeMaxDynamicSharedMemorySize, HL_SMEM_BYTES);
    cudaFuncSetAttribute(k_qw1_mma, cudaFuncAttributeMaxDynamicSharedMemorySize, HL_SMEM_BYTES);
    cudaFuncSetAttribute(k_f_mma,   cudaFuncAttributeMaxDynamicSharedMemorySize, HL_SMEM_BYTES);

    k_concat<<<(Nn*Ee*Dd + 255)/256, 256>>>(q, para, sent, ent);
    k_mask  <<<(Nn*Ee + 255)/256, 256>>>(pm, sm_, em);
    k_split_q<<<(Nn*Dd + 255)/256, 256>>>(q);
    k_tsplit_qw1<<<dim3(32, 8, HT), dim3(32, 8)>>>(qW1);
    k_qw1_mma<<<dim3(2,2,HT), 256, HL_SMEM_BYTES>>>();
    k_gemm_qw2<<<dim3(4,4,HT), 256>>>(qW2, a);
    k_u_mma  <<<dim3(8,2,2*HT), 256, HL_SMEM_BYTES>>>(W);
    k_f_mma  <<<Nn, 256, HL_SMEM_BYTES>>>();
    k_repack_bf<<<(Dd*Dd + 255)/256, 256>>>(W);
    k_hl_mma <<<dim3(8,210), 256, HL_SMEM_BYTES>>>();
    k6_attn  <<<dim3(Hh,Nn), 128, K6_SMEM_BYTES>>>(adj, out);
}

// round 10
// speedup vs baseline: 2.7383x; 1.2446x over previous
#include <cuda_runtime.h>
#include <cuda_bf16.h>
#include <math.h>
#include <stdint.h>

#define Nn 256
#define Pp 4
#define Sr 40
#define Enn 60
#define Ee 105
#define Dd 1024
#define Hh 8
#define Tt 3
#define DHd 128
#define HT 24           // H*T
#define NEGV -1e30f

// ---------------- scratch (device globals; no allocations allowed) ----------------
static __device__ float g_X [Nn*Ee*Dd];           // concat input fp32 (110 MB)
static __device__ __nv_bfloat16 g_Xh[Nn*Ee*Dd];   // bf16 hi split of X
static __device__ __nv_bfloat16 g_Xl[Nn*Ee*Dd];   // bf16 lo split of X
static __device__ float g_mask[Nn*Ee];
static __device__ __nv_bfloat16 g_qh[Nn*Dd];      // q split
static __device__ __nv_bfloat16 g_ql[Nn*Dd];
static __device__ __nv_bfloat16 g_q1h[HT*256*Dd]; // qW1^T split: [ht][n=256][k=1024]
static __device__ __nv_bfloat16 g_q1l[HT*256*Dd];
static __device__ float g_R [HT*Nn*256];          // relu(q @ qW1)
static __device__ float g_V [2*HT*Nn*DHd];        // v1 (r=ht), v2 (r=24+ht)  fp32
static __device__ float g_U [2*HT*Nn*Dd];         // u = W @ v (fp32)
static __device__ float g_F [2*HT*Nn*Ee];         // f1, f2  [r][n][e]
static __device__ __nv_bfloat16 g_WBh[Dd*Dd];     // W[:,T-1]^T as [N=1024][K=1024] bf16 hi
static __device__ __nv_bfloat16 g_WBl[Dd*Dd];     // lo
static __device__ float g_HL[Nn*Ee*Dd];           // h_last (pre-mask) (110 MB)

// ---------------- K1: concat x (fp32 + bf16 hi/lo split) ----------------
__global__ void k_concat(const float* __restrict__ q, const float* __restrict__ para,
                         const float* __restrict__ sent, const float* __restrict__ ent) {
    int idx = blockIdx.x * blockDim.x + threadIdx.x;
    if (idx >= Nn*Ee*Dd) return;
    int d  = idx & (Dd-1);
    int ne = idx >> 10;
    int e  = ne % Ee;
    int n  = ne / Ee;
    float v;
    if (e == 0)              v = q   [n*Dd + d];
    else if (e < 1+Pp)       v = para[(n*Pp  + (e-1))*Dd + d];
    else if (e < 1+Pp+Sr)    v = sent[(n*Sr  + (e-1-Pp))*Dd + d];
    else                     v = ent [(n*Enn + (e-1-Pp-Sr))*Dd + d];
    g_X[idx] = v;
    __nv_bfloat16 hi = __float2bfloat16(v);
    g_Xh[idx] = hi;
    g_Xl[idx] = __float2bfloat16(v - __bfloat162float(hi));
}

__global__ void k_mask(const float* __restrict__ pm, const float* __restrict__ sm_,
                       const float* __restrict__ em) {
    int idx = blockIdx.x * blockDim.x + threadIdx.x;
    if (idx >= Nn*Ee) return;
    int e = idx % Ee, n = idx / Ee;
    float v;
    if (e == 0)            v = 1.f;
    else if (e < 1+Pp)     v = pm[n*Pp  + e-1];
    else if (e < 1+Pp+Sr)  v = sm_[n*Sr + e-1-Pp];
    else                   v = em[n*Enn + e-1-Pp-Sr];
    g_mask[idx] = v;
}

__global__ void k_split_q(const float* __restrict__ q) {
    int idx = blockIdx.x * blockDim.x + threadIdx.x;
    if (idx >= Nn*Dd) return;
    float v = q[idx];
    __nv_bfloat16 hi = __float2bfloat16(v);
    g_qh[idx] = hi;
    g_ql[idx] = __float2bfloat16(v - __bfloat162float(hi));
}

// transpose+split qW1: [ht][k=1024][n=256] -> [ht][n=256][k=1024]
__global__ void k_tsplit_qw1(const float* __restrict__ qW1) {
    __shared__ float t[32][33];
    int ht = blockIdx.z;
    int k0 = blockIdx.x*32, n0 = blockIdx.y*32;
    int tx = threadIdx.x, ty = threadIdx.y;     // 32x8
    const float* src = qW1 + (size_t)ht*Dd*256;
    #pragma unroll
    for (int j = 0; j < 4; j++)
        t[ty+8*j][tx] = src[(size_t)(k0+ty+8*j)*256 + n0 + tx];
    __syncthreads();
    #pragma unroll
    for (int j = 0; j < 4; j++) {
        int nrow = n0 + ty + 8*j;
        int kcol = k0 + tx;
        float v = t[tx][ty+8*j];
        __nv_bfloat16 hi = __float2bfloat16(v);
        size_t o = (size_t)ht*256*Dd + (size_t)nrow*Dd + kcol;
        g_q1h[o] = hi;
        g_q1l[o] = __float2bfloat16(v - __bfloat162float(hi));
    }
}

// ---------------- shared mma bits ----------------
#define HLP 72
#define HL_TILE_ELEMS (128*HLP)
#define HL_SMEM_BYTES (4*HL_TILE_ELEMS*2)
#define HL_DB_SMEM_BYTES (8*HL_TILE_ELEMS*2)

__device__ __forceinline__ void mma16816(float* c, const uint32_t* a, uint32_t b0, uint32_t b1) {
    asm volatile(
        "mma.sync.aligned.m16n8k16.row.col.f32.bf16.bf16.f32 "
        "{%0,%1,%2,%3}, {%4,%5,%6,%7}, {%8,%9}, {%0,%1,%2,%3};"
        : "+f"(c[0]), "+f"(c[1]), "+f"(c[2]), "+f"(c[3])
        : "r"(a[0]), "r"(a[1]), "r"(a[2]), "r"(a[3]), "r"(b0), "r"(b1));
}

__device__ __forceinline__ void split2(float x, float y, __nv_bfloat162* ph, __nv_bfloat162* pl) {
    __nv_bfloat162 h, l;
    h.x = __float2bfloat16(x);
    h.y = __float2bfloat16(y);
    l.x = __float2bfloat16(x - __bfloat162float(h.x));
    l.y = __float2bfloat16(y - __bfloat162float(h.y));
    *ph = h; *pl = l;
}

__device__ __forceinline__ void cp16(void* dst, const void* src) {
    uint32_t d = (uint32_t)__cvta_generic_to_shared(dst);
    asm volatile("cp.async.ca.shared.global [%0], [%1], 16;" :: "r"(d), "l"(src));
}
#define CP_COMMIT() asm volatile("cp.async.commit_group;")
#define CP_WAIT1()  asm volatile("cp.async.wait_group 1;")
#define CP_WAIT0()  asm volatile("cp.async.wait_group 0;")

// ---------------- K2a: R = relu(q @ qW1[ht]^T) via mma clone (round-9 proven) ----------------
__global__ __launch_bounds__(256) void k_qw1_mma() {
    extern __shared__ __nv_bfloat16 sm[];
    __nv_bfloat16* sAh = sm;
    __nv_bfloat16* sAl = sm + HL_TILE_ELEMS;
    __nv_bfloat16* sBh = sm + 2*HL_TILE_ELEMS;
    __nv_bfloat16* sBl = sm + 3*HL_TILE_ELEMS;
    int tid = threadIdx.x;
    int warp = tid >> 5, lane = tid & 31;
    int wm = warp & 3, wn = warp >> 2;
    int g = lane >> 2, tg = lane & 3;
    int n0 = blockIdx.x * 128;
    int m0 = blockIdx.y * 128;
    int ht = blockIdx.z;

    const __nv_bfloat16* Ahb = g_qh + (size_t)m0 * Dd;
    const __nv_bfloat16* Alb = g_ql + (size_t)m0 * Dd;
    const __nv_bfloat16* Bhb = g_q1h + (size_t)ht*256*Dd + (size_t)n0 * Dd;
    const __nv_bfloat16* Blb = g_q1l + (size_t)ht*256*Dd + (size_t)n0 * Dd;

    float acc[2][8][4];
    #pragma unroll
    for (int i=0;i<2;i++)
        #pragma unroll
        for (int j=0;j<8;j++)
            #pragma unroll
            for (int q=0;q<4;q++) acc[i][j][q] = 0.f;

    int sr = tid >> 3;
    int sc = (tid & 7) * 8;

    for (int kc = 0; kc < 16; kc++) {
        #pragma unroll
        for (int it = 0; it < 4; it++) {
            int r = sr + it*32;
            size_t go = (size_t)r * Dd + kc*64 + sc;
            int so = r * HLP + sc;
            *(uint4*)(sAh + so) = *(const uint4*)(Ahb + go);
            *(uint4*)(sAl + so) = *(const uint4*)(Alb + go);
            *(uint4*)(sBh + so) = *(const uint4*)(Bhb + go);
            *(uint4*)(sBl + so) = *(const uint4*)(Blb + go);
        }
        __syncthreads();
        #pragma unroll
        for (int ks = 0; ks < 4; ks++) {
            int kb = ks * 16;
            uint32_t ah[2][4], al[2][4];
            #pragma unroll
            for (int mi = 0; mi < 2; mi++) {
                int row = wm*32 + mi*16 + g;
                const __nv_bfloat16* p0 = sAh + row*HLP + kb + tg*2;
                const __nv_bfloat16* p1 = sAh + (row+8)*HLP + kb + tg*2;
                ah[mi][0] = *(const uint32_t*)(p0);
                ah[mi][1] = *(const uint32_t*)(p1);
                ah[mi][2] = *(const uint32_t*)(p0 + 8);
                ah[mi][3] = *(const uint32_t*)(p1 + 8);
                const __nv_bfloat16* q0 = sAl + row*HLP + kb + tg*2;
                const __nv_bfloat16* q1 = sAl + (row+8)*HLP + kb + tg*2;
                al[mi][0] = *(const uint32_t*)(q0);
                al[mi][1] = *(const uint32_t*)(q1);
                al[mi][2] = *(const uint32_t*)(q0 + 8);
                al[mi][3] = *(const uint32_t*)(q1 + 8);
            }
            #pragma unroll
            for (int nj = 0; nj < 8; nj++) {
                int col = wn*64 + nj*8 + g;
                const __nv_bfloat16* pb = sBh + col*HLP + kb + tg*2;
                const __nv_bfloat16* pl = sBl + col*HLP + kb + tg*2;
                uint32_t bh0 = *(const uint32_t*)(pb);
                uint32_t bh1 = *(const uint32_t*)(pb + 8);
                uint32_t bl0 = *(const uint32_t*)(pl);
                uint32_t bl1 = *(const uint32_t*)(pl + 8);
                #pragma unroll
                for (int mi = 0; mi < 2; mi++) {
                    mma16816(acc[mi][nj], ah[mi], bh0, bh1);
                    mma16816(acc[mi][nj], ah[mi], bl0, bl1);
                    mma16816(acc[mi][nj], al[mi], bh0, bh1);
                }
            }
        }
        __syncthreads();
    }

    float* Cb = g_R + (size_t)ht*Nn*256;
    #pragma unroll
    for (int mi = 0; mi < 2; mi++) {
        int row = m0 + wm*32 + mi*16 + g;
        #pragma unroll
        for (int nj = 0; nj < 8; nj++) {
            int col = n0 + wn*64 + nj*8 + tg*2;
            *(float2*)(&Cb[(size_t)row*256 + col]) =
                make_float2(fmaxf(acc[mi][nj][0], 0.f), fmaxf(acc[mi][nj][1], 0.f));
            *(float2*)(&Cb[(size_t)(row+8)*256 + col]) =
                make_float2(fmaxf(acc[mi][nj][2], 0.f), fmaxf(acc[mi][nj][3], 0.f));
        }
    }
}

// ---------------- K2b: S = sigmoid(R @ qW2[ht]); V = S * a (fp32, round-3 proven) --------
__global__ __launch_bounds__(256) void k_gemm_qw2(const float* __restrict__ qW2,
                                                  const float* __restrict__ a_in) {
    int ht = blockIdx.z;
    int m0 = blockIdx.x*64, n0 = blockIdx.y*64;
    __shared__ float As[16][64];
    __shared__ float Bs[16][64];
    int tid = threadIdx.x;
    int tr = tid/16, tc = tid%16;
    int lm = tid/4,  lk4 = (tid%4)*4;
    int lbk = tid/16, lbc4 = (tid%16)*4;
    const float* Ab = g_R + (size_t)ht*Nn*256;
    const float* Bb = qW2 + (size_t)ht*256*256;
    float acc[4][4] = {};
    for (int k0 = 0; k0 < 256; k0 += 16) {
        float4 av = *(const float4*)(Ab + (m0+lm)*256 + k0 + lk4);
        As[lk4+0][lm]=av.x; As[lk4+1][lm]=av.y; As[lk4+2][lm]=av.z; As[lk4+3][lm]=av.w;
        float4 bv = *(const float4*)(Bb + (size_t)(k0+lbk)*256 + n0 + lbc4);
        *(float4*)(&Bs[lbk][lbc4]) = bv;
        __syncthreads();
        #pragma unroll
        for (int kk = 0; kk < 16; kk++) {
            float4 a = *(const float4*)(&As[kk][tr*4]);
            float4 b = *(const float4*)(&Bs[kk][tc*4]);
            float aa[4]={a.x,a.y,a.z,a.w}, bb[4]={b.x,b.y,b.z,b.w};
            #pragma unroll
            for (int i=0;i<4;i++)
                #pragma unroll
                for (int j=0;j<4;j++) acc[i][j] = fmaf(aa[i], bb[j], acc[i][j]);
        }
        __syncthreads();
    }
    const float* av = a_in + ht*256;
    #pragma unroll
    for (int i=0;i<4;i++) {
        int row = m0 + tr*4 + i;
        #pragma unroll
        for (int j=0;j<4;j++) {
            int col = n0 + tc*4 + j;
            float s = 1.f / (1.f + __expf(-acc[i][j]));
            float val = s * av[col];
            if (col < DHd) g_V[(size_t)ht*Nn*DHd + row*DHd + col] = val;
            else           g_V[(size_t)HT*Nn*DHd + (size_t)ht*Nn*DHd + row*DHd + (col-DHd)] = val;
        }
    }
}

// ---------------- K3: U[r] = V[r] @ W[ht]^T via mma (round-8 proven clone) ----------------
__global__ __launch_bounds__(256) void k_u_mma(const float* __restrict__ W) {
    extern __shared__ __nv_bfloat16 sm[];
    __nv_bfloat16* sAh = sm;
    __nv_bfloat16* sAl = sm + HL_TILE_ELEMS;
    __nv_bfloat16* sBh = sm + 2*HL_TILE_ELEMS;
    __nv_bfloat16* sBl = sm + 3*HL_TILE_ELEMS;
    int tid = threadIdx.x;
    int warp = tid >> 5, lane = tid & 31;
    int wm = warp & 3, wn = warp >> 2;
    int g = lane >> 2, tg = lane & 3;
    int n0 = blockIdx.x * 128;
    int m0 = blockIdx.y * 128;
    int r  = blockIdx.z;
    int ht = r % HT;

    const float* Ab = g_V + (size_t)r*Nn*DHd + (size_t)m0*DHd;
    const float* Bb = W   + (size_t)ht*Dd*DHd + (size_t)n0*DHd;

    float acc[2][8][4];
    #pragma unroll
    for (int i=0;i<2;i++)
        #pragma unroll
        for (int j=0;j<8;j++)
            #pragma unroll
            for (int q=0;q<4;q++) acc[i][j][q] = 0.f;

    int sr = tid >> 3;
    int sc = (tid & 7) * 8;

    for (int kc = 0; kc < 2; kc++) {
        #pragma unroll
        for (int it = 0; it < 4; it++) {
            int rr = sr + it*32;
            const float* pa = Ab + (size_t)rr*DHd + kc*64 + sc;
            const float* pb = Bb + (size_t)rr*DHd + kc*64 + sc;
            int so = rr * HLP + sc;
            #pragma unroll
            for (int jj = 0; jj < 8; jj += 4) {
                float4 va = *(const float4*)(pa + jj);
                split2(va.x, va.y, (__nv_bfloat162*)(sAh + so + jj),     (__nv_bfloat162*)(sAl + so + jj));
                split2(va.z, va.w, (__nv_bfloat162*)(sAh + so + jj + 2), (__nv_bfloat162*)(sAl + so + jj + 2));
                float4 vb = *(const float4*)(pb + jj);
                split2(vb.x, vb.y, (__nv_bfloat162*)(sBh + so + jj),     (__nv_bfloat162*)(sBl + so + jj));
                split2(vb.z, vb.w, (__nv_bfloat162*)(sBh + so + jj + 2), (__nv_bfloat162*)(sBl + so + jj + 2));
            }
        }
        __syncthreads();
        #pragma unroll
        for (int ks = 0; ks < 4; ks++) {
            int kb = ks * 16;
            uint32_t ah[2][4], al[2][4];
            #pragma unroll
            for (int mi = 0; mi < 2; mi++) {
                int row = wm*32 + mi*16 + g;
                const __nv_bfloat16* p0 = sAh + row*HLP + kb + tg*2;
                const __nv_bfloat16* p1 = sAh + (row+8)*HLP + kb + tg*2;
                ah[mi][0] = *(const uint32_t*)(p0);
                ah[mi][1] = *(const uint32_t*)(p1);
                ah[mi][2] = *(const uint32_t*)(p0 + 8);
                ah[mi][3] = *(const uint32_t*)(p1 + 8);
                const __nv_bfloat16* q0 = sAl + row*HLP + kb + tg*2;
                const __nv_bfloat16* q1 = sAl + (row+8)*HLP + kb + tg*2;
                al[mi][0] = *(const uint32_t*)(q0);
                al[mi][1] = *(const uint32_t*)(q1);
                al[mi][2] = *(const uint32_t*)(q0 + 8);
                al[mi][3] = *(const uint32_t*)(q1 + 8);
            }
            #pragma unroll
            for (int nj = 0; nj < 8; nj++) {
                int col = wn*64 + nj*8 + g;
                const __nv_bfloat16* pb = sBh + col*HLP + kb + tg*2;
                const __nv_bfloat16* pl = sBl + col*HLP + kb + tg*2;
                uint32_t bh0 = *(const uint32_t*)(pb);
                uint32_t bh1 = *(const uint32_t*)(pb + 8);
                uint32_t bl0 = *(const uint32_t*)(pl);
                uint32_t bl1 = *(const uint32_t*)(pl + 8);
                #pragma unroll
                for (int mi = 0; mi < 2; mi++) {
                    mma16816(acc[mi][nj], ah[mi], bh0, bh1);
                    mma16816(acc[mi][nj], ah[mi], bl0, bl1);
                    mma16816(acc[mi][nj], al[mi], bh0, bh1);
                }
            }
        }
        __syncthreads();
    }

    #pragma unroll
    for (int mi = 0; mi < 2; mi++) {
        int row = m0 + wm*32 + mi*16 + g;
        #pragma unroll
        for (int nj = 0; nj < 8; nj++) {
            int col = n0 + wn*64 + nj*8 + tg*2;
            *(float2*)(&g_U[(size_t)r*Nn*Dd + (size_t)row*Dd + col])     = make_float2(acc[mi][nj][0], acc[mi][nj][1]);
            *(float2*)(&g_U[(size_t)r*Nn*Dd + (size_t)(row+8)*Dd + col]) = make_float2(acc[mi][nj][2], acc[mi][nj][3]);
        }
    }
}

// ---------------- K4: F via mma (round-9 proven) ----------------
__global__ __launch_bounds__(256) void k_f_mma() {
    extern __shared__ __nv_bfloat16 sm[];
    __nv_bfloat16* sAh = sm;
    __nv_bfloat16* sAl = sm + HL_TILE_ELEMS;
    __nv_bfloat16* sBh = sm + 2*HL_TILE_ELEMS;
    __nv_bfloat16* sBl = sm + 3*HL_TILE_ELEMS;
    int n = blockIdx.x;
    int tid = threadIdx.x;
    int warp = tid >> 5, lane = tid & 31;
    int wm = warp & 3, wn = warp >> 2;      // rows 32*wm (e), cols 24*wn (r)
    int g = lane >> 2, tg = lane & 3;

    float acc[2][3][4];
    #pragma unroll
    for (int i=0;i<2;i++)
        #pragma unroll
        for (int j=0;j<3;j++)
            #pragma unroll
            for (int q=0;q<4;q++) acc[i][j][q] = 0.f;

    int sr = tid >> 3;
    int sc = (tid & 7) * 8;
    const __nv_bfloat16* Ahb = g_Xh + (size_t)n * Ee * Dd;
    const __nv_bfloat16* Alb = g_Xl + (size_t)n * Ee * Dd;

    for (int kc = 0; kc < 16; kc++) {
        #pragma unroll
        for (int it = 0; it < 4; it++) {
            int r = sr + it*32;
            int rc = (r < Ee) ? r : (Ee-1);
            size_t go = (size_t)rc * Dd + kc*64 + sc;
            int so = r * HLP + sc;
            *(uint4*)(sAh + so) = *(const uint4*)(Ahb + go);
            *(uint4*)(sAl + so) = *(const uint4*)(Alb + go);
        }
        for (int i = tid; i < 384; i += 256) {
            int r = i >> 3, c = (i & 7) * 8;
            const float* pb = g_U + (size_t)r*(Nn*Dd) + (size_t)n*Dd + kc*64 + c;
            int so = r * HLP + c;
            #pragma unroll
            for (int jj = 0; jj < 8; jj += 4) {
                float4 vb = *(const float4*)(pb + jj);
                split2(vb.x, vb.y, (__nv_bfloat162*)(sBh + so + jj),     (__nv_bfloat162*)(sBl + so + jj));
                split2(vb.z, vb.w, (__nv_bfloat162*)(sBh + so + jj + 2), (__nv_bfloat162*)(sBl + so + jj + 2));
            }
        }
        __syncthreads();
        #pragma unroll
        for (int ks = 0; ks < 4; ks++) {
            int kb = ks * 16;
            uint32_t ah[2][4], al[2][4];
            #pragma unroll
            for (int mi = 0; mi < 2; mi++) {
                int row = wm*32 + mi*16 + g;
                const __nv_bfloat16* p0 = sAh + row*HLP + kb + tg*2;
                const __nv_bfloat16* p1 = sAh + (row+8)*HLP + kb + tg*2;
                ah[mi][0] = *(const uint32_t*)(p0);
                ah[mi][1] = *(const uint32_t*)(p1);
                ah[mi][2] = *(const uint32_t*)(p0 + 8);
                ah[mi][3] = *(const uint32_t*)(p1 + 8);
                const __nv_bfloat16* q0 = sAl + row*HLP + kb + tg*2;
                const __nv_bfloat16* q1 = sAl + (row+8)*HLP + kb + tg*2;
                al[mi][0] = *(const uint32_t*)(q0);
                al[mi][1] = *(const uint32_t*)(q1);
                al[mi][2] = *(const uint32_t*)(q0 + 8);
                al[mi][3] = *(const uint32_t*)(q1 + 8);
            }
            #pragma unroll
            for (int nj = 0; nj < 3; nj++) {
                int col = wn*24 + nj*8 + g;
                const __nv_bfloat16* pb = sBh + col*HLP + kb + tg*2;
                const __nv_bfloat16* pl = sBl + col*HLP + kb + tg*2;
                uint32_t bh0 = *(const uint32_t*)(pb);
                uint32_t bh1 = *(const uint32_t*)(pb + 8);
                uint32_t bl0 = *(const uint32_t*)(pl);
                uint32_t bl1 = *(const uint32_t*)(pl + 8);
                #pragma unroll
                for (int mi = 0; mi < 2; mi++) {
                    mma16816(acc[mi][nj], ah[mi], bh0, bh1);
                    mma16816(acc[mi][nj], ah[mi], bl0, bl1);
                    mma16816(acc[mi][nj], al[mi], bh0, bh1);
                }
            }
        }
        __syncthreads();
    }

    #pragma unroll
    for (int mi = 0; mi < 2; mi++) {
        int e0 = wm*32 + mi*16 + g;
        #pragma unroll
        for (int nj = 0; nj < 3; nj++) {
            int r = wn*24 + nj*8 + tg*2;
            if (e0 < Ee) {
                g_F[(size_t)r*Nn*Ee + n*Ee + e0]     = acc[mi][nj][0];
                g_F[(size_t)(r+1)*Nn*Ee + n*Ee + e0] = acc[mi][nj][1];
            }
            if (e0 + 8 < Ee) {
                g_F[(size_t)r*Nn*Ee + n*Ee + e0 + 8]     = acc[mi][nj][2];
                g_F[(size_t)(r+1)*Nn*Ee + n*Ee + e0 + 8] = acc[mi][nj][3];
            }
        }
    }
}

// ---------------- K5a: repack W[:, T-1]^T into [N=1024][K=1024] bf16 hi/lo ----
__global__ void k_repack_bf(const float* __restrict__ W) {
    int idx = blockIdx.x * blockDim.x + threadIdx.x;
    if (idx >= Dd*Dd) return;
    int d = idx & 1023, col = idx >> 10;         // out[col][d]
    int h = col >> 7, k = col & 127;
    float v = W[((size_t)(h*Tt + (Tt-1))*Dd + d)*DHd + k];
    __nv_bfloat16 hi = __float2bfloat16(v);
    g_WBh[idx] = hi;
    g_WBl[idx] = __float2bfloat16(v - __bfloat162float(hi));
}

// ---------------- K5b: HL = X @ WB^T via mma, cp.async DOUBLE-BUFFERED ----------------
__global__ __launch_bounds__(256) void k_hl_mma() {
    extern __shared__ __nv_bfloat16 sm[];
    const int TB = 4*HL_TILE_ELEMS;   // per-buffer span (elems)
    int tid = threadIdx.x;
    int warp = tid >> 5, lane = tid & 31;
    int wm = warp & 3, wn = warp >> 2;
    int g = lane >> 2, tg = lane & 3;
    int n0 = blockIdx.x * 128;
    int m0 = blockIdx.y * 128;

    const __nv_bfloat16* Ah0 = g_Xh  + (size_t)m0 * Dd;
    const __nv_bfloat16* Al0 = g_Xl  + (size_t)m0 * Dd;
    const __nv_bfloat16* Bh0 = g_WBh + (size_t)n0 * Dd;
    const __nv_bfloat16* Bl0 = g_WBl + (size_t)n0 * Dd;

    float acc[2][8][4];
    #pragma unroll
    for (int i=0;i<2;i++)
        #pragma unroll
        for (int j=0;j<8;j++)
            #pragma unroll
            for (int q=0;q<4;q++) acc[i][j][q] = 0.f;

    int sr = tid >> 3;
    int sc = (tid & 7) * 8;

    // async-load chunk kc into buffer b
    #define HL_ISSUE(kc, b) do {                                                   \
        __nv_bfloat16* base = sm + (b)*TB;                                         \
        _Pragma("unroll")                                                          \
        for (int it = 0; it < 4; it++) {                                           \
            int r = sr + it*32;                                                    \
            size_t go = (size_t)r * Dd + (kc)*64 + sc;                             \
            int so = r * HLP + sc;                                                 \
            cp16(base + so,                     Ah0 + go);                         \
            cp16(base + HL_TILE_ELEMS + so,     Al0 + go);                         \
            cp16(base + 2*HL_TILE_ELEMS + so,   Bh0 + go);                         \
            cp16(base + 3*HL_TILE_ELEMS + so,   Bl0 + go);                         \
        }                                                                          \
        CP_COMMIT();                                                               \
    } while (0)

    HL_ISSUE(0, 0);
    for (int kc = 0; kc < 16; kc++) {
        if (kc < 15) { HL_ISSUE(kc+1, (kc+1)&1); CP_WAIT1(); }
        else         { CP_WAIT0(); }
        __syncthreads();
        __nv_bfloat16* base = sm + (kc&1)*TB;
        __nv_bfloat16* sAh = base;
        __nv_bfloat16* sAl = base + HL_TILE_ELEMS;
        __nv_bfloat16* sBh = base + 2*HL_TILE_ELEMS;
        __nv_bfloat16* sBl = base + 3*HL_TILE_ELEMS;
        #pragma unroll
        for (int ks = 0; ks < 4; ks++) {
            int kb = ks * 16;
            uint32_t ah[2][4], al[2][4];
            #pragma unroll
            for (int mi = 0; mi < 2; mi++) {
                int row = wm*32 + mi*16 + g;
                const __nv_bfloat16* p0 = sAh + row*HLP + kb + tg*2;
                const __nv_bfloat16* p1 = sAh + (row+8)*HLP + kb + tg*2;
                ah[mi][0] = *(const uint32_t*)(p0);
                ah[mi][1] = *(const uint32_t*)(p1);
                ah[mi][2] = *(const uint32_t*)(p0 + 8);
                ah[mi][3] = *(const uint32_t*)(p1 + 8);
                const __nv_bfloat16* q0 = sAl + row*HLP + kb + tg*2;
                const __nv_bfloat16* q1 = sAl + (row+8)*HLP + kb + tg*2;
                al[mi][0] = *(const uint32_t*)(q0);
                al[mi][1] = *(const uint32_t*)(q1);
                al[mi][2] = *(const uint32_t*)(q0 + 8);
                al[mi][3] = *(const uint32_t*)(q1 + 8);
            }
            #pragma unroll
            for (int nj = 0; nj < 8; nj++) {
                int col = wn*64 + nj*8 + g;
                const __nv_bfloat16* pb = sBh + col*HLP + kb + tg*2;
                const __nv_bfloat16* pl = sBl + col*HLP + kb + tg*2;
                uint32_t bh0 = *(const uint32_t*)(pb);
                uint32_t bh1 = *(const uint32_t*)(pb + 8);
                uint32_t bl0 = *(const uint32_t*)(pl);
                uint32_t bl1 = *(const uint32_t*)(pl + 8);
                #pragma unroll
                for (int mi = 0; mi < 2; mi++) {
                    mma16816(acc[mi][nj], ah[mi], bh0, bh1);
                    mma16816(acc[mi][nj], ah[mi], bl0, bl1);
                    mma16816(acc[mi][nj], al[mi], bh0, bh1);
                }
            }
        }
        __syncthreads();   // buffer (kc&1) free for reuse at kc+2
    }
    #undef HL_ISSUE

    #pragma unroll
    for (int mi = 0; mi < 2; mi++) {
        int row = m0 + wm*32 + mi*16 + g;
        #pragma unroll
        for (int nj = 0; nj < 8; nj++) {
            int col = n0 + wn*64 + nj*8 + tg*2;
            *(float2*)(&g_HL[(size_t)row * Dd + col])     = make_float2(acc[mi][nj][0], acc[mi][nj][1]);
            *(float2*)(&g_HL[(size_t)(row+8) * Dd + col]) = make_float2(acc[mi][nj][2], acc[mi][nj][3]);
        }
    }
}

// ---------------- K6: edge-type score + softmax + aggregate + relu + residual ----------------
__device__ __forceinline__ float k6_score(int t, const float* f1s, const float* f2s, int i, int j) {
    if (t > 0) {
        float v = f1s[(t-1)*Ee + i] + f2s[(t-1)*Ee + j];
        return v > 0.f ? v : 0.2f*v;
    }
    return NEGV;
}

__global__ __launch_bounds__(128) void k6_attn(const int* __restrict__ adj, float* __restrict__ out) {
    int h = blockIdx.x, n = blockIdx.y;
    extern __shared__ float smx[];
    float* HLs  = smx;                   // 105*128
    float* carr = smx + Ee*128;          // 105*4
    float* f1s  = carr + Ee*4;           // 3*105
    float* f2s  = f1s + Tt*Ee;           // 3*105
    int tid = threadIdx.x;
    int lane = tid & 31, w = tid >> 5;

    for (int i = tid; i < Tt*Ee; i += 128) {
        int t = i / Ee, e = i % Ee;
        f1s[i] = g_F[(size_t)(h*Tt+t)*Nn*Ee + n*Ee + e];
        f2s[i] = g_F[(size_t)HT*Nn*Ee + (size_t)(h*Tt+t)*Nn*Ee + n*Ee + e];
    }
    for (int j = 0; j < Ee; j++)
        HLs[j*128 + tid] = g_HL[(size_t)(n*Ee+j)*Dd + h*DHd + tid] * g_mask[n*Ee + j];
    __syncthreads();

    const int* adjn = adj + n*Ee*Ee;
    for (int ig = 0; ig < 27; ig++) {
        int i0 = ig*4;
        int ni = Ee - i0; if (ni > 4) ni = 4;
        if (w < ni) {
            int i = i0 + w;
            const int* arow = adjn + i*Ee;
            float s0 = k6_score(arow[lane],    f1s, f2s, i, lane);
            float s1 = k6_score(arow[lane+32], f1s, f2s, i, lane+32);
            float s2 = k6_score(arow[lane+64], f1s, f2s, i, lane+64);
            float s3 = (lane < 9) ? k6_score(arow[lane+96], f1s, f2s, i, lane+96) : -INFINITY;
            float m = fmaxf(fmaxf(s0, s1), fmaxf(s2, s3));
            #pragma unroll
            for (int o = 16; o > 0; o >>= 1) m = fmaxf(m, __shfl_xor_sync(0xffffffffu, m, o));
            float p0 = __expf(s0 - m), p1 = __expf(s1 - m), p2 = __expf(s2 - m);
            float p3 = (lane < 9) ? __expf(s3 - m) : 0.f;
            float sum = p0 + p1 + p2 + p3;
            #pragma unroll
            for (int o = 16; o > 0; o >>= 1) sum += __shfl_xor_sync(0xffffffffu, sum, o);
            float inv = 1.f / sum;
            carr[lane*4 + w]      = p0 * inv;
            carr[(lane+32)*4 + w] = p1 * inv;
            carr[(lane+64)*4 + w] = p2 * inv;
            if (lane < 9) carr[(lane+96)*4 + w] = p3 * inv;
        } else {
            for (int j = lane; j < Ee; j += 32) carr[j*4 + w] = 0.f;
        }
        __syncthreads();
        float acc0=0.f, acc1=0.f, acc2=0.f, acc3=0.f;
        #pragma unroll 7
        for (int j = 0; j < Ee; j++) {
            float4 c = *(const float4*)(carr + j*4);
            float hl = HLs[j*128 + tid];
            acc0 = fmaf(c.x, hl, acc0);
            acc1 = fmaf(c.y, hl, acc1);
            acc2 = fmaf(c.z, hl, acc2);
            acc3 = fmaf(c.w, hl, acc3);
        }
        int col = h*DHd + tid;
        #pragma unroll
        for (int ii = 0; ii < 4; ii++) {
            if (ii < ni) {
                float a = (ii==0)?acc0:(ii==1)?acc1:(ii==2)?acc2:acc3;
                int i = i0 + ii;
                out[(size_t)(n*Ee + i)*Dd + col] = fmaxf(a, 0.f) + g_X[(size_t)(n*Ee + i)*Dd + col];
            }
        }
        __syncthreads();
    }
}

#define K6_SMEM_BYTES ((Ee*128 + Ee*4 + 2*Tt*Ee) * 4)

// ---------------- launch (fork-join dual-stream graph) ----------------
extern "C" void kernel_launch(void* const* d_in, const int* in_sizes, int n_in,
                              void* d_out, int out_size) {
    const float* q    = (const float*)d_in[0];
    const float* para = (const float*)d_in[1];
    const float* sent = (const float*)d_in[2];
    const float* ent  = (const float*)d_in[3];
    const float* pm   = (const float*)d_in[4];
    const float* sm_  = (const float*)d_in[5];
    const float* em   = (const float*)d_in[6];
    const int*   adj  = (const int*)  d_in[7];
    const float* W    = (const float*)d_in[8];
    const float* a    = (const float*)d_in[9];
    const float* qW1  = (const float*)d_in[10];
    const float* qW2  = (const float*)d_in[11];
    float* out = (float*)d_out;

    static cudaStream_t sB = nullptr;
    static cudaEvent_t evFork = nullptr, evA1 = nullptr, evB1 = nullptr, evB2 = nullptr;
    if (sB == nullptr) {
        cudaStreamCreateWithFlags(&sB, cudaStreamNonBlocking);
        cudaEventCreateWithFlags(&evFork, cudaEventDisableTiming);
        cudaEventCreateWithFlags(&evA1,   cudaEventDisableTiming);
        cudaEventCreateWithFlags(&evB1,   cudaEventDisableTiming);
        cudaEventCreateWithFlags(&evB2,   cudaEventDisableTiming);
        cudaFuncSetAttribute(k6_attn,   cudaFuncAttributeMaxDynamicSharedMemorySize, K6_SMEM_BYTES);
        cudaFuncSetAttribute(k_hl_mma,  cudaFuncAttributeMaxDynamicSharedMemorySize, HL_DB_SMEM_BYTES);
        cudaFuncSetAttribute(k_u_mma,   cudaFuncAttributeMaxDynamicSharedMemorySize, HL_SMEM_BYTES);
        cudaFuncSetAttribute(k_qw1_mma, cudaFuncAttributeMaxDynamicSharedMemorySize, HL_SMEM_BYTES);
        cudaFuncSetAttribute(k_f_mma,   cudaFuncAttributeMaxDynamicSharedMemorySize, HL_SMEM_BYTES);
    }

    // fork: stream B joins capture via event from legacy stream
    cudaEventRecord(evFork, 0);
    cudaStreamWaitEvent(sB, evFork, 0);

    // ---- stream A (legacy): X-side chain ----
    k_concat<<<(Nn*Ee*Dd + 255)/256, 256>>>(q, para, sent, ent);
    cudaEventRecord(evA1, 0);                       // X splits ready (for f_mma)
    k_mask<<<(Nn*Ee + 255)/256, 256>>>(pm, sm_, em);

    // ---- stream B: q-side chain ----
    k_repack_bf<<<(Dd*Dd + 255)/256, 256, 0, sB>>>(W);
    cudaEventRecord(evB1, sB);                      // WB ready (for hl)
    k_split_q<<<(Nn*Dd + 255)/256, 256, 0, sB>>>(q);
    k_tsplit_qw1<<<dim3(32, 8, HT), dim3(32, 8), 0, sB>>>(qW1);
    k_qw1_mma<<<dim3(2,2,HT), 256, HL_SMEM_BYTES, sB>>>();
    k_gemm_qw2<<<dim3(4,4,HT), 256, 0, sB>>>(qW2, a);
    k_u_mma<<<dim3(8,2,2*HT), 256, HL_SMEM_BYTES, sB>>>(W);
    cudaStreamWaitEvent(sB, evA1, 0);               // f needs X splits
    k_f_mma<<<Nn, 256, HL_SMEM_BYTES, sB>>>();
    cudaEventRecord(evB2, sB);

    // ---- stream A: hl (needs concat + repack) then join + k6 ----
    cudaStreamWaitEvent(0, evB1, 0);
    k_hl_mma<<<dim3(8,210), 256, HL_DB_SMEM_BYTES>>>();
    cudaStreamWaitEvent(0, evB2, 0);
    k6_attn<<<dim3(Hh,Nn), 128, K6_SMEM_BYTES>>>(adj, out);
}

// round 11
// speedup vs baseline: 2.9829x; 1.0893x over previous
#include <cuda_runtime.h>
#include <cuda_bf16.h>
#include <math.h>
#include <stdint.h>

#define Nn 256
#define Pp 4
#define Sr 40
#define Enn 60
#define Ee 105
#define Dd 1024
#define Hh 8
#define Tt 3
#define DHd 128
#define HT 24           // H*T
#define NEGV -1e30f

// ---------------- scratch (device globals; no allocations allowed) ----------------
static __device__ float g_X [Nn*Ee*Dd];           // concat input fp32 (110 MB)
static __device__ __nv_bfloat16 g_Xh[Nn*Ee*Dd];   // bf16 hi split of X
static __device__ __nv_bfloat16 g_Xl[Nn*Ee*Dd];   // bf16 lo split of X
static __device__ float g_mask[Nn*Ee];
static __device__ __nv_bfloat16 g_qh[Nn*Dd];      // q split
static __device__ __nv_bfloat16 g_ql[Nn*Dd];
static __device__ __nv_bfloat16 g_q1h[HT*256*Dd]; // qW1^T split: [ht][n=256][k=1024]
static __device__ __nv_bfloat16 g_q1l[HT*256*Dd];
static __device__ float g_R [HT*Nn*256];          // relu(q @ qW1)
static __device__ float g_V [2*HT*Nn*DHd];        // v1 (r=ht), v2 (r=24+ht)  fp32
static __device__ float g_U [2*HT*Nn*Dd];         // u = W @ v (fp32)
static __device__ float g_F [2*HT*Nn*Ee];         // f1, f2  [r][n][e]
static __device__ __nv_bfloat16 g_WBh[Dd*Dd];     // W[:,T-1]^T as [N=1024][K=1024] bf16 hi
static __device__ __nv_bfloat16 g_WBl[Dd*Dd];     // lo
static __device__ float g_HL[Nn*Ee*Dd];           // h_last (pre-mask) (110 MB)

// ---------------- K1: concat x (fp32 + bf16 hi/lo split) ----------------
__global__ void k_concat(const float* __restrict__ q, const float* __restrict__ para,
                         const float* __restrict__ sent, const float* __restrict__ ent) {
    int idx = blockIdx.x * blockDim.x + threadIdx.x;
    if (idx >= Nn*Ee*Dd) return;
    int d  = idx & (Dd-1);
    int ne = idx >> 10;
    int e  = ne % Ee;
    int n  = ne / Ee;
    float v;
    if (e == 0)              v = q   [n*Dd + d];
    else if (e < 1+Pp)       v = para[(n*Pp  + (e-1))*Dd + d];
    else if (e < 1+Pp+Sr)    v = sent[(n*Sr  + (e-1-Pp))*Dd + d];
    else                     v = ent [(n*Enn + (e-1-Pp-Sr))*Dd + d];
    g_X[idx] = v;
    __nv_bfloat16 hi = __float2bfloat16(v);
    g_Xh[idx] = hi;
    g_Xl[idx] = __float2bfloat16(v - __bfloat162float(hi));
}

__global__ void k_mask(const float* __restrict__ pm, const float* __restrict__ sm_,
                       const float* __restrict__ em) {
    int idx = blockIdx.x * blockDim.x + threadIdx.x;
    if (idx >= Nn*Ee) return;
    int e = idx % Ee, n = idx / Ee;
    float v;
    if (e == 0)            v = 1.f;
    else if (e < 1+Pp)     v = pm[n*Pp  + e-1];
    else if (e < 1+Pp+Sr)  v = sm_[n*Sr + e-1-Pp];
    else                   v = em[n*Enn + e-1-Pp-Sr];
    g_mask[idx] = v;
}

__global__ void k_split_q(const float* __restrict__ q) {
    int idx = blockIdx.x * blockDim.x + threadIdx.x;
    if (idx >= Nn*Dd) return;
    float v = q[idx];
    __nv_bfloat16 hi = __float2bfloat16(v);
    g_qh[idx] = hi;
    g_ql[idx] = __float2bfloat16(v - __bfloat162float(hi));
}

// transpose+split qW1: [ht][k=1024][n=256] -> [ht][n=256][k=1024]
__global__ void k_tsplit_qw1(const float* __restrict__ qW1) {
    __shared__ float t[32][33];
    int ht = blockIdx.z;
    int k0 = blockIdx.x*32, n0 = blockIdx.y*32;
    int tx = threadIdx.x, ty = threadIdx.y;     // 32x8
    const float* src = qW1 + (size_t)ht*Dd*256;
    #pragma unroll
    for (int j = 0; j < 4; j++)
        t[ty+8*j][tx] = src[(size_t)(k0+ty+8*j)*256 + n0 + tx];
    __syncthreads();
    #pragma unroll
    for (int j = 0; j < 4; j++) {
        int nrow = n0 + ty + 8*j;
        int kcol = k0 + tx;
        float v = t[tx][ty+8*j];
        __nv_bfloat16 hi = __float2bfloat16(v);
        size_t o = (size_t)ht*256*Dd + (size_t)nrow*Dd + kcol;
        g_q1h[o] = hi;
        g_q1l[o] = __float2bfloat16(v - __bfloat162float(hi));
    }
}

// ---------------- shared mma bits ----------------
#define HLP 72
#define HL_TILE_ELEMS (128*HLP)
#define HL_SMEM_BYTES (4*HL_TILE_ELEMS*2)
#define HL_DB_SMEM_BYTES (8*HL_TILE_ELEMS*2)

__device__ __forceinline__ void mma16816(float* c, const uint32_t* a, uint32_t b0, uint32_t b1) {
    asm volatile(
        "mma.sync.aligned.m16n8k16.row.col.f32.bf16.bf16.f32 "
        "{%0,%1,%2,%3}, {%4,%5,%6,%7}, {%8,%9}, {%0,%1,%2,%3};"
        : "+f"(c[0]), "+f"(c[1]), "+f"(c[2]), "+f"(c[3])
        : "r"(a[0]), "r"(a[1]), "r"(a[2]), "r"(a[3]), "r"(b0), "r"(b1));
}

__device__ __forceinline__ void split2(float x, float y, __nv_bfloat162* ph, __nv_bfloat162* pl) {
    __nv_bfloat162 h, l;
    h.x = __float2bfloat16(x);
    h.y = __float2bfloat16(y);
    l.x = __float2bfloat16(x - __bfloat162float(h.x));
    l.y = __float2bfloat16(y - __bfloat162float(h.y));
    *ph = h; *pl = l;
}

__device__ __forceinline__ void cp16(void* dst, const void* src) {
    uint32_t d = (uint32_t)__cvta_generic_to_shared(dst);
    asm volatile("cp.async.ca.shared.global [%0], [%1], 16;" :: "r"(d), "l"(src));
}
#define CP_COMMIT() asm volatile("cp.async.commit_group;")
#define CP_WAIT1()  asm volatile("cp.async.wait_group 1;")
#define CP_WAIT0()  asm volatile("cp.async.wait_group 0;")

// ---------------- K2a: R = relu(q @ qW1[ht]^T) via mma clone (round-9 proven) ----------------
__global__ __launch_bounds__(256) void k_qw1_mma() {
    extern __shared__ __nv_bfloat16 sm[];
    __nv_bfloat16* sAh = sm;
    __nv_bfloat16* sAl = sm + HL_TILE_ELEMS;
    __nv_bfloat16* sBh = sm + 2*HL_TILE_ELEMS;
    __nv_bfloat16* sBl = sm + 3*HL_TILE_ELEMS;
    int tid = threadIdx.x;
    int warp = tid >> 5, lane = tid & 31;
    int wm = warp & 3, wn = warp >> 2;
    int g = lane >> 2, tg = lane & 3;
    int n0 = blockIdx.x * 128;
    int m0 = blockIdx.y * 128;
    int ht = blockIdx.z;

    const __nv_bfloat16* Ahb = g_qh + (size_t)m0 * Dd;
    const __nv_bfloat16* Alb = g_ql + (size_t)m0 * Dd;
    const __nv_bfloat16* Bhb = g_q1h + (size_t)ht*256*Dd + (size_t)n0 * Dd;
    const __nv_bfloat16* Blb = g_q1l + (size_t)ht*256*Dd + (size_t)n0 * Dd;

    float acc[2][8][4];
    #pragma unroll
    for (int i=0;i<2;i++)
        #pragma unroll
        for (int j=0;j<8;j++)
            #pragma unroll
            for (int q=0;q<4;q++) acc[i][j][q] = 0.f;

    int sr = tid >> 3;
    int sc = (tid & 7) * 8;

    for (int kc = 0; kc < 16; kc++) {
        #pragma unroll
        for (int it = 0; it < 4; it++) {
            int r = sr + it*32;
            size_t go = (size_t)r * Dd + kc*64 + sc;
            int so = r * HLP + sc;
            *(uint4*)(sAh + so) = *(const uint4*)(Ahb + go);
            *(uint4*)(sAl + so) = *(const uint4*)(Alb + go);
            *(uint4*)(sBh + so) = *(const uint4*)(Bhb + go);
            *(uint4*)(sBl + so) = *(const uint4*)(Blb + go);
        }
        __syncthreads();
        #pragma unroll
        for (int ks = 0; ks < 4; ks++) {
            int kb = ks * 16;
            uint32_t ah[2][4], al[2][4];
            #pragma unroll
            for (int mi = 0; mi < 2; mi++) {
                int row = wm*32 + mi*16 + g;
                const __nv_bfloat16* p0 = sAh + row*HLP + kb + tg*2;
                const __nv_bfloat16* p1 = sAh + (row+8)*HLP + kb + tg*2;
                ah[mi][0] = *(const uint32_t*)(p0);
                ah[mi][1] = *(const uint32_t*)(p1);
                ah[mi][2] = *(const uint32_t*)(p0 + 8);
                ah[mi][3] = *(const uint32_t*)(p1 + 8);
                const __nv_bfloat16* q0 = sAl + row*HLP + kb + tg*2;
                const __nv_bfloat16* q1 = sAl + (row+8)*HLP + kb + tg*2;
                al[mi][0] = *(const uint32_t*)(q0);
                al[mi][1] = *(const uint32_t*)(q1);
                al[mi][2] = *(const uint32_t*)(q0 + 8);
                al[mi][3] = *(const uint32_t*)(q1 + 8);
            }
            #pragma unroll
            for (int nj = 0; nj < 8; nj++) {
                int col = wn*64 + nj*8 + g;
                const __nv_bfloat16* pb = sBh + col*HLP + kb + tg*2;
                const __nv_bfloat16* pl = sBl + col*HLP + kb + tg*2;
                uint32_t bh0 = *(const uint32_t*)(pb);
                uint32_t bh1 = *(const uint32_t*)(pb + 8);
                uint32_t bl0 = *(const uint32_t*)(pl);
                uint32_t bl1 = *(const uint32_t*)(pl + 8);
                #pragma unroll
                for (int mi = 0; mi < 2; mi++) {
                    mma16816(acc[mi][nj], ah[mi], bh0, bh1);
                    mma16816(acc[mi][nj], ah[mi], bl0, bl1);
                    mma16816(acc[mi][nj], al[mi], bh0, bh1);
                }
            }
        }
        __syncthreads();
    }

    float* Cb = g_R + (size_t)ht*Nn*256;
    #pragma unroll
    for (int mi = 0; mi < 2; mi++) {
        int row = m0 + wm*32 + mi*16 + g;
        #pragma unroll
        for (int nj = 0; nj < 8; nj++) {
            int col = n0 + wn*64 + nj*8 + tg*2;
            *(float2*)(&Cb[(size_t)row*256 + col]) =
                make_float2(fmaxf(acc[mi][nj][0], 0.f), fmaxf(acc[mi][nj][1], 0.f));
            *(float2*)(&Cb[(size_t)(row+8)*256 + col]) =
                make_float2(fmaxf(acc[mi][nj][2], 0.f), fmaxf(acc[mi][nj][3], 0.f));
        }
    }
}

// ---------------- K2b: S = sigmoid(R @ qW2[ht]); V = S * a (fp32, round-3 proven) --------
__global__ __launch_bounds__(256) void k_gemm_qw2(const float* __restrict__ qW2,
                                                  const float* __restrict__ a_in) {
    int ht = blockIdx.z;
    int m0 = blockIdx.x*64, n0 = blockIdx.y*64;
    __shared__ float As[16][64];
    __shared__ float Bs[16][64];
    int tid = threadIdx.x;
    int tr = tid/16, tc = tid%16;
    int lm = tid/4,  lk4 = (tid%4)*4;
    int lbk = tid/16, lbc4 = (tid%16)*4;
    const float* Ab = g_R + (size_t)ht*Nn*256;
    const float* Bb = qW2 + (size_t)ht*256*256;
    float acc[4][4] = {};
    for (int k0 = 0; k0 < 256; k0 += 16) {
        float4 av = *(const float4*)(Ab + (m0+lm)*256 + k0 + lk4);
        As[lk4+0][lm]=av.x; As[lk4+1][lm]=av.y; As[lk4+2][lm]=av.z; As[lk4+3][lm]=av.w;
        float4 bv = *(const float4*)(Bb + (size_t)(k0+lbk)*256 + n0 + lbc4);
        *(float4*)(&Bs[lbk][lbc4]) = bv;
        __syncthreads();
        #pragma unroll
        for (int kk = 0; kk < 16; kk++) {
            float4 a = *(const float4*)(&As[kk][tr*4]);
            float4 b = *(const float4*)(&Bs[kk][tc*4]);
            float aa[4]={a.x,a.y,a.z,a.w}, bb[4]={b.x,b.y,b.z,b.w};
            #pragma unroll
            for (int i=0;i<4;i++)
                #pragma unroll
                for (int j=0;j<4;j++) acc[i][j] = fmaf(aa[i], bb[j], acc[i][j]);
        }
        __syncthreads();
    }
    const float* av = a_in + ht*256;
    #pragma unroll
    for (int i=0;i<4;i++) {
        int row = m0 + tr*4 + i;
        #pragma unroll
        for (int j=0;j<4;j++) {
            int col = n0 + tc*4 + j;
            float s = 1.f / (1.f + __expf(-acc[i][j]));
            float val = s * av[col];
            if (col < DHd) g_V[(size_t)ht*Nn*DHd + row*DHd + col] = val;
            else           g_V[(size_t)HT*Nn*DHd + (size_t)ht*Nn*DHd + row*DHd + (col-DHd)] = val;
        }
    }
}

// ---------------- K3: U[r] = V[r] @ W[ht]^T via mma (round-8 proven clone) ----------------
__global__ __launch_bounds__(256) void k_u_mma(const float* __restrict__ W) {
    extern __shared__ __nv_bfloat16 sm[];
    __nv_bfloat16* sAh = sm;
    __nv_bfloat16* sAl = sm + HL_TILE_ELEMS;
    __nv_bfloat16* sBh = sm + 2*HL_TILE_ELEMS;
    __nv_bfloat16* sBl = sm + 3*HL_TILE_ELEMS;
    int tid = threadIdx.x;
    int warp = tid >> 5, lane = tid & 31;
    int wm = warp & 3, wn = warp >> 2;
    int g = lane >> 2, tg = lane & 3;
    int n0 = blockIdx.x * 128;
    int m0 = blockIdx.y * 128;
    int r  = blockIdx.z;
    int ht = r % HT;

    const float* Ab = g_V + (size_t)r*Nn*DHd + (size_t)m0*DHd;
    const float* Bb = W   + (size_t)ht*Dd*DHd + (size_t)n0*DHd;

    float acc[2][8][4];
    #pragma unroll
    for (int i=0;i<2;i++)
        #pragma unroll
        for (int j=0;j<8;j++)
            #pragma unroll
            for (int q=0;q<4;q++) acc[i][j][q] = 0.f;

    int sr = tid >> 3;
    int sc = (tid & 7) * 8;

    for (int kc = 0; kc < 2; kc++) {
        #pragma unroll
        for (int it = 0; it < 4; it++) {
            int rr = sr + it*32;
            const float* pa = Ab + (size_t)rr*DHd + kc*64 + sc;
            const float* pb = Bb + (size_t)rr*DHd + kc*64 + sc;
            int so = rr * HLP + sc;
            #pragma unroll
            for (int jj = 0; jj < 8; jj += 4) {
                float4 va = *(const float4*)(pa + jj);
                split2(va.x, va.y, (__nv_bfloat162*)(sAh + so + jj),     (__nv_bfloat162*)(sAl + so + jj));
                split2(va.z, va.w, (__nv_bfloat162*)(sAh + so + jj + 2), (__nv_bfloat162*)(sAl + so + jj + 2));
                float4 vb = *(const float4*)(pb + jj);
                split2(vb.x, vb.y, (__nv_bfloat162*)(sBh + so + jj),     (__nv_bfloat162*)(sBl + so + jj));
                split2(vb.z, vb.w, (__nv_bfloat162*)(sBh + so + jj + 2), (__nv_bfloat162*)(sBl + so + jj + 2));
            }
        }
        __syncthreads();
        #pragma unroll
        for (int ks = 0; ks < 4; ks++) {
            int kb = ks * 16;
            uint32_t ah[2][4], al[2][4];
            #pragma unroll
            for (int mi = 0; mi < 2; mi++) {
                int row = wm*32 + mi*16 + g;
                const __nv_bfloat16* p0 = sAh + row*HLP + kb + tg*2;
                const __nv_bfloat16* p1 = sAh + (row+8)*HLP + kb + tg*2;
                ah[mi][0] = *(const uint32_t*)(p0);
                ah[mi][1] = *(const uint32_t*)(p1);
                ah[mi][2] = *(const uint32_t*)(p0 + 8);
                ah[mi][3] = *(const uint32_t*)(p1 + 8);
                const __nv_bfloat16* q0 = sAl + row*HLP + kb + tg*2;
                const __nv_bfloat16* q1 = sAl + (row+8)*HLP + kb + tg*2;
                al[mi][0] = *(const uint32_t*)(q0);
                al[mi][1] = *(const uint32_t*)(q1);
                al[mi][2] = *(const uint32_t*)(q0 + 8);
                al[mi][3] = *(const uint32_t*)(q1 + 8);
            }
            #pragma unroll
            for (int nj = 0; nj < 8; nj++) {
                int col = wn*64 + nj*8 + g;
                const __nv_bfloat16* pb = sBh + col*HLP + kb + tg*2;
                const __nv_bfloat16* pl = sBl + col*HLP + kb + tg*2;
                uint32_t bh0 = *(const uint32_t*)(pb);
                uint32_t bh1 = *(const uint32_t*)(pb + 8);
                uint32_t bl0 = *(const uint32_t*)(pl);
                uint32_t bl1 = *(const uint32_t*)(pl + 8);
                #pragma unroll
                for (int mi = 0; mi < 2; mi++) {
                    mma16816(acc[mi][nj], ah[mi], bh0, bh1);
                    mma16816(acc[mi][nj], ah[mi], bl0, bl1);
                    mma16816(acc[mi][nj], al[mi], bh0, bh1);
                }
            }
        }
        __syncthreads();
    }

    #pragma unroll
    for (int mi = 0; mi < 2; mi++) {
        int row = m0 + wm*32 + mi*16 + g;
        #pragma unroll
        for (int nj = 0; nj < 8; nj++) {
            int col = n0 + wn*64 + nj*8 + tg*2;
            *(float2*)(&g_U[(size_t)r*Nn*Dd + (size_t)row*Dd + col])     = make_float2(acc[mi][nj][0], acc[mi][nj][1]);
            *(float2*)(&g_U[(size_t)r*Nn*Dd + (size_t)(row+8)*Dd + col]) = make_float2(acc[mi][nj][2], acc[mi][nj][3]);
        }
    }
}

// ---------------- K4: F via mma (round-9 proven) ----------------
__global__ __launch_bounds__(256) void k_f_mma() {
    extern __shared__ __nv_bfloat16 sm[];
    __nv_bfloat16* sAh = sm;
    __nv_bfloat16* sAl = sm + HL_TILE_ELEMS;
    __nv_bfloat16* sBh = sm + 2*HL_TILE_ELEMS;
    __nv_bfloat16* sBl = sm + 3*HL_TILE_ELEMS;
    int n = blockIdx.x;
    int tid = threadIdx.x;
    int warp = tid >> 5, lane = tid & 31;
    int wm = warp & 3, wn = warp >> 2;      // rows 32*wm (e), cols 24*wn (r)
    int g = lane >> 2, tg = lane & 3;

    float acc[2][3][4];
    #pragma unroll
    for (int i=0;i<2;i++)
        #pragma unroll
        for (int j=0;j<3;j++)
            #pragma unroll
            for (int q=0;q<4;q++) acc[i][j][q] = 0.f;

    int sr = tid >> 3;
    int sc = (tid & 7) * 8;
    const __nv_bfloat16* Ahb = g_Xh + (size_t)n * Ee * Dd;
    const __nv_bfloat16* Alb = g_Xl + (size_t)n * Ee * Dd;

    for (int kc = 0; kc < 16; kc++) {
        #pragma unroll
        for (int it = 0; it < 4; it++) {
            int r = sr + it*32;
            int rc = (r < Ee) ? r : (Ee-1);
            size_t go = (size_t)rc * Dd + kc*64 + sc;
            int so = r * HLP + sc;
            *(uint4*)(sAh + so) = *(const uint4*)(Ahb + go);
            *(uint4*)(sAl + so) = *(const uint4*)(Alb + go);
        }
        for (int i = tid; i < 384; i += 256) {
            int r = i >> 3, c = (i & 7) * 8;
            const float* pb = g_U + (size_t)r*(Nn*Dd) + (size_t)n*Dd + kc*64 + c;
            int so = r * HLP + c;
            #pragma unroll
            for (int jj = 0; jj < 8; jj += 4) {
                float4 vb = *(const float4*)(pb + jj);
                split2(vb.x, vb.y, (__nv_bfloat162*)(sBh + so + jj),     (__nv_bfloat162*)(sBl + so + jj));
                split2(vb.z, vb.w, (__nv_bfloat162*)(sBh + so + jj + 2), (__nv_bfloat162*)(sBl + so + jj + 2));
            }
        }
        __syncthreads();
        #pragma unroll
        for (int ks = 0; ks < 4; ks++) {
            int kb = ks * 16;
            uint32_t ah[2][4], al[2][4];
            #pragma unroll
            for (int mi = 0; mi < 2; mi++) {
                int row = wm*32 + mi*16 + g;
                const __nv_bfloat16* p0 = sAh + row*HLP + kb + tg*2;
                const __nv_bfloat16* p1 = sAh + (row+8)*HLP + kb + tg*2;
                ah[mi][0] = *(const uint32_t*)(p0);
                ah[mi][1] = *(const uint32_t*)(p1);
                ah[mi][2] = *(const uint32_t*)(p0 + 8);
                ah[mi][3] = *(const uint32_t*)(p1 + 8);
                const __nv_bfloat16* q0 = sAl + row*HLP + kb + tg*2;
                const __nv_bfloat16* q1 = sAl + (row+8)*HLP + kb + tg*2;
                al[mi][0] = *(const uint32_t*)(q0);
                al[mi][1] = *(const uint32_t*)(q1);
                al[mi][2] = *(const uint32_t*)(q0 + 8);
                al[mi][3] = *(const uint32_t*)(q1 + 8);
            }
            #pragma unroll
            for (int nj = 0; nj < 3; nj++) {
                int col = wn*24 + nj*8 + g;
                const __nv_bfloat16* pb = sBh + col*HLP + kb + tg*2;
                const __nv_bfloat16* pl = sBl + col*HLP + kb + tg*2;
                uint32_t bh0 = *(const uint32_t*)(pb);
                uint32_t bh1 = *(const uint32_t*)(pb + 8);
                uint32_t bl0 = *(const uint32_t*)(pl);
                uint32_t bl1 = *(const uint32_t*)(pl + 8);
                #pragma unroll
                for (int mi = 0; mi < 2; mi++) {
                    mma16816(acc[mi][nj], ah[mi], bh0, bh1);
                    mma16816(acc[mi][nj], ah[mi], bl0, bl1);
                    mma16816(acc[mi][nj], al[mi], bh0, bh1);
                }
            }
        }
        __syncthreads();
    }

    #pragma unroll
    for (int mi = 0; mi < 2; mi++) {
        int e0 = wm*32 + mi*16 + g;
        #pragma unroll
        for (int nj = 0; nj < 3; nj++) {
            int r = wn*24 + nj*8 + tg*2;
            if (e0 < Ee) {
                g_F[(size_t)r*Nn*Ee + n*Ee + e0]     = acc[mi][nj][0];
                g_F[(size_t)(r+1)*Nn*Ee + n*Ee + e0] = acc[mi][nj][1];
            }
            if (e0 + 8 < Ee) {
                g_F[(size_t)r*Nn*Ee + n*Ee + e0 + 8]     = acc[mi][nj][2];
                g_F[(size_t)(r+1)*Nn*Ee + n*Ee + e0 + 8] = acc[mi][nj][3];
            }
        }
    }
}

// ---------------- K5a: repack W[:, T-1]^T into [N=1024][K=1024] bf16 hi/lo ----
__global__ void k_repack_bf(const float* __restrict__ W) {
    int idx = blockIdx.x * blockDim.x + threadIdx.x;
    if (idx >= Dd*Dd) return;
    int d = idx & 1023, col = idx >> 10;         // out[col][d]
    int h = col >> 7, k = col & 127;
    float v = W[((size_t)(h*Tt + (Tt-1))*Dd + d)*DHd + k];
    __nv_bfloat16 hi = __float2bfloat16(v);
    g_WBh[idx] = hi;
    g_WBl[idx] = __float2bfloat16(v - __bfloat162float(hi));
}

// ---------------- K5b: HL = X @ WB^T via mma, cp.async DOUBLE-BUFFERED (round-10 proven) --
__global__ __launch_bounds__(256) void k_hl_mma() {
    extern __shared__ __nv_bfloat16 sm[];
    const int TB = 4*HL_TILE_ELEMS;
    int tid = threadIdx.x;
    int warp = tid >> 5, lane = tid & 31;
    int wm = warp & 3, wn = warp >> 2;
    int g = lane >> 2, tg = lane & 3;
    int n0 = blockIdx.x * 128;
    int m0 = blockIdx.y * 128;

    const __nv_bfloat16* Ah0 = g_Xh  + (size_t)m0 * Dd;
    const __nv_bfloat16* Al0 = g_Xl  + (size_t)m0 * Dd;
    const __nv_bfloat16* Bh0 = g_WBh + (size_t)n0 * Dd;
    const __nv_bfloat16* Bl0 = g_WBl + (size_t)n0 * Dd;

    float acc[2][8][4];
    #pragma unroll
    for (int i=0;i<2;i++)
        #pragma unroll
        for (int j=0;j<8;j++)
            #pragma unroll
            for (int q=0;q<4;q++) acc[i][j][q] = 0.f;

    int sr = tid >> 3;
    int sc = (tid & 7) * 8;

    #define HL_ISSUE(kc, b) do {                                                   \
        __nv_bfloat16* base = sm + (b)*TB;                                         \
        _Pragma("unroll")                                                          \
        for (int it = 0; it < 4; it++) {                                           \
            int r = sr + it*32;                                                    \
            size_t go = (size_t)r * Dd + (kc)*64 + sc;                             \
            int so = r * HLP + sc;                                                 \
            cp16(base + so,                     Ah0 + go);                         \
            cp16(base + HL_TILE_ELEMS + so,     Al0 + go);                         \
            cp16(base + 2*HL_TILE_ELEMS + so,   Bh0 + go);                         \
            cp16(base + 3*HL_TILE_ELEMS + so,   Bl0 + go);                         \
        }                                                                          \
        CP_COMMIT();                                                               \
    } while (0)

    HL_ISSUE(0, 0);
    for (int kc = 0; kc < 16; kc++) {
        if (kc < 15) { HL_ISSUE(kc+1, (kc+1)&1); CP_WAIT1(); }
        else         { CP_WAIT0(); }
        __syncthreads();
        __nv_bfloat16* base = sm + (kc&1)*TB;
        __nv_bfloat16* sAh = base;
        __nv_bfloat16* sAl = base + HL_TILE_ELEMS;
        __nv_bfloat16* sBh = base + 2*HL_TILE_ELEMS;
        __nv_bfloat16* sBl = base + 3*HL_TILE_ELEMS;
        #pragma unroll
        for (int ks = 0; ks < 4; ks++) {
            int kb = ks * 16;
            uint32_t ah[2][4], al[2][4];
            #pragma unroll
            for (int mi = 0; mi < 2; mi++) {
                int row = wm*32 + mi*16 + g;
                const __nv_bfloat16* p0 = sAh + row*HLP + kb + tg*2;
                const __nv_bfloat16* p1 = sAh + (row+8)*HLP + kb + tg*2;
                ah[mi][0] = *(const uint32_t*)(p0);
                ah[mi][1] = *(const uint32_t*)(p1);
                ah[mi][2] = *(const uint32_t*)(p0 + 8);
                ah[mi][3] = *(const uint32_t*)(p1 + 8);
                const __nv_bfloat16* q0 = sAl + row*HLP + kb + tg*2;
                const __nv_bfloat16* q1 = sAl + (row+8)*HLP + kb + tg*2;
                al[mi][0] = *(const uint32_t*)(q0);
                al[mi][1] = *(const uint32_t*)(q1);
                al[mi][2] = *(const uint32_t*)(q0 + 8);
                al[mi][3] = *(const uint32_t*)(q1 + 8);
            }
            #pragma unroll
            for (int nj = 0; nj < 8; nj++) {
                int col = wn*64 + nj*8 + g;
                const __nv_bfloat16* pb = sBh + col*HLP + kb + tg*2;
                const __nv_bfloat16* pl = sBl + col*HLP + kb + tg*2;
                uint32_t bh0 = *(const uint32_t*)(pb);
                uint32_t bh1 = *(const uint32_t*)(pb + 8);
                uint32_t bl0 = *(const uint32_t*)(pl);
                uint32_t bl1 = *(const uint32_t*)(pl + 8);
                #pragma unroll
                for (int mi = 0; mi < 2; mi++) {
                    mma16816(acc[mi][nj], ah[mi], bh0, bh1);
                    mma16816(acc[mi][nj], ah[mi], bl0, bl1);
                    mma16816(acc[mi][nj], al[mi], bh0, bh1);
                }
            }
        }
        __syncthreads();
    }
    #undef HL_ISSUE

    #pragma unroll
    for (int mi = 0; mi < 2; mi++) {
        int row = m0 + wm*32 + mi*16 + g;
        #pragma unroll
        for (int nj = 0; nj < 8; nj++) {
            int col = n0 + wn*64 + nj*8 + tg*2;
            *(float2*)(&g_HL[(size_t)row * Dd + col])     = make_float2(acc[mi][nj][0], acc[mi][nj][1]);
            *(float2*)(&g_HL[(size_t)(row+8) * Dd + col]) = make_float2(acc[mi][nj][2], acc[mi][nj][3]);
        }
    }
}

// ---------------- K6: score + softmax + TENSOR-CORE aggregate + relu + residual ----------
// Per (h, n) block, 256 threads (8 warps).
// A = coefs [i=128(pad)][j=120(pad)] bf16 hi/lo; B = masked HL^T [d=128][j=120] bf16 hi/lo.
// out[i][d] = sum_j coef[i][j] * HL[j][d]  via 3-term split mma, K=112 (7 chunks).
#define K6P 120
#define K6_TILE (128*K6P)
#define K6_F_OFF 0
#define K6_BF_OFF 2560                          // 2*315*4 = 2520, pad to 2560
#define K6_SMEM_BYTES (K6_BF_OFF + 4*K6_TILE*2) // 2560 + 122880 = 125440

__device__ __forceinline__ float k6_score(int t, const float* f1s, const float* f2s, int i, int j) {
    if (t > 0) {
        float v = f1s[(t-1)*Ee + i] + f2s[(t-1)*Ee + j];
        return v > 0.f ? v : 0.2f*v;
    }
    return NEGV;
}

__global__ __launch_bounds__(256) void k6_attn(const int* __restrict__ adj, float* __restrict__ out) {
    int h = blockIdx.x, n = blockIdx.y;
    extern __shared__ char smraw[];
    float* f1s = (float*)(smraw + K6_F_OFF);          // 3*105
    float* f2s = f1s + Tt*Ee;                         // 3*105
    __nv_bfloat16* sAh = (__nv_bfloat16*)(smraw + K6_BF_OFF);
    __nv_bfloat16* sAl = sAh + K6_TILE;
    __nv_bfloat16* sBh = sAl + K6_TILE;
    __nv_bfloat16* sBl = sBh + K6_TILE;
    int tid = threadIdx.x;
    int w = tid >> 5, lane = tid & 31;

    // zero all bf16 tiles (covers all pads: i>=105 rows, j>=105 cols)
    {
        uint4 z = make_uint4(0,0,0,0);
        uint4* p = (uint4*)(smraw + K6_BF_OFF);
        for (int i = tid; i < (4*K6_TILE*2)/16; i += 256) p[i] = z;
    }
    for (int i = tid; i < Tt*Ee; i += 256) {
        int t = i / Ee, e = i % Ee;
        f1s[i] = g_F[(size_t)(h*Tt+t)*Nn*Ee + n*Ee + e];
        f2s[i] = g_F[(size_t)HT*Nn*Ee + (size_t)(h*Tt+t)*Nn*Ee + n*Ee + e];
    }
    __syncthreads();

    // ---- coef phase: 14 groups of 8 rows, one row per warp ----
    const int* adjn = adj + n*Ee*Ee;
    for (int ig = 0; ig < 14; ig++) {
        int i = ig*8 + w;
        if (i < Ee) {
            const int* arow = adjn + i*Ee;
            float s0 = k6_score(arow[lane],    f1s, f2s, i, lane);
            float s1 = k6_score(arow[lane+32], f1s, f2s, i, lane+32);
            float s2 = k6_score(arow[lane+64], f1s, f2s, i, lane+64);
            float s3 = (lane < 9) ? k6_score(arow[lane+96], f1s, f2s, i, lane+96) : -INFINITY;
            float m = fmaxf(fmaxf(s0, s1), fmaxf(s2, s3));
            #pragma unroll
            for (int o = 16; o > 0; o >>= 1) m = fmaxf(m, __shfl_xor_sync(0xffffffffu, m, o));
            float p0 = __expf(s0 - m), p1 = __expf(s1 - m), p2 = __expf(s2 - m);
            float p3 = (lane < 9) ? __expf(s3 - m) : 0.f;
            float sum = p0 + p1 + p2 + p3;
            #pragma unroll
            for (int o = 16; o > 0; o >>= 1) sum += __shfl_xor_sync(0xffffffffu, sum, o);
            float inv = 1.f / sum;
            float c0 = p0*inv, c1 = p1*inv, c2 = p2*inv;
            __nv_bfloat16 hi;
            hi = __float2bfloat16(c0);
            sAh[i*K6P + lane] = hi;      sAl[i*K6P + lane]      = __float2bfloat16(c0 - __bfloat162float(hi));
            hi = __float2bfloat16(c1);
            sAh[i*K6P + lane + 32] = hi; sAl[i*K6P + lane + 32] = __float2bfloat16(c1 - __bfloat162float(hi));
            hi = __float2bfloat16(c2);
            sAh[i*K6P + lane + 64] = hi; sAl[i*K6P + lane + 64] = __float2bfloat16(c2 - __bfloat162float(hi));
            if (lane < 9) {
                float c3 = p3*inv;
                hi = __float2bfloat16(c3);
                sAh[i*K6P + lane + 96] = hi; sAl[i*K6P + lane + 96] = __float2bfloat16(c3 - __bfloat162float(hi));
            }
        }
    }

    // ---- B phase: masked HL transposed: B[d][j] = HL[j][h*128+d] * mask[j] ----
    {
        int d = tid & 127, half = tid >> 7;
        const float* hlb = g_HL + (size_t)n*Ee*Dd + h*DHd + d;
        const float* mk = g_mask + n*Ee;
        for (int j = half; j < Ee; j += 2) {
            float v = hlb[(size_t)j*Dd] * mk[j];
            __nv_bfloat16 hi = __float2bfloat16(v);
            sBh[d*K6P + j] = hi;
            sBl[d*K6P + j] = __float2bfloat16(v - __bfloat162float(hi));
        }
    }
    __syncthreads();

    // ---- MMA: warp w -> rows w*16..w*16+15; K=112 (7 chunks); N=128 (16 nj) ----
    int g = lane >> 2, tg = lane & 3;
    float acc[16][4];
    #pragma unroll
    for (int j = 0; j < 16; j++)
        #pragma unroll
        for (int q = 0; q < 4; q++) acc[j][q] = 0.f;

    for (int kc = 0; kc < 7; kc++) {
        int kb = kc*16;
        int row = w*16 + g;
        uint32_t ah[4], al[4];
        const __nv_bfloat16* p0 = sAh + row*K6P + kb + tg*2;
        const __nv_bfloat16* p1 = sAh + (row+8)*K6P + kb + tg*2;
        ah[0] = *(const uint32_t*)(p0);
        ah[1] = *(const uint32_t*)(p1);
        ah[2] = *(const uint32_t*)(p0 + 8);
        ah[3] = *(const uint32_t*)(p1 + 8);
        const __nv_bfloat16* q0 = sAl + row*K6P + kb + tg*2;
        const __nv_bfloat16* q1 = sAl + (row+8)*K6P + kb + tg*2;
        al[0] = *(const uint32_t*)(q0);
        al[1] = *(const uint32_t*)(q1);
        al[2] = *(const uint32_t*)(q0 + 8);
        al[3] = *(const uint32_t*)(q1 + 8);
        #pragma unroll
        for (int nj = 0; nj < 16; nj++) {
            int col = nj*8 + g;
            const __nv_bfloat16* pb = sBh + col*K6P + kb + tg*2;
            const __nv_bfloat16* pl = sBl + col*K6P + kb + tg*2;
            uint32_t bh0 = *(const uint32_t*)(pb);
            uint32_t bh1 = *(const uint32_t*)(pb + 8);
            uint32_t bl0 = *(const uint32_t*)(pl);
            uint32_t bl1 = *(const uint32_t*)(pl + 8);
            mma16816(acc[nj], ah, bh0, bh1);
            mma16816(acc[nj], ah, bl0, bl1);
            mma16816(acc[nj], al, bh0, bh1);
        }
    }

    // ---- epilogue: relu + residual ----
    #pragma unroll
    for (int rr = 0; rr < 2; rr++) {
        int i = w*16 + rr*8 + g;
        if (i < Ee) {
            size_t rowo = (size_t)(n*Ee + i)*Dd + h*DHd;
            #pragma unroll
            for (int nj = 0; nj < 16; nj++) {
                int col = nj*8 + tg*2;
                float v0 = fmaxf(acc[nj][rr*2+0], 0.f) + g_X[rowo + col];
                float v1 = fmaxf(acc[nj][rr*2+1], 0.f) + g_X[rowo + col + 1];
                *(float2*)(&out[rowo + col]) = make_float2(v0, v1);
            }
        }
    }
}

// ---------------- launch (fork-join dual-stream graph) ----------------
extern "C" void kernel_launch(void* const* d_in, const int* in_sizes, int n_in,
                              void* d_out, int out_size) {
    const float* q    = (const float*)d_in[0];
    const float* para = (const float*)d_in[1];
    const float* sent = (const float*)d_in[2];
    const float* ent  = (const float*)d_in[3];
    const float* pm   = (const float*)d_in[4];
    const float* sm_  = (const float*)d_in[5];
    const float* em   = (const float*)d_in[6];
    const int*   adj  = (const int*)  d_in[7];
    const float* W    = (const float*)d_in[8];
    const float* a    = (const float*)d_in[9];
    const float* qW1  = (const float*)d_in[10];
    const float* qW2  = (const float*)d_in[11];
    float* out = (float*)d_out;

    static cudaStream_t sB = nullptr;
    static cudaEvent_t evFork = nullptr, evA1 = nullptr, evB1 = nullptr, evB2 = nullptr;
    if (sB == nullptr) {
        cudaStreamCreateWithFlags(&sB, cudaStreamNonBlocking);
        cudaEventCreateWithFlags(&evFork, cudaEventDisableTiming);
        cudaEventCreateWithFlags(&evA1,   cudaEventDisableTiming);
        cudaEventCreateWithFlags(&evB1,   cudaEventDisableTiming);
        cudaEventCreateWithFlags(&evB2,   cudaEventDisableTiming);
        cudaFuncSetAttribute(k6_attn,   cudaFuncAttributeMaxDynamicSharedMemorySize, K6_SMEM_BYTES);
        cudaFuncSetAttribute(k_hl_mma,  cudaFuncAttributeMaxDynamicSharedMemorySize, HL_DB_SMEM_BYTES);
        cudaFuncSetAttribute(k_u_mma,   cudaFuncAttributeMaxDynamicSharedMemorySize, HL_SMEM_BYTES);
        cudaFuncSetAttribute(k_qw1_mma, cudaFuncAttributeMaxDynamicSharedMemorySize, HL_SMEM_BYTES);
        cudaFuncSetAttribute(k_f_mma,   cudaFuncAttributeMaxDynamicSharedMemorySize, HL_SMEM_BYTES);
    }

    cudaEventRecord(evFork, 0);
    cudaStreamWaitEvent(sB, evFork, 0);

    // ---- stream A (legacy): X-side chain ----
    k_concat<<<(Nn*Ee*Dd + 255)/256, 256>>>(q, para, sent, ent);
    cudaEventRecord(evA1, 0);                       // X splits ready (for f_mma)
    k_mask<<<(Nn*Ee + 255)/256, 256>>>(pm, sm_, em);

    // ---- stream B: q-side chain ----
    k_repack_bf<<<(Dd*Dd + 255)/256, 256, 0, sB>>>(W);
    cudaEventRecord(evB1, sB);                      // WB ready (for hl)
    k_split_q<<<(Nn*Dd + 255)/256, 256, 0, sB>>>(q);
    k_tsplit_qw1<<<dim3(32, 8, HT), dim3(32, 8), 0, sB>>>(qW1);
    k_qw1_mma<<<dim3(2,2,HT), 256, HL_SMEM_BYTES, sB>>>();
    k_gemm_qw2<<<dim3(4,4,HT), 256, 0, sB>>>(qW2, a);
    k_u_mma<<<dim3(8,2,2*HT), 256, HL_SMEM_BYTES, sB>>>(W);
    cudaStreamWaitEvent(sB, evA1, 0);               // f needs X splits
    k_f_mma<<<Nn, 256, HL_SMEM_BYTES, sB>>>();
    cudaEventRecord(evB2, sB);

    // ---- stream A: hl (needs concat + repack) then join + k6 ----
    cudaStreamWaitEvent(0, evB1, 0);
    k_hl_mma<<<dim3(8,210), 256, HL_DB_SMEM_BYTES>>>();
    cudaStreamWaitEvent(0, evB2, 0);
    k6_attn<<<dim3(Hh,Nn), 256, K6_SMEM_BYTES>>>(adj, out);
}

// round 12
// speedup vs baseline: 3.5197x; 1.1800x over previous
#include <cuda_runtime.h>
#include <cuda_bf16.h>
#include <math.h>
#include <stdint.h>

#define Nn 256
#define Pp 4
#define Sr 40
#define Enn 60
#define Ee 105
#define Dd 1024
#define Hh 8
#define Tt 3
#define DHd 128
#define HT 24           // H*T
#define NEGV -1e30f

// ---------------- scratch (device globals; no allocations allowed) ----------------
static __device__ float g_X [Nn*Ee*Dd];           // concat input fp32 (110 MB)
static __device__ __nv_bfloat16 g_Xh[Nn*Ee*Dd];   // bf16 hi split of X
static __device__ __nv_bfloat16 g_Xl[Nn*Ee*Dd];   // bf16 lo split of X
static __device__ float g_mask[Nn*Ee];
static __device__ int   g_rowidx[Nn*Ee];          // compacted active-row list
static __device__ int   g_nactive;                // count
static __device__ __nv_bfloat16 g_qh[Nn*Dd];      // q split
static __device__ __nv_bfloat16 g_ql[Nn*Dd];
static __device__ __nv_bfloat16 g_q1h[HT*256*Dd]; // qW1^T split: [ht][n=256][k=1024]
static __device__ __nv_bfloat16 g_q1l[HT*256*Dd];
static __device__ float g_R [HT*Nn*256];          // relu(q @ qW1)
static __device__ float g_V [2*HT*Nn*DHd];        // v1 (r=ht), v2 (r=24+ht)  fp32
static __device__ float g_U [2*HT*Nn*Dd];         // u = W @ v (fp32)
static __device__ float g_F [2*HT*Nn*Ee];         // f1, f2  [r][n][e]
static __device__ __nv_bfloat16 g_WBh[Dd*Dd];     // W[:,T-1]^T as [N=1024][K=1024] bf16 hi
static __device__ __nv_bfloat16 g_WBl[Dd*Dd];     // lo
static __device__ float g_HL[Nn*Ee*Dd];           // h_last (pre-mask) (110 MB)

// ---------------- K1: concat x (fp32 + bf16 hi/lo split) ----------------
__global__ void k_concat(const float* __restrict__ q, const float* __restrict__ para,
                         const float* __restrict__ sent, const float* __restrict__ ent) {
    int idx = blockIdx.x * blockDim.x + threadIdx.x;
    if (idx >= Nn*Ee*Dd) return;
    int d  = idx & (Dd-1);
    int ne = idx >> 10;
    int e  = ne % Ee;
    int n  = ne / Ee;
    float v;
    if (e == 0)              v = q   [n*Dd + d];
    else if (e < 1+Pp)       v = para[(n*Pp  + (e-1))*Dd + d];
    else if (e < 1+Pp+Sr)    v = sent[(n*Sr  + (e-1-Pp))*Dd + d];
    else                     v = ent [(n*Enn + (e-1-Pp-Sr))*Dd + d];
    g_X[idx] = v;
    __nv_bfloat16 hi = __float2bfloat16(v);
    g_Xh[idx] = hi;
    g_Xl[idx] = __float2bfloat16(v - __bfloat162float(hi));
}

__global__ void k_mask(const float* __restrict__ pm, const float* __restrict__ sm_,
                       const float* __restrict__ em) {
    int idx = blockIdx.x * blockDim.x + threadIdx.x;
    if (idx >= Nn*Ee) return;
    int e = idx % Ee, n = idx / Ee;
    float v;
    if (e == 0)            v = 1.f;
    else if (e < 1+Pp)     v = pm[n*Pp  + e-1];
    else if (e < 1+Pp+Sr)  v = sm_[n*Sr + e-1-Pp];
    else                   v = em[n*Enn + e-1-Pp-Sr];
    g_mask[idx] = v;
}

__global__ void k_compact_reset() {
    if (threadIdx.x == 0 && blockIdx.x == 0) g_nactive = 0;
}
__global__ void k_compact() {
    int idx = blockIdx.x * blockDim.x + threadIdx.x;
    if (idx >= Nn*Ee) return;
    if (g_mask[idx] > 0.f) {
        int pos = atomicAdd(&g_nactive, 1);
        g_rowidx[pos] = idx;
    }
}

__global__ void k_split_q(const float* __restrict__ q) {
    int idx = blockIdx.x * blockDim.x + threadIdx.x;
    if (idx >= Nn*Dd) return;
    float v = q[idx];
    __nv_bfloat16 hi = __float2bfloat16(v);
    g_qh[idx] = hi;
    g_ql[idx] = __float2bfloat16(v - __bfloat162float(hi));
}

// transpose+split qW1: [ht][k=1024][n=256] -> [ht][n=256][k=1024]
__global__ void k_tsplit_qw1(const float* __restrict__ qW1) {
    __shared__ float t[32][33];
    int ht = blockIdx.z;
    int k0 = blockIdx.x*32, n0 = blockIdx.y*32;
    int tx = threadIdx.x, ty = threadIdx.y;     // 32x8
    const float* src = qW1 + (size_t)ht*Dd*256;
    #pragma unroll
    for (int j = 0; j < 4; j++)
        t[ty+8*j][tx] = src[(size_t)(k0+ty+8*j)*256 + n0 + tx];
    __syncthreads();
    #pragma unroll
    for (int j = 0; j < 4; j++) {
        int nrow = n0 + ty + 8*j;
        int kcol = k0 + tx;
        float v = t[tx][ty+8*j];
        __nv_bfloat16 hi = __float2bfloat16(v);
        size_t o = (size_t)ht*256*Dd + (size_t)nrow*Dd + kcol;
        g_q1h[o] = hi;
        g_q1l[o] = __float2bfloat16(v - __bfloat162float(hi));
    }
}

// ---------------- shared mma bits ----------------
#define HLP 72
#define HL_TILE_ELEMS (128*HLP)
#define HL_SMEM_BYTES (4*HL_TILE_ELEMS*2)
#define HL_IDX_BYTES 1024
#define HL_DB_SMEM_BYTES (HL_IDX_BYTES + 8*HL_TILE_ELEMS*2)

__device__ __forceinline__ void mma16816(float* c, const uint32_t* a, uint32_t b0, uint32_t b1) {
    asm volatile(
        "mma.sync.aligned.m16n8k16.row.col.f32.bf16.bf16.f32 "
        "{%0,%1,%2,%3}, {%4,%5,%6,%7}, {%8,%9}, {%0,%1,%2,%3};"
        : "+f"(c[0]), "+f"(c[1]), "+f"(c[2]), "+f"(c[3])
        : "r"(a[0]), "r"(a[1]), "r"(a[2]), "r"(a[3]), "r"(b0), "r"(b1));
}

__device__ __forceinline__ void split2(float x, float y, __nv_bfloat162* ph, __nv_bfloat162* pl) {
    __nv_bfloat162 h, l;
    h.x = __float2bfloat16(x);
    h.y = __float2bfloat16(y);
    l.x = __float2bfloat16(x - __bfloat162float(h.x));
    l.y = __float2bfloat16(y - __bfloat162float(h.y));
    *ph = h; *pl = l;
}

__device__ __forceinline__ void cp16(void* dst, const void* src) {
    uint32_t d = (uint32_t)__cvta_generic_to_shared(dst);
    asm volatile("cp.async.ca.shared.global [%0], [%1], 16;" :: "r"(d), "l"(src));
}
#define CP_COMMIT() asm volatile("cp.async.commit_group;")
#define CP_WAIT1()  asm volatile("cp.async.wait_group 1;")
#define CP_WAIT0()  asm volatile("cp.async.wait_group 0;")

// ---------------- K2a: R = relu(q @ qW1[ht]^T) via mma clone (round-9 proven) ----------------
__global__ __launch_bounds__(256) void k_qw1_mma() {
    extern __shared__ __nv_bfloat16 sm[];
    __nv_bfloat16* sAh = sm;
    __nv_bfloat16* sAl = sm + HL_TILE_ELEMS;
    __nv_bfloat16* sBh = sm + 2*HL_TILE_ELEMS;
    __nv_bfloat16* sBl = sm + 3*HL_TILE_ELEMS;
    int tid = threadIdx.x;
    int warp = tid >> 5, lane = tid & 31;
    int wm = warp & 3, wn = warp >> 2;
    int g = lane >> 2, tg = lane & 3;
    int n0 = blockIdx.x * 128;
    int m0 = blockIdx.y * 128;
    int ht = blockIdx.z;

    const __nv_bfloat16* Ahb = g_qh + (size_t)m0 * Dd;
    const __nv_bfloat16* Alb = g_ql + (size_t)m0 * Dd;
    const __nv_bfloat16* Bhb = g_q1h + (size_t)ht*256*Dd + (size_t)n0 * Dd;
    const __nv_bfloat16* Blb = g_q1l + (size_t)ht*256*Dd + (size_t)n0 * Dd;

    float acc[2][8][4];
    #pragma unroll
    for (int i=0;i<2;i++)
        #pragma unroll
        for (int j=0;j<8;j++)
            #pragma unroll
            for (int q=0;q<4;q++) acc[i][j][q] = 0.f;

    int sr = tid >> 3;
    int sc = (tid & 7) * 8;

    for (int kc = 0; kc < 16; kc++) {
        #pragma unroll
        for (int it = 0; it < 4; it++) {
            int r = sr + it*32;
            size_t go = (size_t)r * Dd + kc*64 + sc;
            int so = r * HLP + sc;
            *(uint4*)(sAh + so) = *(const uint4*)(Ahb + go);
            *(uint4*)(sAl + so) = *(const uint4*)(Alb + go);
            *(uint4*)(sBh + so) = *(const uint4*)(Bhb + go);
            *(uint4*)(sBl + so) = *(const uint4*)(Blb + go);
        }
        __syncthreads();
        #pragma unroll
        for (int ks = 0; ks < 4; ks++) {
            int kb = ks * 16;
            uint32_t ah[2][4], al[2][4];
            #pragma unroll
            for (int mi = 0; mi < 2; mi++) {
                int row = wm*32 + mi*16 + g;
                const __nv_bfloat16* p0 = sAh + row*HLP + kb + tg*2;
                const __nv_bfloat16* p1 = sAh + (row+8)*HLP + kb + tg*2;
                ah[mi][0] = *(const uint32_t*)(p0);
                ah[mi][1] = *(const uint32_t*)(p1);
                ah[mi][2] = *(const uint32_t*)(p0 + 8);
                ah[mi][3] = *(const uint32_t*)(p1 + 8);
                const __nv_bfloat16* q0 = sAl + row*HLP + kb + tg*2;
                const __nv_bfloat16* q1 = sAl + (row+8)*HLP + kb + tg*2;
                al[mi][0] = *(const uint32_t*)(q0);
                al[mi][1] = *(const uint32_t*)(q1);
                al[mi][2] = *(const uint32_t*)(q0 + 8);
                al[mi][3] = *(const uint32_t*)(q1 + 8);
            }
            #pragma unroll
            for (int nj = 0; nj < 8; nj++) {
                int col = wn*64 + nj*8 + g;
                const __nv_bfloat16* pb = sBh + col*HLP + kb + tg*2;
                const __nv_bfloat16* pl = sBl + col*HLP + kb + tg*2;
                uint32_t bh0 = *(const uint32_t*)(pb);
                uint32_t bh1 = *(const uint32_t*)(pb + 8);
                uint32_t bl0 = *(const uint32_t*)(pl);
                uint32_t bl1 = *(const uint32_t*)(pl + 8);
                #pragma unroll
                for (int mi = 0; mi < 2; mi++) {
                    mma16816(acc[mi][nj], ah[mi], bh0, bh1);
                    mma16816(acc[mi][nj], ah[mi], bl0, bl1);
                    mma16816(acc[mi][nj], al[mi], bh0, bh1);
                }
            }
        }
        __syncthreads();
    }

    float* Cb = g_R + (size_t)ht*Nn*256;
    #pragma unroll
    for (int mi = 0; mi < 2; mi++) {
        int row = m0 + wm*32 + mi*16 + g;
        #pragma unroll
        for (int nj = 0; nj < 8; nj++) {
            int col = n0 + wn*64 + nj*8 + tg*2;
            *(float2*)(&Cb[(size_t)row*256 + col]) =
                make_float2(fmaxf(acc[mi][nj][0], 0.f), fmaxf(acc[mi][nj][1], 0.f));
            *(float2*)(&Cb[(size_t)(row+8)*256 + col]) =
                make_float2(fmaxf(acc[mi][nj][2], 0.f), fmaxf(acc[mi][nj][3], 0.f));
        }
    }
}

// ---------------- K2b: S = sigmoid(R @ qW2[ht]); V = S * a (fp32, round-3 proven) --------
__global__ __launch_bounds__(256) void k_gemm_qw2(const float* __restrict__ qW2,
                                                  const float* __restrict__ a_in) {
    int ht = blockIdx.z;
    int m0 = blockIdx.x*64, n0 = blockIdx.y*64;
    __shared__ float As[16][64];
    __shared__ float Bs[16][64];
    int tid = threadIdx.x;
    int tr = tid/16, tc = tid%16;
    int lm = tid/4,  lk4 = (tid%4)*4;
    int lbk = tid/16, lbc4 = (tid%16)*4;
    const float* Ab = g_R + (size_t)ht*Nn*256;
    const float* Bb = qW2 + (size_t)ht*256*256;
    float acc[4][4] = {};
    for (int k0 = 0; k0 < 256; k0 += 16) {
        float4 av = *(const float4*)(Ab + (m0+lm)*256 + k0 + lk4);
        As[lk4+0][lm]=av.x; As[lk4+1][lm]=av.y; As[lk4+2][lm]=av.z; As[lk4+3][lm]=av.w;
        float4 bv = *(const float4*)(Bb + (size_t)(k0+lbk)*256 + n0 + lbc4);
        *(float4*)(&Bs[lbk][lbc4]) = bv;
        __syncthreads();
        #pragma unroll
        for (int kk = 0; kk < 16; kk++) {
            float4 a = *(const float4*)(&As[kk][tr*4]);
            float4 b = *(const float4*)(&Bs[kk][tc*4]);
            float aa[4]={a.x,a.y,a.z,a.w}, bb[4]={b.x,b.y,b.z,b.w};
            #pragma unroll
            for (int i=0;i<4;i++)
                #pragma unroll
                for (int j=0;j<4;j++) acc[i][j] = fmaf(aa[i], bb[j], acc[i][j]);
        }
        __syncthreads();
    }
    const float* av = a_in + ht*256;
    #pragma unroll
    for (int i=0;i<4;i++) {
        int row = m0 + tr*4 + i;
        #pragma unroll
        for (int j=0;j<4;j++) {
            int col = n0 + tc*4 + j;
            float s = 1.f / (1.f + __expf(-acc[i][j]));
            float val = s * av[col];
            if (col < DHd) g_V[(size_t)ht*Nn*DHd + row*DHd + col] = val;
            else           g_V[(size_t)HT*Nn*DHd + (size_t)ht*Nn*DHd + row*DHd + (col-DHd)] = val;
        }
    }
}

// ---------------- K3: U[r] = V[r] @ W[ht]^T via mma (round-8 proven clone) ----------------
__global__ __launch_bounds__(256) void k_u_mma(const float* __restrict__ W) {
    extern __shared__ __nv_bfloat16 sm[];
    __nv_bfloat16* sAh = sm;
    __nv_bfloat16* sAl = sm + HL_TILE_ELEMS;
    __nv_bfloat16* sBh = sm + 2*HL_TILE_ELEMS;
    __nv_bfloat16* sBl = sm + 3*HL_TILE_ELEMS;
    int tid = threadIdx.x;
    int warp = tid >> 5, lane = tid & 31;
    int wm = warp & 3, wn = warp >> 2;
    int g = lane >> 2, tg = lane & 3;
    int n0 = blockIdx.x * 128;
    int m0 = blockIdx.y * 128;
    int r  = blockIdx.z;
    int ht = r % HT;

    const float* Ab = g_V + (size_t)r*Nn*DHd + (size_t)m0*DHd;
    const float* Bb = W   + (size_t)ht*Dd*DHd + (size_t)n0*DHd;

    float acc[2][8][4];
    #pragma unroll
    for (int i=0;i<2;i++)
        #pragma unroll
        for (int j=0;j<8;j++)
            #pragma unroll
            for (int q=0;q<4;q++) acc[i][j][q] = 0.f;

    int sr = tid >> 3;
    int sc = (tid & 7) * 8;

    for (int kc = 0; kc < 2; kc++) {
        #pragma unroll
        for (int it = 0; it < 4; it++) {
            int rr = sr + it*32;
            const float* pa = Ab + (size_t)rr*DHd + kc*64 + sc;
            const float* pb = Bb + (size_t)rr*DHd + kc*64 + sc;
            int so = rr * HLP + sc;
            #pragma unroll
            for (int jj = 0; jj < 8; jj += 4) {
                float4 va = *(const float4*)(pa + jj);
                split2(va.x, va.y, (__nv_bfloat162*)(sAh + so + jj),     (__nv_bfloat162*)(sAl + so + jj));
                split2(va.z, va.w, (__nv_bfloat162*)(sAh + so + jj + 2), (__nv_bfloat162*)(sAl + so + jj + 2));
                float4 vb = *(const float4*)(pb + jj);
                split2(vb.x, vb.y, (__nv_bfloat162*)(sBh + so + jj),     (__nv_bfloat162*)(sBl + so + jj));
                split2(vb.z, vb.w, (__nv_bfloat162*)(sBh + so + jj + 2), (__nv_bfloat162*)(sBl + so + jj + 2));
            }
        }
        __syncthreads();
        #pragma unroll
        for (int ks = 0; ks < 4; ks++) {
            int kb = ks * 16;
            uint32_t ah[2][4], al[2][4];
            #pragma unroll
            for (int mi = 0; mi < 2; mi++) {
                int row = wm*32 + mi*16 + g;
                const __nv_bfloat16* p0 = sAh + row*HLP + kb + tg*2;
                const __nv_bfloat16* p1 = sAh + (row+8)*HLP + kb + tg*2;
                ah[mi][0] = *(const uint32_t*)(p0);
                ah[mi][1] = *(const uint32_t*)(p1);
                ah[mi][2] = *(const uint32_t*)(p0 + 8);
                ah[mi][3] = *(const uint32_t*)(p1 + 8);
                const __nv_bfloat16* q0 = sAl + row*HLP + kb + tg*2;
                const __nv_bfloat16* q1 = sAl + (row+8)*HLP + kb + tg*2;
                al[mi][0] = *(const uint32_t*)(q0);
                al[mi][1] = *(const uint32_t*)(q1);
                al[mi][2] = *(const uint32_t*)(q0 + 8);
                al[mi][3] = *(const uint32_t*)(q1 + 8);
            }
            #pragma unroll
            for (int nj = 0; nj < 8; nj++) {
                int col = wn*64 + nj*8 + g;
                const __nv_bfloat16* pb = sBh + col*HLP + kb + tg*2;
                const __nv_bfloat16* pl = sBl + col*HLP + kb + tg*2;
                uint32_t bh0 = *(const uint32_t*)(pb);
                uint32_t bh1 = *(const uint32_t*)(pb + 8);
                uint32_t bl0 = *(const uint32_t*)(pl);
                uint32_t bl1 = *(const uint32_t*)(pl + 8);
                #pragma unroll
                for (int mi = 0; mi < 2; mi++) {
                    mma16816(acc[mi][nj], ah[mi], bh0, bh1);
                    mma16816(acc[mi][nj], ah[mi], bl0, bl1);
                    mma16816(acc[mi][nj], al[mi], bh0, bh1);
                }
            }
        }
        __syncthreads();
    }

    #pragma unroll
    for (int mi = 0; mi < 2; mi++) {
        int row = m0 + wm*32 + mi*16 + g;
        #pragma unroll
        for (int nj = 0; nj < 8; nj++) {
            int col = n0 + wn*64 + nj*8 + tg*2;
            *(float2*)(&g_U[(size_t)r*Nn*Dd + (size_t)row*Dd + col])     = make_float2(acc[mi][nj][0], acc[mi][nj][1]);
            *(float2*)(&g_U[(size_t)r*Nn*Dd + (size_t)(row+8)*Dd + col]) = make_float2(acc[mi][nj][2], acc[mi][nj][3]);
        }
    }
}

// ---------------- K4: F via mma (round-9 proven) ----------------
__global__ __launch_bounds__(256) void k_f_mma() {
    extern __shared__ __nv_bfloat16 sm[];
    __nv_bfloat16* sAh = sm;
    __nv_bfloat16* sAl = sm + HL_TILE_ELEMS;
    __nv_bfloat16* sBh = sm + 2*HL_TILE_ELEMS;
    __nv_bfloat16* sBl = sm + 3*HL_TILE_ELEMS;
    int n = blockIdx.x;
    int tid = threadIdx.x;
    int warp = tid >> 5, lane = tid & 31;
    int wm = warp & 3, wn = warp >> 2;
    int g = lane >> 2, tg = lane & 3;

    float acc[2][3][4];
    #pragma unroll
    for (int i=0;i<2;i++)
        #pragma unroll
        for (int j=0;j<3;j++)
            #pragma unroll
            for (int q=0;q<4;q++) acc[i][j][q] = 0.f;

    int sr = tid >> 3;
    int sc = (tid & 7) * 8;
    const __nv_bfloat16* Ahb = g_Xh + (size_t)n * Ee * Dd;
    const __nv_bfloat16* Alb = g_Xl + (size_t)n * Ee * Dd;

    for (int kc = 0; kc < 16; kc++) {
        #pragma unroll
        for (int it = 0; it < 4; it++) {
            int r = sr + it*32;
            int rc = (r < Ee) ? r : (Ee-1);
            size_t go = (size_t)rc * Dd + kc*64 + sc;
            int so = r * HLP + sc;
            *(uint4*)(sAh + so) = *(const uint4*)(Ahb + go);
            *(uint4*)(sAl + so) = *(const uint4*)(Alb + go);
        }
        for (int i = tid; i < 384; i += 256) {
            int r = i >> 3, c = (i & 7) * 8;
            const float* pb = g_U + (size_t)r*(Nn*Dd) + (size_t)n*Dd + kc*64 + c;
            int so = r * HLP + c;
            #pragma unroll
            for (int jj = 0; jj < 8; jj += 4) {
                float4 vb = *(const float4*)(pb + jj);
                split2(vb.x, vb.y, (__nv_bfloat162*)(sBh + so + jj),     (__nv_bfloat162*)(sBl + so + jj));
                split2(vb.z, vb.w, (__nv_bfloat162*)(sBh + so + jj + 2), (__nv_bfloat162*)(sBl + so + jj + 2));
            }
        }
        __syncthreads();
        #pragma unroll
        for (int ks = 0; ks < 4; ks++) {
            int kb = ks * 16;
            uint32_t ah[2][4], al[2][4];
            #pragma unroll
            for (int mi = 0; mi < 2; mi++) {
                int row = wm*32 + mi*16 + g;
                const __nv_bfloat16* p0 = sAh + row*HLP + kb + tg*2;
                const __nv_bfloat16* p1 = sAh + (row+8)*HLP + kb + tg*2;
                ah[mi][0] = *(const uint32_t*)(p0);
                ah[mi][1] = *(const uint32_t*)(p1);
                ah[mi][2] = *(const uint32_t*)(p0 + 8);
                ah[mi][3] = *(const uint32_t*)(p1 + 8);
                const __nv_bfloat16* q0 = sAl + row*HLP + kb + tg*2;
                const __nv_bfloat16* q1 = sAl + (row+8)*HLP + kb + tg*2;
                al[mi][0] = *(const uint32_t*)(q0);
                al[mi][1] = *(const uint32_t*)(q1);
                al[mi][2] = *(const uint32_t*)(q0 + 8);
                al[mi][3] = *(const uint32_t*)(q1 + 8);
            }
            #pragma unroll
            for (int nj = 0; nj < 3; nj++) {
                int col = wn*24 + nj*8 + g;
                const __nv_bfloat16* pb = sBh + col*HLP + kb + tg*2;
                const __nv_bfloat16* pl = sBl + col*HLP + kb + tg*2;
                uint32_t bh0 = *(const uint32_t*)(pb);
                uint32_t bh1 = *(const uint32_t*)(pb + 8);
                uint32_t bl0 = *(const uint32_t*)(pl);
                uint32_t bl1 = *(const uint32_t*)(pl + 8);
                #pragma unroll
                for (int mi = 0; mi < 2; mi++) {
                    mma16816(acc[mi][nj], ah[mi], bh0, bh1);
                    mma16816(acc[mi][nj], ah[mi], bl0, bl1);
                    mma16816(acc[mi][nj], al[mi], bh0, bh1);
                }
            }
        }
        __syncthreads();
    }

    #pragma unroll
    for (int mi = 0; mi < 2; mi++) {
        int e0 = wm*32 + mi*16 + g;
        #pragma unroll
        for (int nj = 0; nj < 3; nj++) {
            int r = wn*24 + nj*8 + tg*2;
            if (e0 < Ee) {
                g_F[(size_t)r*Nn*Ee + n*Ee + e0]     = acc[mi][nj][0];
                g_F[(size_t)(r+1)*Nn*Ee + n*Ee + e0] = acc[mi][nj][1];
            }
            if (e0 + 8 < Ee) {
                g_F[(size_t)r*Nn*Ee + n*Ee + e0 + 8]     = acc[mi][nj][2];
                g_F[(size_t)(r+1)*Nn*Ee + n*Ee + e0 + 8] = acc[mi][nj][3];
            }
        }
    }
}

// ---------------- K5a: repack W[:, T-1]^T into [N=1024][K=1024] bf16 hi/lo ----
__global__ void k_repack_bf(const float* __restrict__ W) {
    int idx = blockIdx.x * blockDim.x + threadIdx.x;
    if (idx >= Dd*Dd) return;
    int d = idx & 1023, col = idx >> 10;         // out[col][d]
    int h = col >> 7, k = col & 127;
    float v = W[((size_t)(h*Tt + (Tt-1))*Dd + d)*DHd + k];
    __nv_bfloat16 hi = __float2bfloat16(v);
    g_WBh[idx] = hi;
    g_WBl[idx] = __float2bfloat16(v - __bfloat162float(hi));
}

// ---------------- K5b: HL = X @ WB^T, ACTIVE ROWS ONLY (mask compaction), cp.async DB ----
__global__ __launch_bounds__(256) void k_hl_mma() {
    extern __shared__ char smraw[];
    int* ridx = (int*)smraw;                             // 128 gathered row indices
    __nv_bfloat16* smbuf = (__nv_bfloat16*)(smraw + HL_IDX_BYTES);
    const int TB = 4*HL_TILE_ELEMS;
    int tid = threadIdx.x;
    int warp = tid >> 5, lane = tid & 31;
    int wm = warp & 3, wn = warp >> 2;
    int g = lane >> 2, tg = lane & 3;
    int n0 = blockIdx.x * 128;
    int mbase = blockIdx.y * 128;

    int count = g_nactive;
    if (mbase >= count) return;
    if (tid < 128) {
        int li = mbase + tid;
        ridx[tid] = g_rowidx[li < count ? li : (count-1)];
    }
    __syncthreads();

    const __nv_bfloat16* Bh0 = g_WBh + (size_t)n0 * Dd;
    const __nv_bfloat16* Bl0 = g_WBl + (size_t)n0 * Dd;

    float acc[2][8][4];
    #pragma unroll
    for (int i=0;i<2;i++)
        #pragma unroll
        for (int j=0;j<8;j++)
            #pragma unroll
            for (int q=0;q<4;q++) acc[i][j][q] = 0.f;

    int sr = tid >> 3;
    int sc = (tid & 7) * 8;

    #define HL_ISSUE(kc, b) do {                                                   \
        __nv_bfloat16* base = smbuf + (b)*TB;                                      \
        _Pragma("unroll")                                                          \
        for (int it = 0; it < 4; it++) {                                           \
            int r = sr + it*32;                                                    \
            size_t ga = (size_t)ridx[r] * Dd + (kc)*64 + sc;                       \
            size_t gb = (size_t)r * Dd + (kc)*64 + sc;                             \
            int so = r * HLP + sc;                                                 \
            cp16(base + so,                     g_Xh + ga);                        \
            cp16(base + HL_TILE_ELEMS + so,     g_Xl + ga);                        \
            cp16(base + 2*HL_TILE_ELEMS + so,   Bh0 + gb);                         \
            cp16(base + 3*HL_TILE_ELEMS + so,   Bl0 + gb);                         \
        }                                                                          \
        CP_COMMIT();                                                               \
    } while (0)

    HL_ISSUE(0, 0);
    for (int kc = 0; kc < 16; kc++) {
        if (kc < 15) { HL_ISSUE(kc+1, (kc+1)&1); CP_WAIT1(); }
        else         { CP_WAIT0(); }
        __syncthreads();
        __nv_bfloat16* base = smbuf + (kc&1)*TB;
        __nv_bfloat16* sAh = base;
        __nv_bfloat16* sAl = base + HL_TILE_ELEMS;
        __nv_bfloat16* sBh = base + 2*HL_TILE_ELEMS;
        __nv_bfloat16* sBl = base + 3*HL_TILE_ELEMS;
        #pragma unroll
        for (int ks = 0; ks < 4; ks++) {
            int kb = ks * 16;
            uint32_t ah[2][4], al[2][4];
            #pragma unroll
            for (int mi = 0; mi < 2; mi++) {
                int row = wm*32 + mi*16 + g;
                const __nv_bfloat16* p0 = sAh + row*HLP + kb + tg*2;
                const __nv_bfloat16* p1 = sAh + (row+8)*HLP + kb + tg*2;
                ah[mi][0] = *(const uint32_t*)(p0);
                ah[mi][1] = *(const uint32_t*)(p1);
                ah[mi][2] = *(const uint32_t*)(p0 + 8);
                ah[mi][3] = *(const uint32_t*)(p1 + 8);
                const __nv_bfloat16* q0 = sAl + row*HLP + kb + tg*2;
                const __nv_bfloat16* q1 = sAl + (row+8)*HLP + kb + tg*2;
                al[mi][0] = *(const uint32_t*)(q0);
                al[mi][1] = *(const uint32_t*)(q1);
                al[mi][2] = *(const uint32_t*)(q0 + 8);
                al[mi][3] = *(const uint32_t*)(q1 + 8);
            }
            #pragma unroll
            for (int nj = 0; nj < 8; nj++) {
                int col = wn*64 + nj*8 + g;
                const __nv_bfloat16* pb = sBh + col*HLP + kb + tg*2;
                const __nv_bfloat16* pl = sBl + col*HLP + kb + tg*2;
                uint32_t bh0 = *(const uint32_t*)(pb);
                uint32_t bh1 = *(const uint32_t*)(pb + 8);
                uint32_t bl0 = *(const uint32_t*)(pl);
                uint32_t bl1 = *(const uint32_t*)(pl + 8);
                #pragma unroll
                for (int mi = 0; mi < 2; mi++) {
                    mma16816(acc[mi][nj], ah[mi], bh0, bh1);
                    mma16816(acc[mi][nj], ah[mi], bl0, bl1);
                    mma16816(acc[mi][nj], al[mi], bh0, bh1);
                }
            }
        }
        __syncthreads();
    }
    #undef HL_ISSUE

    #pragma unroll
    for (int mi = 0; mi < 2; mi++) {
        int rl = wm*32 + mi*16 + g;
        size_t row0 = (size_t)ridx[rl];
        size_t row1 = (size_t)ridx[rl + 8];
        #pragma unroll
        for (int nj = 0; nj < 8; nj++) {
            int col = n0 + wn*64 + nj*8 + tg*2;
            *(float2*)(&g_HL[row0 * Dd + col]) = make_float2(acc[mi][nj][0], acc[mi][nj][1]);
            *(float2*)(&g_HL[row1 * Dd + col]) = make_float2(acc[mi][nj][2], acc[mi][nj][3]);
        }
    }
}

// ---------------- K6: score + softmax + TENSOR-CORE aggregate + relu + residual ----------
#define K6P 120
#define K6_TILE (128*K6P)
#define K6_F_OFF 0
#define K6_BF_OFF 2560
#define K6_SMEM_BYTES (K6_BF_OFF + 4*K6_TILE*2)

__device__ __forceinline__ float k6_score(int t, const float* f1s, const float* f2s, int i, int j) {
    if (t > 0) {
        float v = f1s[(t-1)*Ee + i] + f2s[(t-1)*Ee + j];
        return v > 0.f ? v : 0.2f*v;
    }
    return NEGV;
}

__global__ __launch_bounds__(256) void k6_attn(const int* __restrict__ adj, float* __restrict__ out) {
    int h = blockIdx.x, n = blockIdx.y;
    extern __shared__ char smraw[];
    float* f1s = (float*)(smraw + K6_F_OFF);
    float* f2s = f1s + Tt*Ee;
    __nv_bfloat16* sAh = (__nv_bfloat16*)(smraw + K6_BF_OFF);
    __nv_bfloat16* sAl = sAh + K6_TILE;
    __nv_bfloat16* sBh = sAl + K6_TILE;
    __nv_bfloat16* sBl = sBh + K6_TILE;
    int tid = threadIdx.x;
    int w = tid >> 5, lane = tid & 31;

    {
        uint4 z = make_uint4(0,0,0,0);
        uint4* p = (uint4*)(smraw + K6_BF_OFF);
        for (int i = tid; i < (4*K6_TILE*2)/16; i += 256) p[i] = z;
    }
    for (int i = tid; i < Tt*Ee; i += 256) {
        int t = i / Ee, e = i % Ee;
        f1s[i] = g_F[(size_t)(h*Tt+t)*Nn*Ee + n*Ee + e];
        f2s[i] = g_F[(size_t)HT*Nn*Ee + (size_t)(h*Tt+t)*Nn*Ee + n*Ee + e];
    }
    __syncthreads();

    const int* adjn = adj + n*Ee*Ee;
    for (int ig = 0; ig < 14; ig++) {
        int i = ig*8 + w;
        if (i < Ee) {
            const int* arow = adjn + i*Ee;
            float s0 = k6_score(arow[lane],    f1s, f2s, i, lane);
            float s1 = k6_score(arow[lane+32], f1s, f2s, i, lane+32);
            float s2 = k6_score(arow[lane+64], f1s, f2s, i, lane+64);
            float s3 = (lane < 9) ? k6_score(arow[lane+96], f1s, f2s, i, lane+96) : -INFINITY;
            float m = fmaxf(fmaxf(s0, s1), fmaxf(s2, s3));
            #pragma unroll
            for (int o = 16; o > 0; o >>= 1) m = fmaxf(m, __shfl_xor_sync(0xffffffffu, m, o));
            float p0 = __expf(s0 - m), p1 = __expf(s1 - m), p2 = __expf(s2 - m);
            float p3 = (lane < 9) ? __expf(s3 - m) : 0.f;
            float sum = p0 + p1 + p2 + p3;
            #pragma unroll
            for (int o = 16; o > 0; o >>= 1) sum += __shfl_xor_sync(0xffffffffu, sum, o);
            float inv = 1.f / sum;
            float c0 = p0*inv, c1 = p1*inv, c2 = p2*inv;
            __nv_bfloat16 hi;
            hi = __float2bfloat16(c0);
            sAh[i*K6P + lane] = hi;      sAl[i*K6P + lane]      = __float2bfloat16(c0 - __bfloat162float(hi));
            hi = __float2bfloat16(c1);
            sAh[i*K6P + lane + 32] = hi; sAl[i*K6P + lane + 32] = __float2bfloat16(c1 - __bfloat162float(hi));
            hi = __float2bfloat16(c2);
            sAh[i*K6P + lane + 64] = hi; sAl[i*K6P + lane + 64] = __float2bfloat16(c2 - __bfloat162float(hi));
            if (lane < 9) {
                float c3 = p3*inv;
                hi = __float2bfloat16(c3);
                sAh[i*K6P + lane + 96] = hi; sAl[i*K6P + lane + 96] = __float2bfloat16(c3 - __bfloat162float(hi));
            }
        }
    }

    {
        int d = tid & 127, half = tid >> 7;
        const float* hlb = g_HL + (size_t)n*Ee*Dd + h*DHd + d;
        const float* mk = g_mask + n*Ee;
        for (int j = half; j < Ee; j += 2) {
            float v = hlb[(size_t)j*Dd] * mk[j];
            __nv_bfloat16 hi = __float2bfloat16(v);
            sBh[d*K6P + j] = hi;
            sBl[d*K6P + j] = __float2bfloat16(v - __bfloat162float(hi));
        }
    }
    __syncthreads();

    int g = lane >> 2, tg = lane & 3;
    float acc[16][4];
    #pragma unroll
    for (int j = 0; j < 16; j++)
        #pragma unroll
        for (int q = 0; q < 4; q++) acc[j][q] = 0.f;

    for (int kc = 0; kc < 7; kc++) {
        int kb = kc*16;
        int row = w*16 + g;
        uint32_t ah[4], al[4];
        const __nv_bfloat16* p0 = sAh + row*K6P + kb + tg*2;
        const __nv_bfloat16* p1 = sAh + (row+8)*K6P + kb + tg*2;
        ah[0] = *(const uint32_t*)(p0);
        ah[1] = *(const uint32_t*)(p1);
        ah[2] = *(const uint32_t*)(p0 + 8);
        ah[3] = *(const uint32_t*)(p1 + 8);
        const __nv_bfloat16* q0 = sAl + row*K6P + kb + tg*2;
        const __nv_bfloat16* q1 = sAl + (row+8)*K6P + kb + tg*2;
        al[0] = *(const uint32_t*)(q0);
        al[1] = *(const uint32_t*)(q1);
        al[2] = *(const uint32_t*)(q0 + 8);
        al[3] = *(const uint32_t*)(q1 + 8);
        #pragma unroll
        for (int nj = 0; nj < 16; nj++) {
            int col = nj*8 + g;
            const __nv_bfloat16* pb = sBh + col*K6P + kb + tg*2;
            const __nv_bfloat16* pl = sBl + col*K6P + kb + tg*2;
            uint32_t bh0 = *(const uint32_t*)(pb);
            uint32_t bh1 = *(const uint32_t*)(pb + 8);
            uint32_t bl0 = *(const uint32_t*)(pl);
            uint32_t bl1 = *(const uint32_t*)(pl + 8);
            mma16816(acc[nj], ah, bh0, bh1);
            mma16816(acc[nj], ah, bl0, bl1);
            mma16816(acc[nj], al, bh0, bh1);
        }
    }

    #pragma unroll
    for (int rr = 0; rr < 2; rr++) {
        int i = w*16 + rr*8 + g;
        if (i < Ee) {
            size_t rowo = (size_t)(n*Ee + i)*Dd + h*DHd;
            #pragma unroll
            for (int nj = 0; nj < 16; nj++) {
                int col = nj*8 + tg*2;
                float v0 = fmaxf(acc[nj][rr*2+0], 0.f) + g_X[rowo + col];
                float v1 = fmaxf(acc[nj][rr*2+1], 0.f) + g_X[rowo + col + 1];
                *(float2*)(&out[rowo + col]) = make_float2(v0, v1);
            }
        }
    }
}

// ---------------- launch (fork-join dual-stream graph) ----------------
extern "C" void kernel_launch(void* const* d_in, const int* in_sizes, int n_in,
                              void* d_out, int out_size) {
    const float* q    = (const float*)d_in[0];
    const float* para = (const float*)d_in[1];
    const float* sent = (const float*)d_in[2];
    const float* ent  = (const float*)d_in[3];
    const float* pm   = (const float*)d_in[4];
    const float* sm_  = (const float*)d_in[5];
    const float* em   = (const float*)d_in[6];
    const int*   adj  = (const int*)  d_in[7];
    const float* W    = (const float*)d_in[8];
    const float* a    = (const float*)d_in[9];
    const float* qW1  = (const float*)d_in[10];
    const float* qW2  = (const float*)d_in[11];
    float* out = (float*)d_out;

    static cudaStream_t sB = nullptr;
    static cudaEvent_t evFork = nullptr, evA1 = nullptr, evB1 = nullptr, evB2 = nullptr;
    if (sB == nullptr) {
        cudaStreamCreateWithFlags(&sB, cudaStreamNonBlocking);
        cudaEventCreateWithFlags(&evFork, cudaEventDisableTiming);
        cudaEventCreateWithFlags(&evA1,   cudaEventDisableTiming);
        cudaEventCreateWithFlags(&evB1,   cudaEventDisableTiming);
        cudaEventCreateWithFlags(&evB2,   cudaEventDisableTiming);
        cudaFuncSetAttribute(k6_attn,   cudaFuncAttributeMaxDynamicSharedMemorySize, K6_SMEM_BYTES);
        cudaFuncSetAttribute(k_hl_mma,  cudaFuncAttributeMaxDynamicSharedMemorySize, HL_DB_SMEM_BYTES);
        cudaFuncSetAttribute(k_u_mma,   cudaFuncAttributeMaxDynamicSharedMemorySize, HL_SMEM_BYTES);
        cudaFuncSetAttribute(k_qw1_mma, cudaFuncAttributeMaxDynamicSharedMemorySize, HL_SMEM_BYTES);
        cudaFuncSetAttribute(k_f_mma,   cudaFuncAttributeMaxDynamicSharedMemorySize, HL_SMEM_BYTES);
    }

    cudaEventRecord(evFork, 0);
    cudaStreamWaitEvent(sB, evFork, 0);

    // ---- stream A (legacy): X-side chain ----
    k_concat<<<(Nn*Ee*Dd + 255)/256, 256>>>(q, para, sent, ent);
    cudaEventRecord(evA1, 0);                       // X splits ready (for f_mma)
    k_mask<<<(Nn*Ee + 255)/256, 256>>>(pm, sm_, em);
    k_compact_reset<<<1, 1>>>();
    k_compact<<<(Nn*Ee + 255)/256, 256>>>();

    // ---- stream B: q-side chain ----
    k_repack_bf<<<(Dd*Dd + 255)/256, 256, 0, sB>>>(W);
    cudaEventRecord(evB1, sB);                      // WB ready (for hl)
    k_split_q<<<(Nn*Dd + 255)/256, 256, 0, sB>>>(q);
    k_tsplit_qw1<<<dim3(32, 8, HT), dim3(32, 8), 0, sB>>>(qW1);
    k_qw1_mma<<<dim3(2,2,HT), 256, HL_SMEM_BYTES, sB>>>();
    k_gemm_qw2<<<dim3(4,4,HT), 256, 0, sB>>>(qW2, a);
    k_u_mma<<<dim3(8,2,2*HT), 256, HL_SMEM_BYTES, sB>>>(W);
    cudaStreamWaitEvent(sB, evA1, 0);               // f needs X splits
    k_f_mma<<<Nn, 256, HL_SMEM_BYTES, sB>>>();
    cudaEventRecord(evB2, sB);

    // ---- stream A: hl (needs concat + compact + repack) then join + k6 ----
    cudaStreamWaitEvent(0, evB1, 0);
    k_hl_mma<<<dim3(8,210), 256, HL_DB_SMEM_BYTES>>>();
    cudaStreamWaitEvent(0, evB2, 0);
    k6_attn<<<dim3(Hh,Nn), 256, K6_SMEM_BYTES>>>(adj, out);
}

// round 13
// speedup vs baseline: 3.9858x; 1.1324x over previous
#include <cuda_runtime.h>
#include <cuda_bf16.h>
#include <math.h>
#include <stdint.h>

#define Nn 256
#define Pp 4
#define Sr 40
#define Enn 60
#define Ee 105
#define Dd 1024
#define Hh 8
#define Tt 3
#define DHd 128
#define HT 24           // H*T
#define NEGV -1e30f

// ---------------- scratch (device globals; no allocations allowed) ----------------
static __device__ __nv_bfloat16 g_Xh[Nn*Ee*Dd];   // bf16 hi split of X
static __device__ __nv_bfloat16 g_Xl[Nn*Ee*Dd];   // bf16 lo split of X
static __device__ float g_mask[Nn*Ee];
static __device__ int   g_rowidx[Nn*Ee];          // compacted active-row list
static __device__ int   g_nactive;                // count
static __device__ __nv_bfloat16 g_qh[Nn*Dd];      // q split
static __device__ __nv_bfloat16 g_ql[Nn*Dd];
static __device__ __nv_bfloat16 g_q1h[HT*256*Dd]; // qW1^T split: [ht][n=256][k=1024]
static __device__ __nv_bfloat16 g_q1l[HT*256*Dd];
static __device__ float g_R [HT*Nn*256];          // relu(q @ qW1)
static __device__ float g_V [2*HT*Nn*DHd];        // v1 (r=ht), v2 (r=24+ht)  fp32
static __device__ float g_U [2*HT*Nn*Dd];         // u = W @ v (fp32)
static __device__ float g_F [2*HT*Nn*Ee];         // f1, f2  [r][n][e]
static __device__ __nv_bfloat16 g_WBh[Dd*Dd];     // W[:,T-1]^T as [N=1024][K=1024] bf16 hi
static __device__ __nv_bfloat16 g_WBl[Dd*Dd];     // lo
static __device__ float g_HL[Nn*Ee*Dd];           // h_last (pre-mask) (110 MB)

__device__ __forceinline__ void split2(float x, float y, __nv_bfloat162* ph, __nv_bfloat162* pl) {
    __nv_bfloat162 h, l;
    h.x = __float2bfloat16(x);
    h.y = __float2bfloat16(y);
    l.x = __float2bfloat16(x - __bfloat162float(h.x));
    l.y = __float2bfloat16(y - __bfloat162float(h.y));
    *ph = h; *pl = l;
}

// ---------------- K1: concat x (vectorized, bf16 hi/lo only) ----------------
__global__ void k_concat(const float* __restrict__ q, const float* __restrict__ para,
                         const float* __restrict__ sent, const float* __restrict__ ent) {
    int idx = (blockIdx.x * blockDim.x + threadIdx.x) * 4;
    if (idx >= Nn*Ee*Dd) return;
    int d  = idx & (Dd-1);
    int ne = idx >> 10;
    int e  = ne % Ee;
    int n  = ne / Ee;
    const float* src;
    if (e == 0)              src = q    + (size_t)n*Dd + d;
    else if (e < 1+Pp)       src = para + (size_t)(n*Pp  + (e-1))*Dd + d;
    else if (e < 1+Pp+Sr)    src = sent + (size_t)(n*Sr  + (e-1-Pp))*Dd + d;
    else                     src = ent  + (size_t)(n*Enn + (e-1-Pp-Sr))*Dd + d;
    float4 v = *(const float4*)(src);
    __nv_bfloat162 h01, h23, l01, l23;
    split2(v.x, v.y, &h01, &l01);
    split2(v.z, v.w, &h23, &l23);
    ((__nv_bfloat162*)(g_Xh + idx))[0] = h01;
    ((__nv_bfloat162*)(g_Xh + idx))[1] = h23;
    ((__nv_bfloat162*)(g_Xl + idx))[0] = l01;
    ((__nv_bfloat162*)(g_Xl + idx))[1] = l23;
}

__global__ void k_mask(const float* __restrict__ pm, const float* __restrict__ sm_,
                       const float* __restrict__ em) {
    int idx = blockIdx.x * blockDim.x + threadIdx.x;
    if (idx >= Nn*Ee) return;
    int e = idx % Ee, n = idx / Ee;
    float v;
    if (e == 0)            v = 1.f;
    else if (e < 1+Pp)     v = pm[n*Pp  + e-1];
    else if (e < 1+Pp+Sr)  v = sm_[n*Sr + e-1-Pp];
    else                   v = em[n*Enn + e-1-Pp-Sr];
    g_mask[idx] = v;
}

__global__ void k_compact_reset() {
    if (threadIdx.x == 0 && blockIdx.x == 0) g_nactive = 0;
}
__global__ void k_compact() {
    int idx = blockIdx.x * blockDim.x + threadIdx.x;
    if (idx >= Nn*Ee) return;
    if (g_mask[idx] > 0.f) {
        int pos = atomicAdd(&g_nactive, 1);
        g_rowidx[pos] = idx;
    }
}

__global__ void k_split_q(const float* __restrict__ q) {
    int idx = blockIdx.x * blockDim.x + threadIdx.x;
    if (idx >= Nn*Dd) return;
    float v = q[idx];
    __nv_bfloat16 hi = __float2bfloat16(v);
    g_qh[idx] = hi;
    g_ql[idx] = __float2bfloat16(v - __bfloat162float(hi));
}

// transpose+split qW1: [ht][k=1024][n=256] -> [ht][n=256][k=1024]
__global__ void k_tsplit_qw1(const float* __restrict__ qW1) {
    __shared__ float t[32][33];
    int ht = blockIdx.z;
    int k0 = blockIdx.x*32, n0 = blockIdx.y*32;
    int tx = threadIdx.x, ty = threadIdx.y;     // 32x8
    const float* src = qW1 + (size_t)ht*Dd*256;
    #pragma unroll
    for (int j = 0; j < 4; j++)
        t[ty+8*j][tx] = src[(size_t)(k0+ty+8*j)*256 + n0 + tx];
    __syncthreads();
    #pragma unroll
    for (int j = 0; j < 4; j++) {
        int nrow = n0 + ty + 8*j;
        int kcol = k0 + tx;
        float v = t[tx][ty+8*j];
        __nv_bfloat16 hi = __float2bfloat16(v);
        size_t o = (size_t)ht*256*Dd + (size_t)nrow*Dd + kcol;
        g_q1h[o] = hi;
        g_q1l[o] = __float2bfloat16(v - __bfloat162float(hi));
    }
}

// ---------------- shared mma bits ----------------
#define HLP 72
#define HL_TILE_ELEMS (128*HLP)
#define HL_SMEM_BYTES (4*HL_TILE_ELEMS*2)
#define HL_IDX_BYTES 1024
#define HL_DB_SMEM_BYTES (HL_IDX_BYTES + 8*HL_TILE_ELEMS*2)

__device__ __forceinline__ void mma16816(float* c, const uint32_t* a, uint32_t b0, uint32_t b1) {
    asm volatile(
        "mma.sync.aligned.m16n8k16.row.col.f32.bf16.bf16.f32 "
        "{%0,%1,%2,%3}, {%4,%5,%6,%7}, {%8,%9}, {%0,%1,%2,%3};"
        : "+f"(c[0]), "+f"(c[1]), "+f"(c[2]), "+f"(c[3])
        : "r"(a[0]), "r"(a[1]), "r"(a[2]), "r"(a[3]), "r"(b0), "r"(b1));
}

__device__ __forceinline__ void cp16(void* dst, const void* src) {
    uint32_t d = (uint32_t)__cvta_generic_to_shared(dst);
    asm volatile("cp.async.ca.shared.global [%0], [%1], 16;" :: "r"(d), "l"(src));
}
#define CP_COMMIT() asm volatile("cp.async.commit_group;")
#define CP_WAIT1()  asm volatile("cp.async.wait_group 1;")
#define CP_WAIT0()  asm volatile("cp.async.wait_group 0;")

// ---------------- K2a: R = relu(q @ qW1[ht]^T) via mma clone (round-9 proven) ----------------
__global__ __launch_bounds__(256) void k_qw1_mma() {
    extern __shared__ __nv_bfloat16 sm[];
    __nv_bfloat16* sAh = sm;
    __nv_bfloat16* sAl = sm + HL_TILE_ELEMS;
    __nv_bfloat16* sBh = sm + 2*HL_TILE_ELEMS;
    __nv_bfloat16* sBl = sm + 3*HL_TILE_ELEMS;
    int tid = threadIdx.x;
    int warp = tid >> 5, lane = tid & 31;
    int wm = warp & 3, wn = warp >> 2;
    int g = lane >> 2, tg = lane & 3;
    int n0 = blockIdx.x * 128;
    int m0 = blockIdx.y * 128;
    int ht = blockIdx.z;

    const __nv_bfloat16* Ahb = g_qh + (size_t)m0 * Dd;
    const __nv_bfloat16* Alb = g_ql + (size_t)m0 * Dd;
    const __nv_bfloat16* Bhb = g_q1h + (size_t)ht*256*Dd + (size_t)n0 * Dd;
    const __nv_bfloat16* Blb = g_q1l + (size_t)ht*256*Dd + (size_t)n0 * Dd;

    float acc[2][8][4];
    #pragma unroll
    for (int i=0;i<2;i++)
        #pragma unroll
        for (int j=0;j<8;j++)
            #pragma unroll
            for (int q=0;q<4;q++) acc[i][j][q] = 0.f;

    int sr = tid >> 3;
    int sc = (tid & 7) * 8;

    for (int kc = 0; kc < 16; kc++) {
        #pragma unroll
        for (int it = 0; it < 4; it++) {
            int r = sr + it*32;
            size_t go = (size_t)r * Dd + kc*64 + sc;
            int so = r * HLP + sc;
            *(uint4*)(sAh + so) = *(const uint4*)(Ahb + go);
            *(uint4*)(sAl + so) = *(const uint4*)(Alb + go);
            *(uint4*)(sBh + so) = *(const uint4*)(Bhb + go);
            *(uint4*)(sBl + so) = *(const uint4*)(Blb + go);
        }
        __syncthreads();
        #pragma unroll
        for (int ks = 0; ks < 4; ks++) {
            int kb = ks * 16;
            uint32_t ah[2][4], al[2][4];
            #pragma unroll
            for (int mi = 0; mi < 2; mi++) {
                int row = wm*32 + mi*16 + g;
                const __nv_bfloat16* p0 = sAh + row*HLP + kb + tg*2;
                const __nv_bfloat16* p1 = sAh + (row+8)*HLP + kb + tg*2;
                ah[mi][0] = *(const uint32_t*)(p0);
                ah[mi][1] = *(const uint32_t*)(p1);
                ah[mi][2] = *(const uint32_t*)(p0 + 8);
                ah[mi][3] = *(const uint32_t*)(p1 + 8);
                const __nv_bfloat16* q0 = sAl + row*HLP + kb + tg*2;
                const __nv_bfloat16* q1 = sAl + (row+8)*HLP + kb + tg*2;
                al[mi][0] = *(const uint32_t*)(q0);
                al[mi][1] = *(const uint32_t*)(q1);
                al[mi][2] = *(const uint32_t*)(q0 + 8);
                al[mi][3] = *(const uint32_t*)(q1 + 8);
            }
            #pragma unroll
            for (int nj = 0; nj < 8; nj++) {
                int col = wn*64 + nj*8 + g;
                const __nv_bfloat16* pb = sBh + col*HLP + kb + tg*2;
                const __nv_bfloat16* pl = sBl + col*HLP + kb + tg*2;
                uint32_t bh0 = *(const uint32_t*)(pb);
                uint32_t bh1 = *(const uint32_t*)(pb + 8);
                uint32_t bl0 = *(const uint32_t*)(pl);
                uint32_t bl1 = *(const uint32_t*)(pl + 8);
                #pragma unroll
                for (int mi = 0; mi < 2; mi++) {
                    mma16816(acc[mi][nj], ah[mi], bh0, bh1);
                    mma16816(acc[mi][nj], ah[mi], bl0, bl1);
                    mma16816(acc[mi][nj], al[mi], bh0, bh1);
                }
            }
        }
        __syncthreads();
    }

    float* Cb = g_R + (size_t)ht*Nn*256;
    #pragma unroll
    for (int mi = 0; mi < 2; mi++) {
        int row = m0 + wm*32 + mi*16 + g;
        #pragma unroll
        for (int nj = 0; nj < 8; nj++) {
            int col = n0 + wn*64 + nj*8 + tg*2;
            *(float2*)(&Cb[(size_t)row*256 + col]) =
                make_float2(fmaxf(acc[mi][nj][0], 0.f), fmaxf(acc[mi][nj][1], 0.f));
            *(float2*)(&Cb[(size_t)(row+8)*256 + col]) =
                make_float2(fmaxf(acc[mi][nj][2], 0.f), fmaxf(acc[mi][nj][3], 0.f));
        }
    }
}

// ---------------- K2b: S = sigmoid(R @ qW2[ht]); V = S * a (fp32, round-3 proven) --------
__global__ __launch_bounds__(256) void k_gemm_qw2(const float* __restrict__ qW2,
                                                  const float* __restrict__ a_in) {
    int ht = blockIdx.z;
    int m0 = blockIdx.x*64, n0 = blockIdx.y*64;
    __shared__ float As[16][64];
    __shared__ float Bs[16][64];
    int tid = threadIdx.x;
    int tr = tid/16, tc = tid%16;
    int lm = tid/4,  lk4 = (tid%4)*4;
    int lbk = tid/16, lbc4 = (tid%16)*4;
    const float* Ab = g_R + (size_t)ht*Nn*256;
    const float* Bb = qW2 + (size_t)ht*256*256;
    float acc[4][4] = {};
    for (int k0 = 0; k0 < 256; k0 += 16) {
        float4 av = *(const float4*)(Ab + (m0+lm)*256 + k0 + lk4);
        As[lk4+0][lm]=av.x; As[lk4+1][lm]=av.y; As[lk4+2][lm]=av.z; As[lk4+3][lm]=av.w;
        float4 bv = *(const float4*)(Bb + (size_t)(k0+lbk)*256 + n0 + lbc4);
        *(float4*)(&Bs[lbk][lbc4]) = bv;
        __syncthreads();
        #pragma unroll
        for (int kk = 0; kk < 16; kk++) {
            float4 a = *(const float4*)(&As[kk][tr*4]);
            float4 b = *(const float4*)(&Bs[kk][tc*4]);
            float aa[4]={a.x,a.y,a.z,a.w}, bb[4]={b.x,b.y,b.z,b.w};
            #pragma unroll
            for (int i=0;i<4;i++)
                #pragma unroll
                for (int j=0;j<4;j++) acc[i][j] = fmaf(aa[i], bb[j], acc[i][j]);
        }
        __syncthreads();
    }
    const float* av = a_in + ht*256;
    #pragma unroll
    for (int i=0;i<4;i++) {
        int row = m0 + tr*4 + i;
        #pragma unroll
        for (int j=0;j<4;j++) {
            int col = n0 + tc*4 + j;
            float s = 1.f / (1.f + __expf(-acc[i][j]));
            float val = s * av[col];
            if (col < DHd) g_V[(size_t)ht*Nn*DHd + row*DHd + col] = val;
            else           g_V[(size_t)HT*Nn*DHd + (size_t)ht*Nn*DHd + row*DHd + (col-DHd)] = val;
        }
    }
}

// ---------------- K3: U[r] = V[r] @ W[ht]^T via mma (round-8 proven clone) ----------------
__global__ __launch_bounds__(256) void k_u_mma(const float* __restrict__ W) {
    extern __shared__ __nv_bfloat16 sm[];
    __nv_bfloat16* sAh = sm;
    __nv_bfloat16* sAl = sm + HL_TILE_ELEMS;
    __nv_bfloat16* sBh = sm + 2*HL_TILE_ELEMS;
    __nv_bfloat16* sBl = sm + 3*HL_TILE_ELEMS;
    int tid = threadIdx.x;
    int warp = tid >> 5, lane = tid & 31;
    int wm = warp & 3, wn = warp >> 2;
    int g = lane >> 2, tg = lane & 3;
    int n0 = blockIdx.x * 128;
    int m0 = blockIdx.y * 128;
    int r  = blockIdx.z;
    int ht = r % HT;

    const float* Ab = g_V + (size_t)r*Nn*DHd + (size_t)m0*DHd;
    const float* Bb = W   + (size_t)ht*Dd*DHd + (size_t)n0*DHd;

    float acc[2][8][4];
    #pragma unroll
    for (int i=0;i<2;i++)
        #pragma unroll
        for (int j=0;j<8;j++)
            #pragma unroll
            for (int q=0;q<4;q++) acc[i][j][q] = 0.f;

    int sr = tid >> 3;
    int sc = (tid & 7) * 8;

    for (int kc = 0; kc < 2; kc++) {
        #pragma unroll
        for (int it = 0; it < 4; it++) {
            int rr = sr + it*32;
            const float* pa = Ab + (size_t)rr*DHd + kc*64 + sc;
            const float* pb = Bb + (size_t)rr*DHd + kc*64 + sc;
            int so = rr * HLP + sc;
            #pragma unroll
            for (int jj = 0; jj < 8; jj += 4) {
                float4 va = *(const float4*)(pa + jj);
                split2(va.x, va.y, (__nv_bfloat162*)(sAh + so + jj),     (__nv_bfloat162*)(sAl + so + jj));
                split2(va.z, va.w, (__nv_bfloat162*)(sAh + so + jj + 2), (__nv_bfloat162*)(sAl + so + jj + 2));
                float4 vb = *(const float4*)(pb + jj);
                split2(vb.x, vb.y, (__nv_bfloat162*)(sBh + so + jj),     (__nv_bfloat162*)(sBl + so + jj));
                split2(vb.z, vb.w, (__nv_bfloat162*)(sBh + so + jj + 2), (__nv_bfloat162*)(sBl + so + jj + 2));
            }
        }
        __syncthreads();
        #pragma unroll
        for (int ks = 0; ks < 4; ks++) {
            int kb = ks * 16;
            uint32_t ah[2][4], al[2][4];
            #pragma unroll
            for (int mi = 0; mi < 2; mi++) {
                int row = wm*32 + mi*16 + g;
                const __nv_bfloat16* p0 = sAh + row*HLP + kb + tg*2;
                const __nv_bfloat16* p1 = sAh + (row+8)*HLP + kb + tg*2;
                ah[mi][0] = *(const uint32_t*)(p0);
                ah[mi][1] = *(const uint32_t*)(p1);
                ah[mi][2] = *(const uint32_t*)(p0 + 8);
                ah[mi][3] = *(const uint32_t*)(p1 + 8);
                const __nv_bfloat16* q0 = sAl + row*HLP + kb + tg*2;
                const __nv_bfloat16* q1 = sAl + (row+8)*HLP + kb + tg*2;
                al[mi][0] = *(const uint32_t*)(q0);
                al[mi][1] = *(const uint32_t*)(q1);
                al[mi][2] = *(const uint32_t*)(q0 + 8);
                al[mi][3] = *(const uint32_t*)(q1 + 8);
            }
            #pragma unroll
            for (int nj = 0; nj < 8; nj++) {
                int col = wn*64 + nj*8 + g;
                const __nv_bfloat16* pb = sBh + col*HLP + kb + tg*2;
                const __nv_bfloat16* pl = sBl + col*HLP + kb + tg*2;
                uint32_t bh0 = *(const uint32_t*)(pb);
                uint32_t bh1 = *(const uint32_t*)(pb + 8);
                uint32_t bl0 = *(const uint32_t*)(pl);
                uint32_t bl1 = *(const uint32_t*)(pl + 8);
                #pragma unroll
                for (int mi = 0; mi < 2; mi++) {
                    mma16816(acc[mi][nj], ah[mi], bh0, bh1);
                    mma16816(acc[mi][nj], ah[mi], bl0, bl1);
                    mma16816(acc[mi][nj], al[mi], bh0, bh1);
                }
            }
        }
        __syncthreads();
    }

    #pragma unroll
    for (int mi = 0; mi < 2; mi++) {
        int row = m0 + wm*32 + mi*16 + g;
        #pragma unroll
        for (int nj = 0; nj < 8; nj++) {
            int col = n0 + wn*64 + nj*8 + tg*2;
            *(float2*)(&g_U[(size_t)r*Nn*Dd + (size_t)row*Dd + col])     = make_float2(acc[mi][nj][0], acc[mi][nj][1]);
            *(float2*)(&g_U[(size_t)r*Nn*Dd + (size_t)(row+8)*Dd + col]) = make_float2(acc[mi][nj][2], acc[mi][nj][3]);
        }
    }
}

// ---------------- K4: F via mma (round-9 proven) ----------------
__global__ __launch_bounds__(256) void k_f_mma() {
    extern __shared__ __nv_bfloat16 sm[];
    __nv_bfloat16* sAh = sm;
    __nv_bfloat16* sAl = sm + HL_TILE_ELEMS;
    __nv_bfloat16* sBh = sm + 2*HL_TILE_ELEMS;
    __nv_bfloat16* sBl = sm + 3*HL_TILE_ELEMS;
    int n = blockIdx.x;
    int tid = threadIdx.x;
    int warp = tid >> 5, lane = tid & 31;
    int wm = warp & 3, wn = warp >> 2;
    int g = lane >> 2, tg = lane & 3;

    float acc[2][3][4];
    #pragma unroll
    for (int i=0;i<2;i++)
        #pragma unroll
        for (int j=0;j<3;j++)
            #pragma unroll
            for (int q=0;q<4;q++) acc[i][j][q] = 0.f;

    int sr = tid >> 3;
    int sc = (tid & 7) * 8;
    const __nv_bfloat16* Ahb = g_Xh + (size_t)n * Ee * Dd;
    const __nv_bfloat16* Alb = g_Xl + (size_t)n * Ee * Dd;

    for (int kc = 0; kc < 16; kc++) {
        #pragma unroll
        for (int it = 0; it < 4; it++) {
            int r = sr + it*32;
            int rc = (r < Ee) ? r : (Ee-1);
            size_t go = (size_t)rc * Dd + kc*64 + sc;
            int so = r * HLP + sc;
            *(uint4*)(sAh + so) = *(const uint4*)(Ahb + go);
            *(uint4*)(sAl + so) = *(const uint4*)(Alb + go);
        }
        for (int i = tid; i < 384; i += 256) {
            int r = i >> 3, c = (i & 7) * 8;
            const float* pb = g_U + (size_t)r*(Nn*Dd) + (size_t)n*Dd + kc*64 + c;
            int so = r * HLP + c;
            #pragma unroll
            for (int jj = 0; jj < 8; jj += 4) {
                float4 vb = *(const float4*)(pb + jj);
                split2(vb.x, vb.y, (__nv_bfloat162*)(sBh + so + jj),     (__nv_bfloat162*)(sBl + so + jj));
                split2(vb.z, vb.w, (__nv_bfloat162*)(sBh + so + jj + 2), (__nv_bfloat162*)(sBl + so + jj + 2));
            }
        }
        __syncthreads();
        #pragma unroll
        for (int ks = 0; ks < 4; ks++) {
            int kb = ks * 16;
            uint32_t ah[2][4], al[2][4];
            #pragma unroll
            for (int mi = 0; mi < 2; mi++) {
                int row = wm*32 + mi*16 + g;
                const __nv_bfloat16* p0 = sAh + row*HLP + kb + tg*2;
                const __nv_bfloat16* p1 = sAh + (row+8)*HLP + kb + tg*2;
                ah[mi][0] = *(const uint32_t*)(p0);
                ah[mi][1] = *(const uint32_t*)(p1);
                ah[mi][2] = *(const uint32_t*)(p0 + 8);
                ah[mi][3] = *(const uint32_t*)(p1 + 8);
                const __nv_bfloat16* q0 = sAl + row*HLP + kb + tg*2;
                const __nv_bfloat16* q1 = sAl + (row+8)*HLP + kb + tg*2;
                al[mi][0] = *(const uint32_t*)(q0);
                al[mi][1] = *(const uint32_t*)(q1);
                al[mi][2] = *(const uint32_t*)(q0 + 8);
                al[mi][3] = *(const uint32_t*)(q1 + 8);
            }
            #pragma unroll
            for (int nj = 0; nj < 3; nj++) {
                int col = wn*24 + nj*8 + g;
                const __nv_bfloat16* pb = sBh + col*HLP + kb + tg*2;
                const __nv_bfloat16* pl = sBl + col*HLP + kb + tg*2;
                uint32_t bh0 = *(const uint32_t*)(pb);
                uint32_t bh1 = *(const uint32_t*)(pb + 8);
                uint32_t bl0 = *(const uint32_t*)(pl);
                uint32_t bl1 = *(const uint32_t*)(pl + 8);
                #pragma unroll
                for (int mi = 0; mi < 2; mi++) {
                    mma16816(acc[mi][nj], ah[mi], bh0, bh1);
                    mma16816(acc[mi][nj], ah[mi], bl0, bl1);
                    mma16816(acc[mi][nj], al[mi], bh0, bh1);
                }
            }
        }
        __syncthreads();
    }

    #pragma unroll
    for (int mi = 0; mi < 2; mi++) {
        int e0 = wm*32 + mi*16 + g;
        #pragma unroll
        for (int nj = 0; nj < 3; nj++) {
            int r = wn*24 + nj*8 + tg*2;
            if (e0 < Ee) {
                g_F[(size_t)r*Nn*Ee + n*Ee + e0]     = acc[mi][nj][0];
                g_F[(size_t)(r+1)*Nn*Ee + n*Ee + e0] = acc[mi][nj][1];
            }
            if (e0 + 8 < Ee) {
                g_F[(size_t)r*Nn*Ee + n*Ee + e0 + 8]     = acc[mi][nj][2];
                g_F[(size_t)(r+1)*Nn*Ee + n*Ee + e0 + 8] = acc[mi][nj][3];
            }
        }
    }
}

// ---------------- K5a: repack W[:, T-1]^T into [N=1024][K=1024] bf16 hi/lo ----
__global__ void k_repack_bf(const float* __restrict__ W) {
    int idx = blockIdx.x * blockDim.x + threadIdx.x;
    if (idx >= Dd*Dd) return;
    int d = idx & 1023, col = idx >> 10;         // out[col][d]
    int h = col >> 7, k = col & 127;
    float v = W[((size_t)(h*Tt + (Tt-1))*Dd + d)*DHd + k];
    __nv_bfloat16 hi = __float2bfloat16(v);
    g_WBh[idx] = hi;
    g_WBl[idx] = __float2bfloat16(v - __bfloat162float(hi));
}

// ---------------- K5b: HL = X @ WB^T, ACTIVE ROWS ONLY (mask compaction), cp.async DB ----
__global__ __launch_bounds__(256) void k_hl_mma() {
    extern __shared__ char smraw[];
    int* ridx = (int*)smraw;
    __nv_bfloat16* smbuf = (__nv_bfloat16*)(smraw + HL_IDX_BYTES);
    const int TB = 4*HL_TILE_ELEMS;
    int tid = threadIdx.x;
    int warp = tid >> 5, lane = tid & 31;
    int wm = warp & 3, wn = warp >> 2;
    int g = lane >> 2, tg = lane & 3;
    int n0 = blockIdx.x * 128;
    int mbase = blockIdx.y * 128;

    int count = g_nactive;
    if (mbase >= count) return;
    if (tid < 128) {
        int li = mbase + tid;
        ridx[tid] = g_rowidx[li < count ? li : (count-1)];
    }
    __syncthreads();

    const __nv_bfloat16* Bh0 = g_WBh + (size_t)n0 * Dd;
    const __nv_bfloat16* Bl0 = g_WBl + (size_t)n0 * Dd;

    float acc[2][8][4];
    #pragma unroll
    for (int i=0;i<2;i++)
        #pragma unroll
        for (int j=0;j<8;j++)
            #pragma unroll
            for (int q=0;q<4;q++) acc[i][j][q] = 0.f;

    int sr = tid >> 3;
    int sc = (tid & 7) * 8;

    #define HL_ISSUE(kc, b) do {                                                   \
        __nv_bfloat16* base = smbuf + (b)*TB;                                      \
        _Pragma("unroll")                                                          \
        for (int it = 0; it < 4; it++) {                                           \
            int r = sr + it*32;                                                    \
            size_t ga = (size_t)ridx[r] * Dd + (kc)*64 + sc;                       \
            size_t gb = (size_t)r * Dd + (kc)*64 + sc;                             \
            int so = r * HLP + sc;                                                 \
            cp16(base + so,                     g_Xh + ga);                        \
            cp16(base + HL_TILE_ELEMS + so,     g_Xl + ga);                        \
            cp16(base + 2*HL_TILE_ELEMS + so,   Bh0 + gb);                         \
            cp16(base + 3*HL_TILE_ELEMS + so,   Bl0 + gb);                         \
        }                                                                          \
        CP_COMMIT();                                                               \
    } while (0)

    HL_ISSUE(0, 0);
    for (int kc = 0; kc < 16; kc++) {
        if (kc < 15) { HL_ISSUE(kc+1, (kc+1)&1); CP_WAIT1(); }
        else         { CP_WAIT0(); }
        __syncthreads();
        __nv_bfloat16* base = smbuf + (kc&1)*TB;
        __nv_bfloat16* sAh = base;
        __nv_bfloat16* sAl = base + HL_TILE_ELEMS;
        __nv_bfloat16* sBh = base + 2*HL_TILE_ELEMS;
        __nv_bfloat16* sBl = base + 3*HL_TILE_ELEMS;
        #pragma unroll
        for (int ks = 0; ks < 4; ks++) {
            int kb = ks * 16;
            uint32_t ah[2][4], al[2][4];
            #pragma unroll
            for (int mi = 0; mi < 2; mi++) {
                int row = wm*32 + mi*16 + g;
                const __nv_bfloat16* p0 = sAh + row*HLP + kb + tg*2;
                const __nv_bfloat16* p1 = sAh + (row+8)*HLP + kb + tg*2;
                ah[mi][0] = *(const uint32_t*)(p0);
                ah[mi][1] = *(const uint32_t*)(p1);
                ah[mi][2] = *(const uint32_t*)(p0 + 8);
                ah[mi][3] = *(const uint32_t*)(p1 + 8);
                const __nv_bfloat16* q0 = sAl + row*HLP + kb + tg*2;
                const __nv_bfloat16* q1 = sAl + (row+8)*HLP + kb + tg*2;
                al[mi][0] = *(const uint32_t*)(q0);
                al[mi][1] = *(const uint32_t*)(q1);
                al[mi][2] = *(const uint32_t*)(q0 + 8);
                al[mi][3] = *(const uint32_t*)(q1 + 8);
            }
            #pragma unroll
            for (int nj = 0; nj < 8; nj++) {
                int col = wn*64 + nj*8 + g;
                const __nv_bfloat16* pb = sBh + col*HLP + kb + tg*2;
                const __nv_bfloat16* pl = sBl + col*HLP + kb + tg*2;
                uint32_t bh0 = *(const uint32_t*)(pb);
                uint32_t bh1 = *(const uint32_t*)(pb + 8);
                uint32_t bl0 = *(const uint32_t*)(pl);
                uint32_t bl1 = *(const uint32_t*)(pl + 8);
                #pragma unroll
                for (int mi = 0; mi < 2; mi++) {
                    mma16816(acc[mi][nj], ah[mi], bh0, bh1);
                    mma16816(acc[mi][nj], ah[mi], bl0, bl1);
                    mma16816(acc[mi][nj], al[mi], bh0, bh1);
                }
            }
        }
        __syncthreads();
    }
    #undef HL_ISSUE

    #pragma unroll
    for (int mi = 0; mi < 2; mi++) {
        int rl = wm*32 + mi*16 + g;
        size_t row0 = (size_t)ridx[rl];
        size_t row1 = (size_t)ridx[rl + 8];
        #pragma unroll
        for (int nj = 0; nj < 8; nj++) {
            int col = n0 + wn*64 + nj*8 + tg*2;
            *(float2*)(&g_HL[row0 * Dd + col]) = make_float2(acc[mi][nj][0], acc[mi][nj][1]);
            *(float2*)(&g_HL[row1 * Dd + col]) = make_float2(acc[mi][nj][2], acc[mi][nj][3]);
        }
    }
}

// ---------------- K6: score + softmax + TENSOR-CORE aggregate + relu + residual ----------
#define K6P 120
#define K6_TILE (128*K6P)
#define K6_F_OFF 0
#define K6_BF_OFF 2560
#define K6_SMEM_BYTES (K6_BF_OFF + 4*K6_TILE*2)

__device__ __forceinline__ float k6_score(int t, const float* f1s, const float* f2s, int i, int j) {
    if (t > 0) {
        float v = f1s[(t-1)*Ee + i] + f2s[(t-1)*Ee + j];
        return v > 0.f ? v : 0.2f*v;
    }
    return NEGV;
}

__global__ __launch_bounds__(256) void k6_attn(const int* __restrict__ adj, float* __restrict__ out) {
    int h = blockIdx.x, n = blockIdx.y;
    extern __shared__ char smraw[];
    float* f1s = (float*)(smraw + K6_F_OFF);
    float* f2s = f1s + Tt*Ee;
    __nv_bfloat16* sAh = (__nv_bfloat16*)(smraw + K6_BF_OFF);
    __nv_bfloat16* sAl = sAh + K6_TILE;
    __nv_bfloat16* sBh = sAl + K6_TILE;
    __nv_bfloat16* sBl = sBh + K6_TILE;
    int tid = threadIdx.x;
    int w = tid >> 5, lane = tid & 31;

    {
        uint4 z = make_uint4(0,0,0,0);
        uint4* p = (uint4*)(smraw + K6_BF_OFF);
        for (int i = tid; i < (4*K6_TILE*2)/16; i += 256) p[i] = z;
    }
    for (int i = tid; i < Tt*Ee; i += 256) {
        int t = i / Ee, e = i % Ee;
        f1s[i] = g_F[(size_t)(h*Tt+t)*Nn*Ee + n*Ee + e];
        f2s[i] = g_F[(size_t)HT*Nn*Ee + (size_t)(h*Tt+t)*Nn*Ee + n*Ee + e];
    }
    __syncthreads();

    const int* adjn = adj + n*Ee*Ee;
    for (int ig = 0; ig < 14; ig++) {
        int i = ig*8 + w;
        if (i < Ee) {
            const int* arow = adjn + i*Ee;
            float s0 = k6_score(arow[lane],    f1s, f2s, i, lane);
            float s1 = k6_score(arow[lane+32], f1s, f2s, i, lane+32);
            float s2 = k6_score(arow[lane+64], f1s, f2s, i, lane+64);
            float s3 = (lane < 9) ? k6_score(arow[lane+96], f1s, f2s, i, lane+96) : -INFINITY;
            float m = fmaxf(fmaxf(s0, s1), fmaxf(s2, s3));
            #pragma unroll
            for (int o = 16; o > 0; o >>= 1) m = fmaxf(m, __shfl_xor_sync(0xffffffffu, m, o));
            float p0 = __expf(s0 - m), p1 = __expf(s1 - m), p2 = __expf(s2 - m);
            float p3 = (lane < 9) ? __expf(s3 - m) : 0.f;
            float sum = p0 + p1 + p2 + p3;
            #pragma unroll
            for (int o = 16; o > 0; o >>= 1) sum += __shfl_xor_sync(0xffffffffu, sum, o);
            float inv = 1.f / sum;
            float c0 = p0*inv, c1 = p1*inv, c2 = p2*inv;
            __nv_bfloat16 hi;
            hi = __float2bfloat16(c0);
            sAh[i*K6P + lane] = hi;      sAl[i*K6P + lane]      = __float2bfloat16(c0 - __bfloat162float(hi));
            hi = __float2bfloat16(c1);
            sAh[i*K6P + lane + 32] = hi; sAl[i*K6P + lane + 32] = __float2bfloat16(c1 - __bfloat162float(hi));
            hi = __float2bfloat16(c2);
            sAh[i*K6P + lane + 64] = hi; sAl[i*K6P + lane + 64] = __float2bfloat16(c2 - __bfloat162float(hi));
            if (lane < 9) {
                float c3 = p3*inv;
                hi = __float2bfloat16(c3);
                sAh[i*K6P + lane + 96] = hi; sAl[i*K6P + lane + 96] = __float2bfloat16(c3 - __bfloat162float(hi));
            }
        }
    }

    {
        int d = tid & 127, half = tid >> 7;
        const float* hlb = g_HL + (size_t)n*Ee*Dd + h*DHd + d;
        const float* mk = g_mask + n*Ee;
        for (int j = half; j < Ee; j += 2) {
            float v = hlb[(size_t)j*Dd] * mk[j];
            __nv_bfloat16 hi = __float2bfloat16(v);
            sBh[d*K6P + j] = hi;
            sBl[d*K6P + j] = __float2bfloat16(v - __bfloat162float(hi));
        }
    }
    __syncthreads();

    int g = lane >> 2, tg = lane & 3;
    float acc[16][4];
    #pragma unroll
    for (int j = 0; j < 16; j++)
        #pragma unroll
        for (int q = 0; q < 4; q++) acc[j][q] = 0.f;

    for (int kc = 0; kc < 7; kc++) {
        int kb = kc*16;
        int row = w*16 + g;
        uint32_t ah[4], al[4];
        const __nv_bfloat16* p0 = sAh + row*K6P + kb + tg*2;
        const __nv_bfloat16* p1 = sAh + (row+8)*K6P + kb + tg*2;
        ah[0] = *(const uint32_t*)(p0);
        ah[1] = *(const uint32_t*)(p1);
        ah[2] = *(const uint32_t*)(p0 + 8);
        ah[3] = *(const uint32_t*)(p1 + 8);
        const __nv_bfloat16* q0 = sAl + row*K6P + kb + tg*2;
        const __nv_bfloat16* q1 = sAl + (row+8)*K6P + kb + tg*2;
        al[0] = *(const uint32_t*)(q0);
        al[1] = *(const uint32_t*)(q1);
        al[2] = *(const uint32_t*)(q0 + 8);
        al[3] = *(const uint32_t*)(q1 + 8);
        #pragma unroll
        for (int nj = 0; nj < 16; nj++) {
            int col = nj*8 + g;
            const __nv_bfloat16* pb = sBh + col*K6P + kb + tg*2;
            const __nv_bfloat16* pl = sBl + col*K6P + kb + tg*2;
            uint32_t bh0 = *(const uint32_t*)(pb);
            uint32_t bh1 = *(const uint32_t*)(pb + 8);
            uint32_t bl0 = *(const uint32_t*)(pl);
            uint32_t bl1 = *(const uint32_t*)(pl + 8);
            mma16816(acc[nj], ah, bh0, bh1);
            mma16816(acc[nj], ah, bl0, bl1);
            mma16816(acc[nj], al, bh0, bh1);
        }
    }

    // epilogue: relu + residual (x reconstructed from bf16 hi+lo splits)
    #pragma unroll
    for (int rr = 0; rr < 2; rr++) {
        int i = w*16 + rr*8 + g;
        if (i < Ee) {
            size_t rowo = (size_t)(n*Ee + i)*Dd + h*DHd;
            #pragma unroll
            for (int nj = 0; nj < 16; nj++) {
                int col = nj*8 + tg*2;
                __nv_bfloat162 xh = *(const __nv_bfloat162*)(&g_Xh[rowo + col]);
                __nv_bfloat162 xl = *(const __nv_bfloat162*)(&g_Xl[rowo + col]);
                float x0 = __bfloat162float(xh.x) + __bfloat162float(xl.x);
                float x1 = __bfloat162float(xh.y) + __bfloat162float(xl.y);
                float v0 = fmaxf(acc[nj][rr*2+0], 0.f) + x0;
                float v1 = fmaxf(acc[nj][rr*2+1], 0.f) + x1;
                *(float2*)(&out[rowo + col]) = make_float2(v0, v1);
            }
        }
    }
}

// ---------------- launch (fork-join dual-stream graph) ----------------
extern "C" void kernel_launch(void* const* d_in, const int* in_sizes, int n_in,
                              void* d_out, int out_size) {
    const float* q    = (const float*)d_in[0];
    const float* para = (const float*)d_in[1];
    const float* sent = (const float*)d_in[2];
    const float* ent  = (const float*)d_in[3];
    const float* pm   = (const float*)d_in[4];
    const float* sm_  = (const float*)d_in[5];
    const float* em   = (const float*)d_in[6];
    const int*   adj  = (const int*)  d_in[7];
    const float* W    = (const float*)d_in[8];
    const float* a    = (const float*)d_in[9];
    const float* qW1  = (const float*)d_in[10];
    const float* qW2  = (const float*)d_in[11];
    float* out = (float*)d_out;

    static cudaStream_t sB = nullptr;
    static cudaEvent_t evFork = nullptr, evA1 = nullptr, evB1 = nullptr, evB2 = nullptr;
    if (sB == nullptr) {
        cudaStreamCreateWithFlags(&sB, cudaStreamNonBlocking);
        cudaEventCreateWithFlags(&evFork, cudaEventDisableTiming);
        cudaEventCreateWithFlags(&evA1,   cudaEventDisableTiming);
        cudaEventCreateWithFlags(&evB1,   cudaEventDisableTiming);
        cudaEventCreateWithFlags(&evB2,   cudaEventDisableTiming);
        cudaFuncSetAttribute(k6_attn,   cudaFuncAttributeMaxDynamicSharedMemorySize, K6_SMEM_BYTES);
        cudaFuncSetAttribute(k_hl_mma,  cudaFuncAttributeMaxDynamicSharedMemorySize, HL_DB_SMEM_BYTES);
        cudaFuncSetAttribute(k_u_mma,   cudaFuncAttributeMaxDynamicSharedMemorySize, HL_SMEM_BYTES);
        cudaFuncSetAttribute(k_qw1_mma, cudaFuncAttributeMaxDynamicSharedMemorySize, HL_SMEM_BYTES);
        cudaFuncSetAttribute(k_f_mma,   cudaFuncAttributeMaxDynamicSharedMemorySize, HL_SMEM_BYTES);
    }

    cudaEventRecord(evFork, 0);
    cudaStreamWaitEvent(sB, evFork, 0);

    // ---- stream A (legacy): X-side chain ----
    k_concat<<<(Nn*Ee*Dd/4 + 255)/256, 256>>>(q, para, sent, ent);
    cudaEventRecord(evA1, 0);                       // X splits ready (for f_mma)
    k_mask<<<(Nn*Ee + 255)/256, 256>>>(pm, sm_, em);
    k_compact_reset<<<1, 1>>>();
    k_compact<<<(Nn*Ee + 255)/256, 256>>>();

    // ---- stream B: q-side chain ----
    k_repack_bf<<<(Dd*Dd + 255)/256, 256, 0, sB>>>(W);
    cudaEventRecord(evB1, sB);                      // WB ready (for hl)
    k_split_q<<<(Nn*Dd + 255)/256, 256, 0, sB>>>(q);
    k_tsplit_qw1<<<dim3(32, 8, HT), dim3(32, 8), 0, sB>>>(qW1);
    k_qw1_mma<<<dim3(2,2,HT), 256, HL_SMEM_BYTES, sB>>>();
    k_gemm_qw2<<<dim3(4,4,HT), 256, 0, sB>>>(qW2, a);
    k_u_mma<<<dim3(8,2,2*HT), 256, HL_SMEM_BYTES, sB>>>(W);
    cudaStreamWaitEvent(sB, evA1, 0);               // f needs X splits
    k_f_mma<<<Nn, 256, HL_SMEM_BYTES, sB>>>();
    cudaEventRecord(evB2, sB);

    // ---- stream A: hl (needs concat + compact + repack) then join + k6 ----
    cudaStreamWaitEvent(0, evB1, 0);
    k_hl_mma<<<dim3(8,210), 256, HL_DB_SMEM_BYTES>>>();
    cudaStreamWaitEvent(0, evB2, 0);
    k6_attn<<<dim3(Hh,Nn), 256, K6_SMEM_BYTES>>>(adj, out);
}

// round 14
// speedup vs baseline: 5.1354x; 1.2884x over previous
#include <cuda_runtime.h>
#include <cuda_bf16.h>
#include <math.h>
#include <stdint.h>

#define Nn 256
#define Pp 4
#define Sr 40
#define Enn 60
#define Ee 105
#define Dd 1024
#define Hh 8
#define Tt 3
#define DHd 128
#define HT 24           // H*T
#define NEGV -1e30f

// ---------------- scratch (device globals; no allocations allowed) ----------------
static __device__ __nv_bfloat16 g_Xh[Nn*Ee*Dd];   // bf16 hi split of X
static __device__ __nv_bfloat16 g_Xl[Nn*Ee*Dd];   // bf16 lo split of X
static __device__ float g_mask[Nn*Ee];
static __device__ int   g_rowidx[Nn*Ee];          // compacted active-row list
static __device__ int   g_nactive;                // count
static __device__ __nv_bfloat16 g_qh[Nn*Dd];      // q split
static __device__ __nv_bfloat16 g_ql[Nn*Dd];
static __device__ __nv_bfloat16 g_q1h[HT*256*Dd]; // qW1^T split: [ht][n=256][k=1024]
static __device__ __nv_bfloat16 g_q1l[HT*256*Dd];
static __device__ __nv_bfloat16 g_q2h[HT*256*256]; // qW2^T split: [ht][n=256][k=256]
static __device__ __nv_bfloat16 g_q2l[HT*256*256];
static __device__ float g_R [HT*Nn*256];          // relu(q @ qW1)
static __device__ float g_V [2*HT*Nn*DHd];        // v1 (r=ht), v2 (r=24+ht)  fp32
static __device__ float g_U [2*HT*Nn*Dd];         // u = W @ v (fp32)
static __device__ float g_F [2*HT*Nn*Ee];         // f1, f2  [r][n][e]
static __device__ __nv_bfloat16 g_WBh[Dd*Dd];     // W[:,T-1]^T as [N=1024][K=1024] bf16 hi
static __device__ __nv_bfloat16 g_WBl[Dd*Dd];     // lo
static __device__ float g_HL[Nn*Ee*Dd];           // h_last (pre-mask) (110 MB)

__device__ __forceinline__ void split2(float x, float y, __nv_bfloat162* ph, __nv_bfloat162* pl) {
    __nv_bfloat162 h, l;
    h.x = __float2bfloat16(x);
    h.y = __float2bfloat16(y);
    l.x = __float2bfloat16(x - __bfloat162float(h.x));
    l.y = __float2bfloat16(y - __bfloat162float(h.y));
    *ph = h; *pl = l;
}

// ---------------- K1: concat x (vectorized, bf16 hi/lo only) ----------------
__global__ void k_concat(const float* __restrict__ q, const float* __restrict__ para,
                         const float* __restrict__ sent, const float* __restrict__ ent) {
    int idx = (blockIdx.x * blockDim.x + threadIdx.x) * 4;
    if (idx >= Nn*Ee*Dd) return;
    int d  = idx & (Dd-1);
    int ne = idx >> 10;
    int e  = ne % Ee;
    int n  = ne / Ee;
    const float* src;
    if (e == 0)              src = q    + (size_t)n*Dd + d;
    else if (e < 1+Pp)       src = para + (size_t)(n*Pp  + (e-1))*Dd + d;
    else if (e < 1+Pp+Sr)    src = sent + (size_t)(n*Sr  + (e-1-Pp))*Dd + d;
    else                     src = ent  + (size_t)(n*Enn + (e-1-Pp-Sr))*Dd + d;
    float4 v = *(const float4*)(src);
    __nv_bfloat162 h01, h23, l01, l23;
    split2(v.x, v.y, &h01, &l01);
    split2(v.z, v.w, &h23, &l23);
    ((__nv_bfloat162*)(g_Xh + idx))[0] = h01;
    ((__nv_bfloat162*)(g_Xh + idx))[1] = h23;
    ((__nv_bfloat162*)(g_Xl + idx))[0] = l01;
    ((__nv_bfloat162*)(g_Xl + idx))[1] = l23;
}

__global__ void k_mask(const float* __restrict__ pm, const float* __restrict__ sm_,
                       const float* __restrict__ em) {
    int idx = blockIdx.x * blockDim.x + threadIdx.x;
    if (idx >= Nn*Ee) return;
    int e = idx % Ee, n = idx / Ee;
    float v;
    if (e == 0)            v = 1.f;
    else if (e < 1+Pp)     v = pm[n*Pp  + e-1];
    else if (e < 1+Pp+Sr)  v = sm_[n*Sr + e-1-Pp];
    else                   v = em[n*Enn + e-1-Pp-Sr];
    g_mask[idx] = v;
}

__global__ void k_compact_reset() {
    if (threadIdx.x == 0 && blockIdx.x == 0) g_nactive = 0;
}
__global__ void k_compact() {
    int idx = blockIdx.x * blockDim.x + threadIdx.x;
    if (idx >= Nn*Ee) return;
    if (g_mask[idx] > 0.f) {
        int pos = atomicAdd(&g_nactive, 1);
        g_rowidx[pos] = idx;
    }
}

__global__ void k_split_q(const float* __restrict__ q) {
    int idx = blockIdx.x * blockDim.x + threadIdx.x;
    if (idx >= Nn*Dd) return;
    float v = q[idx];
    __nv_bfloat16 hi = __float2bfloat16(v);
    g_qh[idx] = hi;
    g_ql[idx] = __float2bfloat16(v - __bfloat162float(hi));
}

// transpose+split qW1: [ht][k=1024][n=256] -> [ht][n=256][k=1024]
__global__ void k_tsplit_qw1(const float* __restrict__ qW1) {
    __shared__ float t[32][33];
    int ht = blockIdx.z;
    int k0 = blockIdx.x*32, n0 = blockIdx.y*32;
    int tx = threadIdx.x, ty = threadIdx.y;     // 32x8
    const float* src = qW1 + (size_t)ht*Dd*256;
    #pragma unroll
    for (int j = 0; j < 4; j++)
        t[ty+8*j][tx] = src[(size_t)(k0+ty+8*j)*256 + n0 + tx];
    __syncthreads();
    #pragma unroll
    for (int j = 0; j < 4; j++) {
        int nrow = n0 + ty + 8*j;
        int kcol = k0 + tx;
        float v = t[tx][ty+8*j];
        __nv_bfloat16 hi = __float2bfloat16(v);
        size_t o = (size_t)ht*256*Dd + (size_t)nrow*Dd + kcol;
        g_q1h[o] = hi;
        g_q1l[o] = __float2bfloat16(v - __bfloat162float(hi));
    }
}

// transpose+split qW2: [ht][k=256][n=256] -> [ht][n=256][k=256]
__global__ void k_tsplit_qw2(const float* __restrict__ qW2) {
    __shared__ float t[32][33];
    int ht = blockIdx.z;
    int k0 = blockIdx.x*32, n0 = blockIdx.y*32;
    int tx = threadIdx.x, ty = threadIdx.y;     // 32x8
    const float* src = qW2 + (size_t)ht*256*256;
    #pragma unroll
    for (int j = 0; j < 4; j++)
        t[ty+8*j][tx] = src[(size_t)(k0+ty+8*j)*256 + n0 + tx];
    __syncthreads();
    #pragma unroll
    for (int j = 0; j < 4; j++) {
        int nrow = n0 + ty + 8*j;
        int kcol = k0 + tx;
        float v = t[tx][ty+8*j];
        __nv_bfloat16 hi = __float2bfloat16(v);
        size_t o = (size_t)ht*256*256 + (size_t)nrow*256 + kcol;
        g_q2h[o] = hi;
        g_q2l[o] = __float2bfloat16(v - __bfloat162float(hi));
    }
}

// ---------------- shared mma bits ----------------
#define HLP 72
#define HL_TILE_ELEMS (128*HLP)
#define HL_SMEM_BYTES (4*HL_TILE_ELEMS*2)
#define HL_IDX_BYTES 1024
#define HL_DB_SMEM_BYTES (HL_IDX_BYTES + 8*HL_TILE_ELEMS*2)

__device__ __forceinline__ void mma16816(float* c, const uint32_t* a, uint32_t b0, uint32_t b1) {
    asm volatile(
        "mma.sync.aligned.m16n8k16.row.col.f32.bf16.bf16.f32 "
        "{%0,%1,%2,%3}, {%4,%5,%6,%7}, {%8,%9}, {%0,%1,%2,%3};"
        : "+f"(c[0]), "+f"(c[1]), "+f"(c[2]), "+f"(c[3])
        : "r"(a[0]), "r"(a[1]), "r"(a[2]), "r"(a[3]), "r"(b0), "r"(b1));
}

__device__ __forceinline__ void cp16(void* dst, const void* src) {
    uint32_t d = (uint32_t)__cvta_generic_to_shared(dst);
    asm volatile("cp.async.ca.shared.global [%0], [%1], 16;" :: "r"(d), "l"(src));
}
#define CP_COMMIT() asm volatile("cp.async.commit_group;")
#define CP_WAIT1()  asm volatile("cp.async.wait_group 1;")
#define CP_WAIT0()  asm volatile("cp.async.wait_group 0;")

// ---------------- K2a: R = relu(q @ qW1[ht]^T) via mma clone (round-9 proven) ----------------
__global__ __launch_bounds__(256) void k_qw1_mma() {
    extern __shared__ __nv_bfloat16 sm[];
    __nv_bfloat16* sAh = sm;
    __nv_bfloat16* sAl = sm + HL_TILE_ELEMS;
    __nv_bfloat16* sBh = sm + 2*HL_TILE_ELEMS;
    __nv_bfloat16* sBl = sm + 3*HL_TILE_ELEMS;
    int tid = threadIdx.x;
    int warp = tid >> 5, lane = tid & 31;
    int wm = warp & 3, wn = warp >> 2;
    int g = lane >> 2, tg = lane & 3;
    int n0 = blockIdx.x * 128;
    int m0 = blockIdx.y * 128;
    int ht = blockIdx.z;

    const __nv_bfloat16* Ahb = g_qh + (size_t)m0 * Dd;
    const __nv_bfloat16* Alb = g_ql + (size_t)m0 * Dd;
    const __nv_bfloat16* Bhb = g_q1h + (size_t)ht*256*Dd + (size_t)n0 * Dd;
    const __nv_bfloat16* Blb = g_q1l + (size_t)ht*256*Dd + (size_t)n0 * Dd;

    float acc[2][8][4];
    #pragma unroll
    for (int i=0;i<2;i++)
        #pragma unroll
        for (int j=0;j<8;j++)
            #pragma unroll
            for (int q=0;q<4;q++) acc[i][j][q] = 0.f;

    int sr = tid >> 3;
    int sc = (tid & 7) * 8;

    for (int kc = 0; kc < 16; kc++) {
        #pragma unroll
        for (int it = 0; it < 4; it++) {
            int r = sr + it*32;
            size_t go = (size_t)r * Dd + kc*64 + sc;
            int so = r * HLP + sc;
            *(uint4*)(sAh + so) = *(const uint4*)(Ahb + go);
            *(uint4*)(sAl + so) = *(const uint4*)(Alb + go);
            *(uint4*)(sBh + so) = *(const uint4*)(Bhb + go);
            *(uint4*)(sBl + so) = *(const uint4*)(Blb + go);
        }
        __syncthreads();
        #pragma unroll
        for (int ks = 0; ks < 4; ks++) {
            int kb = ks * 16;
            uint32_t ah[2][4], al[2][4];
            #pragma unroll
            for (int mi = 0; mi < 2; mi++) {
                int row = wm*32 + mi*16 + g;
                const __nv_bfloat16* p0 = sAh + row*HLP + kb + tg*2;
                const __nv_bfloat16* p1 = sAh + (row+8)*HLP + kb + tg*2;
                ah[mi][0] = *(const uint32_t*)(p0);
                ah[mi][1] = *(const uint32_t*)(p1);
                ah[mi][2] = *(const uint32_t*)(p0 + 8);
                ah[mi][3] = *(const uint32_t*)(p1 + 8);
                const __nv_bfloat16* q0 = sAl + row*HLP + kb + tg*2;
                const __nv_bfloat16* q1 = sAl + (row+8)*HLP + kb + tg*2;
                al[mi][0] = *(const uint32_t*)(q0);
                al[mi][1] = *(const uint32_t*)(q1);
                al[mi][2] = *(const uint32_t*)(q0 + 8);
                al[mi][3] = *(const uint32_t*)(q1 + 8);
            }
            #pragma unroll
            for (int nj = 0; nj < 8; nj++) {
                int col = wn*64 + nj*8 + g;
                const __nv_bfloat16* pb = sBh + col*HLP + kb + tg*2;
                const __nv_bfloat16* pl = sBl + col*HLP + kb + tg*2;
                uint32_t bh0 = *(const uint32_t*)(pb);
                uint32_t bh1 = *(const uint32_t*)(pb + 8);
                uint32_t bl0 = *(const uint32_t*)(pl);
                uint32_t bl1 = *(const uint32_t*)(pl + 8);
                #pragma unroll
                for (int mi = 0; mi < 2; mi++) {
                    mma16816(acc[mi][nj], ah[mi], bh0, bh1);
                    mma16816(acc[mi][nj], ah[mi], bl0, bl1);
                    mma16816(acc[mi][nj], al[mi], bh0, bh1);
                }
            }
        }
        __syncthreads();
    }

    float* Cb = g_R + (size_t)ht*Nn*256;
    #pragma unroll
    for (int mi = 0; mi < 2; mi++) {
        int row = m0 + wm*32 + mi*16 + g;
        #pragma unroll
        for (int nj = 0; nj < 8; nj++) {
            int col = n0 + wn*64 + nj*8 + tg*2;
            *(float2*)(&Cb[(size_t)row*256 + col]) =
                make_float2(fmaxf(acc[mi][nj][0], 0.f), fmaxf(acc[mi][nj][1], 0.f));
            *(float2*)(&Cb[(size_t)(row+8)*256 + col]) =
                make_float2(fmaxf(acc[mi][nj][2], 0.f), fmaxf(acc[mi][nj][3], 0.f));
        }
    }
}

// ---------------- K2b: V = sigmoid(R @ qW2^T) * a via mma clone (KCHUNKS=4) ----------------
__global__ __launch_bounds__(256) void k_qw2_mma(const float* __restrict__ a_in) {
    extern __shared__ __nv_bfloat16 sm[];
    __nv_bfloat16* sAh = sm;
    __nv_bfloat16* sAl = sm + HL_TILE_ELEMS;
    __nv_bfloat16* sBh = sm + 2*HL_TILE_ELEMS;
    __nv_bfloat16* sBl = sm + 3*HL_TILE_ELEMS;
    int tid = threadIdx.x;
    int warp = tid >> 5, lane = tid & 31;
    int wm = warp & 3, wn = warp >> 2;
    int g = lane >> 2, tg = lane & 3;
    int n0 = blockIdx.x * 128;
    int m0 = blockIdx.y * 128;
    int ht = blockIdx.z;

    const float* Ab = g_R + (size_t)ht*Nn*256 + (size_t)m0*256;     // fp32, split inline
    const __nv_bfloat16* Bhb = g_q2h + (size_t)ht*256*256 + (size_t)n0 * 256;
    const __nv_bfloat16* Blb = g_q2l + (size_t)ht*256*256 + (size_t)n0 * 256;

    float acc[2][8][4];
    #pragma unroll
    for (int i=0;i<2;i++)
        #pragma unroll
        for (int j=0;j<8;j++)
            #pragma unroll
            for (int q=0;q<4;q++) acc[i][j][q] = 0.f;

    int sr = tid >> 3;
    int sc = (tid & 7) * 8;

    for (int kc = 0; kc < 4; kc++) {
        #pragma unroll
        for (int it = 0; it < 4; it++) {
            int r = sr + it*32;
            const float* pa = Ab + (size_t)r * 256 + kc*64 + sc;
            size_t gb = (size_t)r * 256 + kc*64 + sc;
            int so = r * HLP + sc;
            #pragma unroll
            for (int jj = 0; jj < 8; jj += 4) {
                float4 va = *(const float4*)(pa + jj);
                split2(va.x, va.y, (__nv_bfloat162*)(sAh + so + jj),     (__nv_bfloat162*)(sAl + so + jj));
                split2(va.z, va.w, (__nv_bfloat162*)(sAh + so + jj + 2), (__nv_bfloat162*)(sAl + so + jj + 2));
            }
            *(uint4*)(sBh + so) = *(const uint4*)(Bhb + gb);
            *(uint4*)(sBl + so) = *(const uint4*)(Blb + gb);
        }
        __syncthreads();
        #pragma unroll
        for (int ks = 0; ks < 4; ks++) {
            int kb = ks * 16;
            uint32_t ah[2][4], al[2][4];
            #pragma unroll
            for (int mi = 0; mi < 2; mi++) {
                int row = wm*32 + mi*16 + g;
                const __nv_bfloat16* p0 = sAh + row*HLP + kb + tg*2;
                const __nv_bfloat16* p1 = sAh + (row+8)*HLP + kb + tg*2;
                ah[mi][0] = *(const uint32_t*)(p0);
                ah[mi][1] = *(const uint32_t*)(p1);
                ah[mi][2] = *(const uint32_t*)(p0 + 8);
                ah[mi][3] = *(const uint32_t*)(p1 + 8);
                const __nv_bfloat16* q0 = sAl + row*HLP + kb + tg*2;
                const __nv_bfloat16* q1 = sAl + (row+8)*HLP + kb + tg*2;
                al[mi][0] = *(const uint32_t*)(q0);
                al[mi][1] = *(const uint32_t*)(q1);
                al[mi][2] = *(const uint32_t*)(q0 + 8);
                al[mi][3] = *(const uint32_t*)(q1 + 8);
            }
            #pragma unroll
            for (int nj = 0; nj < 8; nj++) {
                int col = wn*64 + nj*8 + g;
                const __nv_bfloat16* pb = sBh + col*HLP + kb + tg*2;
                const __nv_bfloat16* pl = sBl + col*HLP + kb + tg*2;
                uint32_t bh0 = *(const uint32_t*)(pb);
                uint32_t bh1 = *(const uint32_t*)(pb + 8);
                uint32_t bl0 = *(const uint32_t*)(pl);
                uint32_t bl1 = *(const uint32_t*)(pl + 8);
                #pragma unroll
                for (int mi = 0; mi < 2; mi++) {
                    mma16816(acc[mi][nj], ah[mi], bh0, bh1);
                    mma16816(acc[mi][nj], ah[mi], bl0, bl1);
                    mma16816(acc[mi][nj], al[mi], bh0, bh1);
                }
            }
        }
        __syncthreads();
    }

    const float* av = a_in + ht*256;
    #pragma unroll
    for (int mi = 0; mi < 2; mi++) {
        #pragma unroll
        for (int nj = 0; nj < 8; nj++) {
            #pragma unroll
            for (int q = 0; q < 4; q++) {
                int row = m0 + wm*32 + mi*16 + g + (q >= 2 ? 8 : 0);
                int col = n0 + wn*64 + nj*8 + tg*2 + (q & 1);
                float s = 1.f / (1.f + __expf(-acc[mi][nj][q]));
                float val = s * av[col];
                int r = (col < DHd) ? ht : (HT + ht);
                int k = col & (DHd-1);
                g_V[((size_t)r*Nn + row)*DHd + k] = val;
            }
        }
    }
}

// ---------------- K3: U[r] = V[r] @ W[ht]^T via mma (round-8 proven clone) ----------------
__global__ __launch_bounds__(256) void k_u_mma(const float* __restrict__ W) {
    extern __shared__ __nv_bfloat16 sm[];
    __nv_bfloat16* sAh = sm;
    __nv_bfloat16* sAl = sm + HL_TILE_ELEMS;
    __nv_bfloat16* sBh = sm + 2*HL_TILE_ELEMS;
    __nv_bfloat16* sBl = sm + 3*HL_TILE_ELEMS;
    int tid = threadIdx.x;
    int warp = tid >> 5, lane = tid & 31;
    int wm = warp & 3, wn = warp >> 2;
    int g = lane >> 2, tg = lane & 3;
    int n0 = blockIdx.x * 128;
    int m0 = blockIdx.y * 128;
    int r  = blockIdx.z;
    int ht = r % HT;

    const float* Ab = g_V + (size_t)r*Nn*DHd + (size_t)m0*DHd;
    const float* Bb = W   + (size_t)ht*Dd*DHd + (size_t)n0*DHd;

    float acc[2][8][4];
    #pragma unroll
    for (int i=0;i<2;i++)
        #pragma unroll
        for (int j=0;j<8;j++)
            #pragma unroll
            for (int q=0;q<4;q++) acc[i][j][q] = 0.f;

    int sr = tid >> 3;
    int sc = (tid & 7) * 8;

    for (int kc = 0; kc < 2; kc++) {
        #pragma unroll
        for (int it = 0; it < 4; it++) {
            int rr = sr + it*32;
            const float* pa = Ab + (size_t)rr*DHd + kc*64 + sc;
            const float* pb = Bb + (size_t)rr*DHd + kc*64 + sc;
            int so = rr * HLP + sc;
            #pragma unroll
            for (int jj = 0; jj < 8; jj += 4) {
                float4 va = *(const float4*)(pa + jj);
                split2(va.x, va.y, (__nv_bfloat162*)(sAh + so + jj),     (__nv_bfloat162*)(sAl + so + jj));
                split2(va.z, va.w, (__nv_bfloat162*)(sAh + so + jj + 2), (__nv_bfloat162*)(sAl + so + jj + 2));
                float4 vb = *(const float4*)(pb + jj);
                split2(vb.x, vb.y, (__nv_bfloat162*)(sBh + so + jj),     (__nv_bfloat162*)(sBl + so + jj));
                split2(vb.z, vb.w, (__nv_bfloat162*)(sBh + so + jj + 2), (__nv_bfloat162*)(sBl + so + jj + 2));
            }
        }
        __syncthreads();
        #pragma unroll
        for (int ks = 0; ks < 4; ks++) {
            int kb = ks * 16;
            uint32_t ah[2][4], al[2][4];
            #pragma unroll
            for (int mi = 0; mi < 2; mi++) {
                int row = wm*32 + mi*16 + g;
                const __nv_bfloat16* p0 = sAh + row*HLP + kb + tg*2;
                const __nv_bfloat16* p1 = sAh + (row+8)*HLP + kb + tg*2;
                ah[mi][0] = *(const uint32_t*)(p0);
                ah[mi][1] = *(const uint32_t*)(p1);
                ah[mi][2] = *(const uint32_t*)(p0 + 8);
                ah[mi][3] = *(const uint32_t*)(p1 + 8);
                const __nv_bfloat16* q0 = sAl + row*HLP + kb + tg*2;
                const __nv_bfloat16* q1 = sAl + (row+8)*HLP + kb + tg*2;
                al[mi][0] = *(const uint32_t*)(q0);
                al[mi][1] = *(const uint32_t*)(q1);
                al[mi][2] = *(const uint32_t*)(q0 + 8);
                al[mi][3] = *(const uint32_t*)(q1 + 8);
            }
            #pragma unroll
            for (int nj = 0; nj < 8; nj++) {
                int col = wn*64 + nj*8 + g;
                const __nv_bfloat16* pb = sBh + col*HLP + kb + tg*2;
                const __nv_bfloat16* pl = sBl + col*HLP + kb + tg*2;
                uint32_t bh0 = *(const uint32_t*)(pb);
                uint32_t bh1 = *(const uint32_t*)(pb + 8);
                uint32_t bl0 = *(const uint32_t*)(pl);
                uint32_t bl1 = *(const uint32_t*)(pl + 8);
                #pragma unroll
                for (int mi = 0; mi < 2; mi++) {
                    mma16816(acc[mi][nj], ah[mi], bh0, bh1);
                    mma16816(acc[mi][nj], ah[mi], bl0, bl1);
                    mma16816(acc[mi][nj], al[mi], bh0, bh1);
                }
            }
        }
        __syncthreads();
    }

    #pragma unroll
    for (int mi = 0; mi < 2; mi++) {
        int row = m0 + wm*32 + mi*16 + g;
        #pragma unroll
        for (int nj = 0; nj < 8; nj++) {
            int col = n0 + wn*64 + nj*8 + tg*2;
            *(float2*)(&g_U[(size_t)r*Nn*Dd + (size_t)row*Dd + col])     = make_float2(acc[mi][nj][0], acc[mi][nj][1]);
            *(float2*)(&g_U[(size_t)r*Nn*Dd + (size_t)(row+8)*Dd + col]) = make_float2(acc[mi][nj][2], acc[mi][nj][3]);
        }
    }
}

// ---------------- K4: F via mma (round-9 proven) ----------------
__global__ __launch_bounds__(256) void k_f_mma() {
    extern __shared__ __nv_bfloat16 sm[];
    __nv_bfloat16* sAh = sm;
    __nv_bfloat16* sAl = sm + HL_TILE_ELEMS;
    __nv_bfloat16* sBh = sm + 2*HL_TILE_ELEMS;
    __nv_bfloat16* sBl = sm + 3*HL_TILE_ELEMS;
    int n = blockIdx.x;
    int tid = threadIdx.x;
    int warp = tid >> 5, lane = tid & 31;
    int wm = warp & 3, wn = warp >> 2;
    int g = lane >> 2, tg = lane & 3;

    float acc[2][3][4];
    #pragma unroll
    for (int i=0;i<2;i++)
        #pragma unroll
        for (int j=0;j<3;j++)
            #pragma unroll
            for (int q=0;q<4;q++) acc[i][j][q] = 0.f;

    int sr = tid >> 3;
    int sc = (tid & 7) * 8;
    const __nv_bfloat16* Ahb = g_Xh + (size_t)n * Ee * Dd;
    const __nv_bfloat16* Alb = g_Xl + (size_t)n * Ee * Dd;

    for (int kc = 0; kc < 16; kc++) {
        #pragma unroll
        for (int it = 0; it < 4; it++) {
            int r = sr + it*32;
            int rc = (r < Ee) ? r : (Ee-1);
            size_t go = (size_t)rc * Dd + kc*64 + sc;
            int so = r * HLP + sc;
            *(uint4*)(sAh + so) = *(const uint4*)(Ahb + go);
            *(uint4*)(sAl + so) = *(const uint4*)(Alb + go);
        }
        for (int i = tid; i < 384; i += 256) {
            int r = i >> 3, c = (i & 7) * 8;
            const float* pb = g_U + (size_t)r*(Nn*Dd) + (size_t)n*Dd + kc*64 + c;
            int so = r * HLP + c;
            #pragma unroll
            for (int jj = 0; jj < 8; jj += 4) {
                float4 vb = *(const float4*)(pb + jj);
                split2(vb.x, vb.y, (__nv_bfloat162*)(sBh + so + jj),     (__nv_bfloat162*)(sBl + so + jj));
                split2(vb.z, vb.w, (__nv_bfloat162*)(sBh + so + jj + 2), (__nv_bfloat162*)(sBl + so + jj + 2));
            }
        }
        __syncthreads();
        #pragma unroll
        for (int ks = 0; ks < 4; ks++) {
            int kb = ks * 16;
            uint32_t ah[2][4], al[2][4];
            #pragma unroll
            for (int mi = 0; mi < 2; mi++) {
                int row = wm*32 + mi*16 + g;
                const __nv_bfloat16* p0 = sAh + row*HLP + kb + tg*2;
                const __nv_bfloat16* p1 = sAh + (row+8)*HLP + kb + tg*2;
                ah[mi][0] = *(const uint32_t*)(p0);
                ah[mi][1] = *(const uint32_t*)(p1);
                ah[mi][2] = *(const uint32_t*)(p0 + 8);
                ah[mi][3] = *(const uint32_t*)(p1 + 8);
                const __nv_bfloat16* q0 = sAl + row*HLP + kb + tg*2;
                const __nv_bfloat16* q1 = sAl + (row+8)*HLP + kb + tg*2;
                al[mi][0] = *(const uint32_t*)(q0);
                al[mi][1] = *(const uint32_t*)(q1);
                al[mi][2] = *(const uint32_t*)(q0 + 8);
                al[mi][3] = *(const uint32_t*)(q1 + 8);
            }
            #pragma unroll
            for (int nj = 0; nj < 3; nj++) {
                int col = wn*24 + nj*8 + g;
                const __nv_bfloat16* pb = sBh + col*HLP + kb + tg*2;
                const __nv_bfloat16* pl = sBl + col*HLP + kb + tg*2;
                uint32_t bh0 = *(const uint32_t*)(pb);
                uint32_t bh1 = *(const uint32_t*)(pb + 8);
                uint32_t bl0 = *(const uint32_t*)(pl);
                uint32_t bl1 = *(const uint32_t*)(pl + 8);
                #pragma unroll
                for (int mi = 0; mi < 2; mi++) {
                    mma16816(acc[mi][nj], ah[mi], bh0, bh1);
                    mma16816(acc[mi][nj], ah[mi], bl0, bl1);
                    mma16816(acc[mi][nj], al[mi], bh0, bh1);
                }
            }
        }
        __syncthreads();
    }

    #pragma unroll
    for (int mi = 0; mi < 2; mi++) {
        int e0 = wm*32 + mi*16 + g;
        #pragma unroll
        for (int nj = 0; nj < 3; nj++) {
            int r = wn*24 + nj*8 + tg*2;
            if (e0 < Ee) {
                g_F[(size_t)r*Nn*Ee + n*Ee + e0]     = acc[mi][nj][0];
                g_F[(size_t)(r+1)*Nn*Ee + n*Ee + e0] = acc[mi][nj][1];
            }
            if (e0 + 8 < Ee) {
                g_F[(size_t)r*Nn*Ee + n*Ee + e0 + 8]     = acc[mi][nj][2];
                g_F[(size_t)(r+1)*Nn*Ee + n*Ee + e0 + 8] = acc[mi][nj][3];
            }
        }
    }
}

// ---------------- K5a: repack W[:, T-1]^T into [N=1024][K=1024] bf16 hi/lo ----
__global__ void k_repack_bf(const float* __restrict__ W) {
    int idx = blockIdx.x * blockDim.x + threadIdx.x;
    if (idx >= Dd*Dd) return;
    int d = idx & 1023, col = idx >> 10;         // out[col][d]
    int h = col >> 7, k = col & 127;
    float v = W[((size_t)(h*Tt + (Tt-1))*Dd + d)*DHd + k];
    __nv_bfloat16 hi = __float2bfloat16(v);
    g_WBh[idx] = hi;
    g_WBl[idx] = __float2bfloat16(v - __bfloat162float(hi));
}

// ---------------- K5b: HL = X @ WB^T, ACTIVE ROWS ONLY (round-12 proven) ----
__global__ __launch_bounds__(256) void k_hl_mma() {
    extern __shared__ char smraw[];
    int* ridx = (int*)smraw;
    __nv_bfloat16* smbuf = (__nv_bfloat16*)(smraw + HL_IDX_BYTES);
    const int TB = 4*HL_TILE_ELEMS;
    int tid = threadIdx.x;
    int warp = tid >> 5, lane = tid & 31;
    int wm = warp & 3, wn = warp >> 2;
    int g = lane >> 2, tg = lane & 3;
    int n0 = blockIdx.x * 128;
    int mbase = blockIdx.y * 128;

    int count = g_nactive;
    if (mbase >= count) return;
    if (tid < 128) {
        int li = mbase + tid;
        ridx[tid] = g_rowidx[li < count ? li : (count-1)];
    }
    __syncthreads();

    const __nv_bfloat16* Bh0 = g_WBh + (size_t)n0 * Dd;
    const __nv_bfloat16* Bl0 = g_WBl + (size_t)n0 * Dd;

    float acc[2][8][4];
    #pragma unroll
    for (int i=0;i<2;i++)
        #pragma unroll
        for (int j=0;j<8;j++)
            #pragma unroll
            for (int q=0;q<4;q++) acc[i][j][q] = 0.f;

    int sr = tid >> 3;
    int sc = (tid & 7) * 8;

    #define HL_ISSUE(kc, b) do {                                                   \
        __nv_bfloat16* base = smbuf + (b)*TB;                                      \
        _Pragma("unroll")                                                          \
        for (int it = 0; it < 4; it++) {                                           \
            int r = sr + it*32;                                                    \
            size_t ga = (size_t)ridx[r] * Dd + (kc)*64 + sc;                       \
            size_t gb = (size_t)r * Dd + (kc)*64 + sc;                             \
            int so = r * HLP + sc;                                                 \
            cp16(base + so,                     g_Xh + ga);                        \
            cp16(base + HL_TILE_ELEMS + so,     g_Xl + ga);                        \
            cp16(base + 2*HL_TILE_ELEMS + so,   Bh0 + gb);                         \
            cp16(base + 3*HL_TILE_ELEMS + so,   Bl0 + gb);                         \
        }                                                                          \
        CP_COMMIT();                                                               \
    } while (0)

    HL_ISSUE(0, 0);
    for (int kc = 0; kc < 16; kc++) {
        if (kc < 15) { HL_ISSUE(kc+1, (kc+1)&1); CP_WAIT1(); }
        else         { CP_WAIT0(); }
        __syncthreads();
        __nv_bfloat16* base = smbuf + (kc&1)*TB;
        __nv_bfloat16* sAh = base;
        __nv_bfloat16* sAl = base + HL_TILE_ELEMS;
        __nv_bfloat16* sBh = base + 2*HL_TILE_ELEMS;
        __nv_bfloat16* sBl = base + 3*HL_TILE_ELEMS;
        #pragma unroll
        for (int ks = 0; ks < 4; ks++) {
            int kb = ks * 16;
            uint32_t ah[2][4], al[2][4];
            #pragma unroll
            for (int mi = 0; mi < 2; mi++) {
                int row = wm*32 + mi*16 + g;
                const __nv_bfloat16* p0 = sAh + row*HLP + kb + tg*2;
                const __nv_bfloat16* p1 = sAh + (row+8)*HLP + kb + tg*2;
                ah[mi][0] = *(const uint32_t*)(p0);
                ah[mi][1] = *(const uint32_t*)(p1);
                ah[mi][2] = *(const uint32_t*)(p0 + 8);
                ah[mi][3] = *(const uint32_t*)(p1 + 8);
                const __nv_bfloat16* q0 = sAl + row*HLP + kb + tg*2;
                const __nv_bfloat16* q1 = sAl + (row+8)*HLP + kb + tg*2;
                al[mi][0] = *(const uint32_t*)(q0);
                al[mi][1] = *(const uint32_t*)(q1);
                al[mi][2] = *(const uint32_t*)(q0 + 8);
                al[mi][3] = *(const uint32_t*)(q1 + 8);
            }
            #pragma unroll
            for (int nj = 0; nj < 8; nj++) {
                int col = wn*64 + nj*8 + g;
                const __nv_bfloat16* pb = sBh + col*HLP + kb + tg*2;
                const __nv_bfloat16* pl = sBl + col*HLP + kb + tg*2;
                uint32_t bh0 = *(const uint32_t*)(pb);
                uint32_t bh1 = *(const uint32_t*)(pb + 8);
                uint32_t bl0 = *(const uint32_t*)(pl);
                uint32_t bl1 = *(const uint32_t*)(pl + 8);
                #pragma unroll
                for (int mi = 0; mi < 2; mi++) {
                    mma16816(acc[mi][nj], ah[mi], bh0, bh1);
                    mma16816(acc[mi][nj], ah[mi], bl0, bl1);
                    mma16816(acc[mi][nj], al[mi], bh0, bh1);
                }
            }
        }
        __syncthreads();
    }
    #undef HL_ISSUE

    #pragma unroll
    for (int mi = 0; mi < 2; mi++) {
        int rl = wm*32 + mi*16 + g;
        size_t row0 = (size_t)ridx[rl];
        size_t row1 = (size_t)ridx[rl + 8];
        #pragma unroll
        for (int nj = 0; nj < 8; nj++) {
            int col = n0 + wn*64 + nj*8 + tg*2;
            *(float2*)(&g_HL[row0 * Dd + col]) = make_float2(acc[mi][nj][0], acc[mi][nj][1]);
            *(float2*)(&g_HL[row1 * Dd + col]) = make_float2(acc[mi][nj][2], acc[mi][nj][3]);
        }
    }
}

// ---------------- K6: score + softmax + TC aggregate, 2-phase B (2 blocks/SM) ----------
#define K6P 120
#define K6_A_TILE (128*K6P)
#define K6_B_TILE (64*K6P)
#define K6_F_OFF 0
#define K6_BF_OFF 2560
#define K6_SMEM_BYTES (K6_BF_OFF + (2*K6_A_TILE + 2*K6_B_TILE)*2)   // 94720

__device__ __forceinline__ float k6_score(int t, const float* f1s, const float* f2s, int i, int j) {
    if (t > 0) {
        float v = f1s[(t-1)*Ee + i] + f2s[(t-1)*Ee + j];
        return v > 0.f ? v : 0.2f*v;
    }
    return NEGV;
}

__global__ __launch_bounds__(256, 2) void k6_attn(const int* __restrict__ adj, float* __restrict__ out) {
    int h = blockIdx.x, n = blockIdx.y;
    extern __shared__ char smraw[];
    float* f1s = (float*)(smraw + K6_F_OFF);
    float* f2s = f1s + Tt*Ee;
    __nv_bfloat16* sAh = (__nv_bfloat16*)(smraw + K6_BF_OFF);
    __nv_bfloat16* sAl = sAh + K6_A_TILE;
    __nv_bfloat16* sBh = sAl + K6_A_TILE;
    __nv_bfloat16* sBl = sBh + K6_B_TILE;
    int tid = threadIdx.x;
    int w = tid >> 5, lane = tid & 31;

    // zero all bf16 tiles (covers pads)
    {
        uint4 z = make_uint4(0,0,0,0);
        uint4* p = (uint4*)(smraw + K6_BF_OFF);
        for (int i = tid; i < ((2*K6_A_TILE + 2*K6_B_TILE)*2)/16; i += 256) p[i] = z;
    }
    for (int i = tid; i < Tt*Ee; i += 256) {
        int t = i / Ee, e = i % Ee;
        f1s[i] = g_F[(size_t)(h*Tt+t)*Nn*Ee + n*Ee + e];
        f2s[i] = g_F[(size_t)HT*Nn*Ee + (size_t)(h*Tt+t)*Nn*Ee + n*Ee + e];
    }
    __syncthreads();

    // coef phase: A[i][j]
    const int* adjn = adj + n*Ee*Ee;
    for (int ig = 0; ig < 14; ig++) {
        int i = ig*8 + w;
        if (i < Ee) {
            const int* arow = adjn + i*Ee;
            float s0 = k6_score(arow[lane],    f1s, f2s, i, lane);
            float s1 = k6_score(arow[lane+32], f1s, f2s, i, lane+32);
            float s2 = k6_score(arow[lane+64], f1s, f2s, i, lane+64);
            float s3 = (lane < 9) ? k6_score(arow[lane+96], f1s, f2s, i, lane+96) : -INFINITY;
            float m = fmaxf(fmaxf(s0, s1), fmaxf(s2, s3));
            #pragma unroll
            for (int o = 16; o > 0; o >>= 1) m = fmaxf(m, __shfl_xor_sync(0xffffffffu, m, o));
            float p0 = __expf(s0 - m), p1 = __expf(s1 - m), p2 = __expf(s2 - m);
            float p3 = (lane < 9) ? __expf(s3 - m) : 0.f;
            float sum = p0 + p1 + p2 + p3;
            #pragma unroll
            for (int o = 16; o > 0; o >>= 1) sum += __shfl_xor_sync(0xffffffffu, sum, o);
            float inv = 1.f / sum;
            float c0 = p0*inv, c1 = p1*inv, c2 = p2*inv;
            __nv_bfloat16 hi;
            hi = __float2bfloat16(c0);
            sAh[i*K6P + lane] = hi;      sAl[i*K6P + lane]      = __float2bfloat16(c0 - __bfloat162float(hi));
            hi = __float2bfloat16(c1);
            sAh[i*K6P + lane + 32] = hi; sAl[i*K6P + lane + 32] = __float2bfloat16(c1 - __bfloat162float(hi));
            hi = __float2bfloat16(c2);
            sAh[i*K6P + lane + 64] = hi; sAl[i*K6P + lane + 64] = __float2bfloat16(c2 - __bfloat162float(hi));
            if (lane < 9) {
                float c3 = p3*inv;
                hi = __float2bfloat16(c3);
                sAh[i*K6P + lane + 96] = hi; sAl[i*K6P + lane + 96] = __float2bfloat16(c3 - __bfloat162float(hi));
            }
        }
    }

    int g = lane >> 2, tg = lane & 3;
    float acc[16][4];
    #pragma unroll
    for (int j = 0; j < 16; j++)
        #pragma unroll
        for (int q = 0; q < 4; q++) acc[j][q] = 0.f;

    const float* mk = g_mask + n*Ee;
    #pragma unroll
    for (int p = 0; p < 2; p++) {
        // B phase p: B[d][j] = HL[j][h*128 + p*64 + d] * mask[j], d in [0,64)
        {
            int d = tid & 63, quarter = tid >> 6;
            const float* hlb = g_HL + (size_t)n*Ee*Dd + h*DHd + p*64 + d;
            for (int j = quarter; j < Ee; j += 4) {
                float v = hlb[(size_t)j*Dd] * mk[j];
                __nv_bfloat16 hi = __float2bfloat16(v);
                sBh[d*K6P + j] = hi;
                sBl[d*K6P + j] = __float2bfloat16(v - __bfloat162float(hi));
            }
        }
        __syncthreads();
        for (int kc = 0; kc < 7; kc++) {
            int kb = kc*16;
            int row = w*16 + g;
            uint32_t ah[4], al[4];
            const __nv_bfloat16* p0 = sAh + row*K6P + kb + tg*2;
            const __nv_bfloat16* p1 = sAh + (row+8)*K6P + kb + tg*2;
            ah[0] = *(const uint32_t*)(p0);
            ah[1] = *(const uint32_t*)(p1);
            ah[2] = *(const uint32_t*)(p0 + 8);
            ah[3] = *(const uint32_t*)(p1 + 8);
            const __nv_bfloat16* q0 = sAl + row*K6P + kb + tg*2;
            const __nv_bfloat16* q1 = sAl + (row+8)*K6P + kb + tg*2;
            al[0] = *(const uint32_t*)(q0);
            al[1] = *(const uint32_t*)(q1);
            al[2] = *(const uint32_t*)(q0 + 8);
            al[3] = *(const uint32_t*)(q1 + 8);
            #pragma unroll
            for (int nj = 0; nj < 8; nj++) {
                int col = nj*8 + g;
                const __nv_bfloat16* pb = sBh + col*K6P + kb + tg*2;
                const __nv_bfloat16* pl = sBl + col*K6P + kb + tg*2;
                uint32_t bh0 = *(const uint32_t*)(pb);
                uint32_t bh1 = *(const uint32_t*)(pb + 8);
                uint32_t bl0 = *(const uint32_t*)(pl);
                uint32_t bl1 = *(const uint32_t*)(pl + 8);
                mma16816(acc[p*8+nj], ah, bh0, bh1);
                mma16816(acc[p*8+nj], ah, bl0, bl1);
                mma16816(acc[p*8+nj], al, bh0, bh1);
            }
        }
        __syncthreads();   // B buffer reuse
    }

    // epilogue: relu + residual (x reconstructed from bf16 hi+lo splits)
    #pragma unroll
    for (int rr = 0; rr < 2; rr++) {
        int i = w*16 + rr*8 + g;
        if (i < Ee) {
            size_t rowo = (size_t)(n*Ee + i)*Dd + h*DHd;
            #pragma unroll
            for (int nj = 0; nj < 16; nj++) {
                int col = nj*8 + tg*2;
                __nv_bfloat162 xh = *(const __nv_bfloat162*)(&g_Xh[rowo + col]);
                __nv_bfloat162 xl = *(const __nv_bfloat162*)(&g_Xl[rowo + col]);
                float x0 = __bfloat162float(xh.x) + __bfloat162float(xl.x);
                float x1 = __bfloat162float(xh.y) + __bfloat162float(xl.y);
                float v0 = fmaxf(acc[nj][rr*2+0], 0.f) + x0;
                float v1 = fmaxf(acc[nj][rr*2+1], 0.f) + x1;
                *(float2*)(&out[rowo + col]) = make_float2(v0, v1);
            }
        }
    }
}

// ---------------- launch (fork-join dual-stream graph) ----------------
extern "C" void kernel_launch(void* const* d_in, const int* in_sizes, int n_in,
                              void* d_out, int out_size) {
    const float* q    = (const float*)d_in[0];
    const float* para = (const float*)d_in[1];
    const float* sent = (const float*)d_in[2];
    const float* ent  = (const float*)d_in[3];
    const float* pm   = (const float*)d_in[4];
    const float* sm_  = (const float*)d_in[5];
    const float* em   = (const float*)d_in[6];
    const int*   adj  = (const int*)  d_in[7];
    const float* W    = (const float*)d_in[8];
    const float* a    = (const float*)d_in[9];
    const float* qW1  = (const float*)d_in[10];
    const float* qW2  = (const float*)d_in[11];
    float* out = (float*)d_out;

    static cudaStream_t sB = nullptr;
    static cudaEvent_t evFork = nullptr, evA1 = nullptr, evB1 = nullptr, evB2 = nullptr;
    if (sB == nullptr) {
        cudaStreamCreateWithFlags(&sB, cudaStreamNonBlocking);
        cudaEventCreateWithFlags(&evFork, cudaEventDisableTiming);
        cudaEventCreateWithFlags(&evA1,   cudaEventDisableTiming);
        cudaEventCreateWithFlags(&evB1,   cudaEventDisableTiming);
        cudaEventCreateWithFlags(&evB2,   cudaEventDisableTiming);
        cudaFuncSetAttribute(k6_attn,   cudaFuncAttributeMaxDynamicSharedMemorySize, K6_SMEM_BYTES);
        cudaFuncSetAttribute(k_hl_mma,  cudaFuncAttributeMaxDynamicSharedMemorySize, HL_DB_SMEM_BYTES);
        cudaFuncSetAttribute(k_u_mma,   cudaFuncAttributeMaxDynamicSharedMemorySize, HL_SMEM_BYTES);
        cudaFuncSetAttribute(k_qw1_mma, cudaFuncAttributeMaxDynamicSharedMemorySize, HL_SMEM_BYTES);
        cudaFuncSetAttribute(k_qw2_mma, cudaFuncAttributeMaxDynamicSharedMemorySize, HL_SMEM_BYTES);
        cudaFuncSetAttribute(k_f_mma,   cudaFuncAttributeMaxDynamicSharedMemorySize, HL_SMEM_BYTES);
    }

    cudaEventRecord(evFork, 0);
    cudaStreamWaitEvent(sB, evFork, 0);

    // ---- stream A (legacy): X-side chain ----
    k_concat<<<(Nn*Ee*Dd/4 + 255)/256, 256>>>(q, para, sent, ent);
    cudaEventRecord(evA1, 0);                       // X splits ready (for f_mma)
    k_mask<<<(Nn*Ee + 255)/256, 256>>>(pm, sm_, em);
    k_compact_reset<<<1, 1>>>();
    k_compact<<<(Nn*Ee + 255)/256, 256>>>();

    // ---- stream B: q-side chain ----
    k_repack_bf<<<(Dd*Dd + 255)/256, 256, 0, sB>>>(W);
    cudaEventRecord(evB1, sB);                      // WB ready (for hl)
    k_split_q<<<(Nn*Dd + 255)/256, 256, 0, sB>>>(q);
    k_tsplit_qw1<<<dim3(32, 8, HT), dim3(32, 8), 0, sB>>>(qW1);
    k_tsplit_qw2<<<dim3(8, 8, HT), dim3(32, 8), 0, sB>>>(qW2);
    k_qw1_mma<<<dim3(2,2,HT), 256, HL_SMEM_BYTES, sB>>>();
    k_qw2_mma<<<dim3(2,2,HT), 256, HL_SMEM_BYTES, sB>>>(a);
    k_u_mma<<<dim3(8,2,2*HT), 256, HL_SMEM_BYTES, sB>>>(W);
    cudaStreamWaitEvent(sB, evA1, 0);               // f needs X splits
    k_f_mma<<<Nn, 256, HL_SMEM_BYTES, sB>>>();
    cudaEventRecord(evB2, sB);

    // ---- stream A: hl (needs concat + compact + repack) then join + k6 ----
    cudaStreamWaitEvent(0, evB1, 0);
    k_hl_mma<<<dim3(8,210), 256, HL_DB_SMEM_BYTES>>>();
    cudaStreamWaitEvent(0, evB2, 0);
    k6_attn<<<dim3(Hh,Nn), 256, K6_SMEM_BYTES>>>(adj, out);
}

// round 15
// speedup vs baseline: 5.1462x; 1.0021x over previous
#include <cuda_runtime.h>
#include <cuda_bf16.h>
#include <math.h>
#include <stdint.h>

#define Nn 256
#define Pp 4
#define Sr 40
#define Enn 60
#define Ee 105
#define Dd 1024
#define Hh 8
#define Tt 3
#define DHd 128
#define HT 24           // H*T
#define NEGV -1e30f

// ---------------- scratch (device globals; no allocations allowed) ----------------
static __device__ __nv_bfloat16 g_Xh[Nn*Ee*Dd];   // bf16 hi split of X
static __device__ __nv_bfloat16 g_Xl[Nn*Ee*Dd];   // bf16 lo split of X
static __device__ float g_mask[Nn*Ee];
static __device__ int   g_rowidx[Nn*Ee];          // compacted active-row list
static __device__ int   g_nactive;                // count
static __device__ __nv_bfloat16 g_qh[Nn*Dd];      // q split
static __device__ __nv_bfloat16 g_ql[Nn*Dd];
static __device__ __nv_bfloat16 g_q1h[HT*256*Dd]; // qW1^T split: [ht][n=256][k=1024]
static __device__ __nv_bfloat16 g_q1l[HT*256*Dd];
static __device__ __nv_bfloat16 g_q2h[HT*256*256]; // qW2^T split: [ht][n=256][k=256]
static __device__ __nv_bfloat16 g_q2l[HT*256*256];
static __device__ float g_R [HT*Nn*256];          // relu(q @ qW1)
static __device__ float g_V [2*HT*Nn*DHd];        // v1 (r=ht), v2 (r=24+ht)  fp32
static __device__ float g_U [2*HT*Nn*Dd];         // u = W @ v (fp32)
static __device__ float g_F [2*HT*Nn*Ee];         // f1, f2  [r][n][e]
static __device__ __nv_bfloat16 g_WBh[Dd*Dd];     // W[:,T-1]^T as [N=1024][K=1024] bf16 hi
static __device__ __nv_bfloat16 g_WBl[Dd*Dd];     // lo
static __device__ float g_HL[Nn*Ee*Dd];           // h_last (pre-mask) (110 MB)

__device__ __forceinline__ void split2(float x, float y, __nv_bfloat162* ph, __nv_bfloat162* pl) {
    __nv_bfloat162 h, l;
    h.x = __float2bfloat16(x);
    h.y = __float2bfloat16(y);
    l.x = __float2bfloat16(x - __bfloat162float(h.x));
    l.y = __float2bfloat16(y - __bfloat162float(h.y));
    *ph = h; *pl = l;
}

// ---------------- K1: concat x (vectorized, bf16 hi/lo only) ----------------
__global__ void k_concat(const float* __restrict__ q, const float* __restrict__ para,
                         const float* __restrict__ sent, const float* __restrict__ ent) {
    int idx = (blockIdx.x * blockDim.x + threadIdx.x) * 4;
    if (idx >= Nn*Ee*Dd) return;
    int d  = idx & (Dd-1);
    int ne = idx >> 10;
    int e  = ne % Ee;
    int n  = ne / Ee;
    const float* src;
    if (e == 0)              src = q    + (size_t)n*Dd + d;
    else if (e < 1+Pp)       src = para + (size_t)(n*Pp  + (e-1))*Dd + d;
    else if (e < 1+Pp+Sr)    src = sent + (size_t)(n*Sr  + (e-1-Pp))*Dd + d;
    else                     src = ent  + (size_t)(n*Enn + (e-1-Pp-Sr))*Dd + d;
    float4 v = *(const float4*)(src);
    __nv_bfloat162 h01, h23, l01, l23;
    split2(v.x, v.y, &h01, &l01);
    split2(v.z, v.w, &h23, &l23);
    ((__nv_bfloat162*)(g_Xh + idx))[0] = h01;
    ((__nv_bfloat162*)(g_Xh + idx))[1] = h23;
    ((__nv_bfloat162*)(g_Xl + idx))[0] = l01;
    ((__nv_bfloat162*)(g_Xl + idx))[1] = l23;
}

__global__ void k_mask(const float* __restrict__ pm, const float* __restrict__ sm_,
                       const float* __restrict__ em) {
    int idx = blockIdx.x * blockDim.x + threadIdx.x;
    if (idx >= Nn*Ee) return;
    int e = idx % Ee, n = idx / Ee;
    float v;
    if (e == 0)            v = 1.f;
    else if (e < 1+Pp)     v = pm[n*Pp  + e-1];
    else if (e < 1+Pp+Sr)  v = sm_[n*Sr + e-1-Pp];
    else                   v = em[n*Enn + e-1-Pp-Sr];
    g_mask[idx] = v;
}

__global__ void k_compact_reset() {
    if (threadIdx.x == 0 && blockIdx.x == 0) g_nactive = 0;
}
__global__ void k_compact() {
    int idx = blockIdx.x * blockDim.x + threadIdx.x;
    if (idx >= Nn*Ee) return;
    if (g_mask[idx] > 0.f) {
        int pos = atomicAdd(&g_nactive, 1);
        g_rowidx[pos] = idx;
    }
}

__global__ void k_split_q(const float* __restrict__ q) {
    int idx = blockIdx.x * blockDim.x + threadIdx.x;
    if (idx >= Nn*Dd) return;
    float v = q[idx];
    __nv_bfloat16 hi = __float2bfloat16(v);
    g_qh[idx] = hi;
    g_ql[idx] = __float2bfloat16(v - __bfloat162float(hi));
}

// transpose+split qW1: [ht][k=1024][n=256] -> [ht][n=256][k=1024]
__global__ void k_tsplit_qw1(const float* __restrict__ qW1) {
    __shared__ float t[32][33];
    int ht = blockIdx.z;
    int k0 = blockIdx.x*32, n0 = blockIdx.y*32;
    int tx = threadIdx.x, ty = threadIdx.y;     // 32x8
    const float* src = qW1 + (size_t)ht*Dd*256;
    #pragma unroll
    for (int j = 0; j < 4; j++)
        t[ty+8*j][tx] = src[(size_t)(k0+ty+8*j)*256 + n0 + tx];
    __syncthreads();
    #pragma unroll
    for (int j = 0; j < 4; j++) {
        int nrow = n0 + ty + 8*j;
        int kcol = k0 + tx;
        float v = t[tx][ty+8*j];
        __nv_bfloat16 hi = __float2bfloat16(v);
        size_t o = (size_t)ht*256*Dd + (size_t)nrow*Dd + kcol;
        g_q1h[o] = hi;
        g_q1l[o] = __float2bfloat16(v - __bfloat162float(hi));
    }
}

// transpose+split qW2: [ht][k=256][n=256] -> [ht][n=256][k=256]
__global__ void k_tsplit_qw2(const float* __restrict__ qW2) {
    __shared__ float t[32][33];
    int ht = blockIdx.z;
    int k0 = blockIdx.x*32, n0 = blockIdx.y*32;
    int tx = threadIdx.x, ty = threadIdx.y;     // 32x8
    const float* src = qW2 + (size_t)ht*256*256;
    #pragma unroll
    for (int j = 0; j < 4; j++)
        t[ty+8*j][tx] = src[(size_t)(k0+ty+8*j)*256 + n0 + tx];
    __syncthreads();
    #pragma unroll
    for (int j = 0; j < 4; j++) {
        int nrow = n0 + ty + 8*j;
        int kcol = k0 + tx;
        float v = t[tx][ty+8*j];
        __nv_bfloat16 hi = __float2bfloat16(v);
        size_t o = (size_t)ht*256*256 + (size_t)nrow*256 + kcol;
        g_q2h[o] = hi;
        g_q2l[o] = __float2bfloat16(v - __bfloat162float(hi));
    }
}

// ---------------- shared mma bits ----------------
#define HLP 72
#define HL_TILE_ELEMS (128*HLP)
#define HL_SMEM_BYTES (4*HL_TILE_ELEMS*2)
#define HL_IDX_BYTES 1024
// A double-buffered (2 buf x hi/lo), B single-buffered (hi/lo): 6 tiles total
#define HL_DB_SMEM_BYTES (HL_IDX_BYTES + 6*HL_TILE_ELEMS*2)   // 111,616

__device__ __forceinline__ void mma16816(float* c, const uint32_t* a, uint32_t b0, uint32_t b1) {
    asm volatile(
        "mma.sync.aligned.m16n8k16.row.col.f32.bf16.bf16.f32 "
        "{%0,%1,%2,%3}, {%4,%5,%6,%7}, {%8,%9}, {%0,%1,%2,%3};"
        : "+f"(c[0]), "+f"(c[1]), "+f"(c[2]), "+f"(c[3])
        : "r"(a[0]), "r"(a[1]), "r"(a[2]), "r"(a[3]), "r"(b0), "r"(b1));
}

__device__ __forceinline__ void cp16(void* dst, const void* src) {
    uint32_t d = (uint32_t)__cvta_generic_to_shared(dst);
    asm volatile("cp.async.ca.shared.global [%0], [%1], 16;" :: "r"(d), "l"(src));
}
#define CP_COMMIT() asm volatile("cp.async.commit_group;")
#define CP_WAIT1()  asm volatile("cp.async.wait_group 1;")
#define CP_WAIT0()  asm volatile("cp.async.wait_group 0;")

// ---------------- K2a: R = relu(q @ qW1[ht]^T) via mma clone (round-9 proven) ----------------
__global__ __launch_bounds__(256) void k_qw1_mma() {
    extern __shared__ __nv_bfloat16 sm[];
    __nv_bfloat16* sAh = sm;
    __nv_bfloat16* sAl = sm + HL_TILE_ELEMS;
    __nv_bfloat16* sBh = sm + 2*HL_TILE_ELEMS;
    __nv_bfloat16* sBl = sm + 3*HL_TILE_ELEMS;
    int tid = threadIdx.x;
    int warp = tid >> 5, lane = tid & 31;
    int wm = warp & 3, wn = warp >> 2;
    int g = lane >> 2, tg = lane & 3;
    int n0 = blockIdx.x * 128;
    int m0 = blockIdx.y * 128;
    int ht = blockIdx.z;

    const __nv_bfloat16* Ahb = g_qh + (size_t)m0 * Dd;
    const __nv_bfloat16* Alb = g_ql + (size_t)m0 * Dd;
    const __nv_bfloat16* Bhb = g_q1h + (size_t)ht*256*Dd + (size_t)n0 * Dd;
    const __nv_bfloat16* Blb = g_q1l + (size_t)ht*256*Dd + (size_t)n0 * Dd;

    float acc[2][8][4];
    #pragma unroll
    for (int i=0;i<2;i++)
        #pragma unroll
        for (int j=0;j<8;j++)
            #pragma unroll
            for (int q=0;q<4;q++) acc[i][j][q] = 0.f;

    int sr = tid >> 3;
    int sc = (tid & 7) * 8;

    for (int kc = 0; kc < 16; kc++) {
        #pragma unroll
        for (int it = 0; it < 4; it++) {
            int r = sr + it*32;
            size_t go = (size_t)r * Dd + kc*64 + sc;
            int so = r * HLP + sc;
            *(uint4*)(sAh + so) = *(const uint4*)(Ahb + go);
            *(uint4*)(sAl + so) = *(const uint4*)(Alb + go);
            *(uint4*)(sBh + so) = *(const uint4*)(Bhb + go);
            *(uint4*)(sBl + so) = *(const uint4*)(Blb + go);
        }
        __syncthreads();
        #pragma unroll
        for (int ks = 0; ks < 4; ks++) {
            int kb = ks * 16;
            uint32_t ah[2][4], al[2][4];
            #pragma unroll
            for (int mi = 0; mi < 2; mi++) {
                int row = wm*32 + mi*16 + g;
                const __nv_bfloat16* p0 = sAh + row*HLP + kb + tg*2;
                const __nv_bfloat16* p1 = sAh + (row+8)*HLP + kb + tg*2;
                ah[mi][0] = *(const uint32_t*)(p0);
                ah[mi][1] = *(const uint32_t*)(p1);
                ah[mi][2] = *(const uint32_t*)(p0 + 8);
                ah[mi][3] = *(const uint32_t*)(p1 + 8);
                const __nv_bfloat16* q0 = sAl + row*HLP + kb + tg*2;
                const __nv_bfloat16* q1 = sAl + (row+8)*HLP + kb + tg*2;
                al[mi][0] = *(const uint32_t*)(q0);
                al[mi][1] = *(const uint32_t*)(q1);
                al[mi][2] = *(const uint32_t*)(q0 + 8);
                al[mi][3] = *(const uint32_t*)(q1 + 8);
            }
            #pragma unroll
            for (int nj = 0; nj < 8; nj++) {
                int col = wn*64 + nj*8 + g;
                const __nv_bfloat16* pb = sBh + col*HLP + kb + tg*2;
                const __nv_bfloat16* pl = sBl + col*HLP + kb + tg*2;
                uint32_t bh0 = *(const uint32_t*)(pb);
                uint32_t bh1 = *(const uint32_t*)(pb + 8);
                uint32_t bl0 = *(const uint32_t*)(pl);
                uint32_t bl1 = *(const uint32_t*)(pl + 8);
                #pragma unroll
                for (int mi = 0; mi < 2; mi++) {
                    mma16816(acc[mi][nj], ah[mi], bh0, bh1);
                    mma16816(acc[mi][nj], ah[mi], bl0, bl1);
                    mma16816(acc[mi][nj], al[mi], bh0, bh1);
                }
            }
        }
        __syncthreads();
    }

    float* Cb = g_R + (size_t)ht*Nn*256;
    #pragma unroll
    for (int mi = 0; mi < 2; mi++) {
        int row = m0 + wm*32 + mi*16 + g;
        #pragma unroll
        for (int nj = 0; nj < 8; nj++) {
            int col = n0 + wn*64 + nj*8 + tg*2;
            *(float2*)(&Cb[(size_t)row*256 + col]) =
                make_float2(fmaxf(acc[mi][nj][0], 0.f), fmaxf(acc[mi][nj][1], 0.f));
            *(float2*)(&Cb[(size_t)(row+8)*256 + col]) =
                make_float2(fmaxf(acc[mi][nj][2], 0.f), fmaxf(acc[mi][nj][3], 0.f));
        }
    }
}

// ---------------- K2b: V = sigmoid(R @ qW2^T) * a via mma clone (KCHUNKS=4) ----------------
__global__ __launch_bounds__(256) void k_qw2_mma(const float* __restrict__ a_in) {
    extern __shared__ __nv_bfloat16 sm[];
    __nv_bfloat16* sAh = sm;
    __nv_bfloat16* sAl = sm + HL_TILE_ELEMS;
    __nv_bfloat16* sBh = sm + 2*HL_TILE_ELEMS;
    __nv_bfloat16* sBl = sm + 3*HL_TILE_ELEMS;
    int tid = threadIdx.x;
    int warp = tid >> 5, lane = tid & 31;
    int wm = warp & 3, wn = warp >> 2;
    int g = lane >> 2, tg = lane & 3;
    int n0 = blockIdx.x * 128;
    int m0 = blockIdx.y * 128;
    int ht = blockIdx.z;

    const float* Ab = g_R + (size_t)ht*Nn*256 + (size_t)m0*256;
    const __nv_bfloat16* Bhb = g_q2h + (size_t)ht*256*256 + (size_t)n0 * 256;
    const __nv_bfloat16* Blb = g_q2l + (size_t)ht*256*256 + (size_t)n0 * 256;

    float acc[2][8][4];
    #pragma unroll
    for (int i=0;i<2;i++)
        #pragma unroll
        for (int j=0;j<8;j++)
            #pragma unroll
            for (int q=0;q<4;q++) acc[i][j][q] = 0.f;

    int sr = tid >> 3;
    int sc = (tid & 7) * 8;

    for (int kc = 0; kc < 4; kc++) {
        #pragma unroll
        for (int it = 0; it < 4; it++) {
            int r = sr + it*32;
            const float* pa = Ab + (size_t)r * 256 + kc*64 + sc;
            size_t gb = (size_t)r * 256 + kc*64 + sc;
            int so = r * HLP + sc;
            #pragma unroll
            for (int jj = 0; jj < 8; jj += 4) {
                float4 va = *(const float4*)(pa + jj);
                split2(va.x, va.y, (__nv_bfloat162*)(sAh + so + jj),     (__nv_bfloat162*)(sAl + so + jj));
                split2(va.z, va.w, (__nv_bfloat162*)(sAh + so + jj + 2), (__nv_bfloat162*)(sAl + so + jj + 2));
            }
            *(uint4*)(sBh + so) = *(const uint4*)(Bhb + gb);
            *(uint4*)(sBl + so) = *(const uint4*)(Blb + gb);
        }
        __syncthreads();
        #pragma unroll
        for (int ks = 0; ks < 4; ks++) {
            int kb = ks * 16;
            uint32_t ah[2][4], al[2][4];
            #pragma unroll
            for (int mi = 0; mi < 2; mi++) {
                int row = wm*32 + mi*16 + g;
                const __nv_bfloat16* p0 = sAh + row*HLP + kb + tg*2;
                const __nv_bfloat16* p1 = sAh + (row+8)*HLP + kb + tg*2;
                ah[mi][0] = *(const uint32_t*)(p0);
                ah[mi][1] = *(const uint32_t*)(p1);
                ah[mi][2] = *(const uint32_t*)(p0 + 8);
                ah[mi][3] = *(const uint32_t*)(p1 + 8);
                const __nv_bfloat16* q0 = sAl + row*HLP + kb + tg*2;
                const __nv_bfloat16* q1 = sAl + (row+8)*HLP + kb + tg*2;
                al[mi][0] = *(const uint32_t*)(q0);
                al[mi][1] = *(const uint32_t*)(q1);
                al[mi][2] = *(const uint32_t*)(q0 + 8);
                al[mi][3] = *(const uint32_t*)(q1 + 8);
            }
            #pragma unroll
            for (int nj = 0; nj < 8; nj++) {
                int col = wn*64 + nj*8 + g;
                const __nv_bfloat16* pb = sBh + col*HLP + kb + tg*2;
                const __nv_bfloat16* pl = sBl + col*HLP + kb + tg*2;
                uint32_t bh0 = *(const uint32_t*)(pb);
                uint32_t bh1 = *(const uint32_t*)(pb + 8);
                uint32_t bl0 = *(const uint32_t*)(pl);
                uint32_t bl1 = *(const uint32_t*)(pl + 8);
                #pragma unroll
                for (int mi = 0; mi < 2; mi++) {
                    mma16816(acc[mi][nj], ah[mi], bh0, bh1);
                    mma16816(acc[mi][nj], ah[mi], bl0, bl1);
                    mma16816(acc[mi][nj], al[mi], bh0, bh1);
                }
            }
        }
        __syncthreads();
    }

    const float* av = a_in + ht*256;
    #pragma unroll
    for (int mi = 0; mi < 2; mi++) {
        #pragma unroll
        for (int nj = 0; nj < 8; nj++) {
            #pragma unroll
            for (int q = 0; q < 4; q++) {
                int row = m0 + wm*32 + mi*16 + g + (q >= 2 ? 8 : 0);
                int col = n0 + wn*64 + nj*8 + tg*2 + (q & 1);
                float s = 1.f / (1.f + __expf(-acc[mi][nj][q]));
                float val = s * av[col];
                int r = (col < DHd) ? ht : (HT + ht);
                int k = col & (DHd-1);
                g_V[((size_t)r*Nn + row)*DHd + k] = val;
            }
        }
    }
}

// ---------------- K3: U[r] = V[r] @ W[ht]^T via mma (round-8 proven clone) ----------------
__global__ __launch_bounds__(256) void k_u_mma(const float* __restrict__ W) {
    extern __shared__ __nv_bfloat16 sm[];
    __nv_bfloat16* sAh = sm;
    __nv_bfloat16* sAl = sm + HL_TILE_ELEMS;
    __nv_bfloat16* sBh = sm + 2*HL_TILE_ELEMS;
    __nv_bfloat16* sBl = sm + 3*HL_TILE_ELEMS;
    int tid = threadIdx.x;
    int warp = tid >> 5, lane = tid & 31;
    int wm = warp & 3, wn = warp >> 2;
    int g = lane >> 2, tg = lane & 3;
    int n0 = blockIdx.x * 128;
    int m0 = blockIdx.y * 128;
    int r  = blockIdx.z;
    int ht = r % HT;

    const float* Ab = g_V + (size_t)r*Nn*DHd + (size_t)m0*DHd;
    const float* Bb = W   + (size_t)ht*Dd*DHd + (size_t)n0*DHd;

    float acc[2][8][4];
    #pragma unroll
    for (int i=0;i<2;i++)
        #pragma unroll
        for (int j=0;j<8;j++)
            #pragma unroll
            for (int q=0;q<4;q++) acc[i][j][q] = 0.f;

    int sr = tid >> 3;
    int sc = (tid & 7) * 8;

    for (int kc = 0; kc < 2; kc++) {
        #pragma unroll
        for (int it = 0; it < 4; it++) {
            int rr = sr + it*32;
            const float* pa = Ab + (size_t)rr*DHd + kc*64 + sc;
            const float* pb = Bb + (size_t)rr*DHd + kc*64 + sc;
            int so = rr * HLP + sc;
            #pragma unroll
            for (int jj = 0; jj < 8; jj += 4) {
                float4 va = *(const float4*)(pa + jj);
                split2(va.x, va.y, (__nv_bfloat162*)(sAh + so + jj),     (__nv_bfloat162*)(sAl + so + jj));
                split2(va.z, va.w, (__nv_bfloat162*)(sAh + so + jj + 2), (__nv_bfloat162*)(sAl + so + jj + 2));
                float4 vb = *(const float4*)(pb + jj);
                split2(vb.x, vb.y, (__nv_bfloat162*)(sBh + so + jj),     (__nv_bfloat162*)(sBl + so + jj));
                split2(vb.z, vb.w, (__nv_bfloat162*)(sBh + so + jj + 2), (__nv_bfloat162*)(sBl + so + jj + 2));
            }
        }
        __syncthreads();
        #pragma unroll
        for (int ks = 0; ks < 4; ks++) {
            int kb = ks * 16;
            uint32_t ah[2][4], al[2][4];
            #pragma unroll
            for (int mi = 0; mi < 2; mi++) {
                int row = wm*32 + mi*16 + g;
                const __nv_bfloat16* p0 = sAh + row*HLP + kb + tg*2;
                const __nv_bfloat16* p1 = sAh + (row+8)*HLP + kb + tg*2;
                ah[mi][0] = *(const uint32_t*)(p0);
                ah[mi][1] = *(const uint32_t*)(p1);
                ah[mi][2] = *(const uint32_t*)(p0 + 8);
                ah[mi][3] = *(const uint32_t*)(p1 + 8);
                const __nv_bfloat16* q0 = sAl + row*HLP + kb + tg*2;
                const __nv_bfloat16* q1 = sAl + (row+8)*HLP + kb + tg*2;
                al[mi][0] = *(const uint32_t*)(q0);
                al[mi][1] = *(const uint32_t*)(q1);
                al[mi][2] = *(const uint32_t*)(q0 + 8);
                al[mi][3] = *(const uint32_t*)(q1 + 8);
            }
            #pragma unroll
            for (int nj = 0; nj < 8; nj++) {
                int col = wn*64 + nj*8 + g;
                const __nv_bfloat16* pb = sBh + col*HLP + kb + tg*2;
                const __nv_bfloat16* pl = sBl + col*HLP + kb + tg*2;
                uint32_t bh0 = *(const uint32_t*)(pb);
                uint32_t bh1 = *(const uint32_t*)(pb + 8);
                uint32_t bl0 = *(const uint32_t*)(pl);
                uint32_t bl1 = *(const uint32_t*)(pl + 8);
                #pragma unroll
                for (int mi = 0; mi < 2; mi++) {
                    mma16816(acc[mi][nj], ah[mi], bh0, bh1);
                    mma16816(acc[mi][nj], ah[mi], bl0, bl1);
                    mma16816(acc[mi][nj], al[mi], bh0, bh1);
                }
            }
        }
        __syncthreads();
    }

    #pragma unroll
    for (int mi = 0; mi < 2; mi++) {
        int row = m0 + wm*32 + mi*16 + g;
        #pragma unroll
        for (int nj = 0; nj < 8; nj++) {
            int col = n0 + wn*64 + nj*8 + tg*2;
            *(float2*)(&g_U[(size_t)r*Nn*Dd + (size_t)row*Dd + col])     = make_float2(acc[mi][nj][0], acc[mi][nj][1]);
            *(float2*)(&g_U[(size_t)r*Nn*Dd + (size_t)(row+8)*Dd + col]) = make_float2(acc[mi][nj][2], acc[mi][nj][3]);
        }
    }
}

// ---------------- K4: F via mma (round-9 proven) ----------------
__global__ __launch_bounds__(256) void k_f_mma() {
    extern __shared__ __nv_bfloat16 sm[];
    __nv_bfloat16* sAh = sm;
    __nv_bfloat16* sAl = sm + HL_TILE_ELEMS;
    __nv_bfloat16* sBh = sm + 2*HL_TILE_ELEMS;
    __nv_bfloat16* sBl = sm + 3*HL_TILE_ELEMS;
    int n = blockIdx.x;
    int tid = threadIdx.x;
    int warp = tid >> 5, lane = tid & 31;
    int wm = warp & 3, wn = warp >> 2;
    int g = lane >> 2, tg = lane & 3;

    float acc[2][3][4];
    #pragma unroll
    for (int i=0;i<2;i++)
        #pragma unroll
        for (int j=0;j<3;j++)
            #pragma unroll
            for (int q=0;q<4;q++) acc[i][j][q] = 0.f;

    int sr = tid >> 3;
    int sc = (tid & 7) * 8;
    const __nv_bfloat16* Ahb = g_Xh + (size_t)n * Ee * Dd;
    const __nv_bfloat16* Alb = g_Xl + (size_t)n * Ee * Dd;

    for (int kc = 0; kc < 16; kc++) {
        #pragma unroll
        for (int it = 0; it < 4; it++) {
            int r = sr + it*32;
            int rc = (r < Ee) ? r : (Ee-1);
            size_t go = (size_t)rc * Dd + kc*64 + sc;
            int so = r * HLP + sc;
            *(uint4*)(sAh + so) = *(const uint4*)(Ahb + go);
            *(uint4*)(sAl + so) = *(const uint4*)(Alb + go);
        }
        for (int i = tid; i < 384; i += 256) {
            int r = i >> 3, c = (i & 7) * 8;
            const float* pb = g_U + (size_t)r*(Nn*Dd) + (size_t)n*Dd + kc*64 + c;
            int so = r * HLP + c;
            #pragma unroll
            for (int jj = 0; jj < 8; jj += 4) {
                float4 vb = *(const float4*)(pb + jj);
                split2(vb.x, vb.y, (__nv_bfloat162*)(sBh + so + jj),     (__nv_bfloat162*)(sBl + so + jj));
                split2(vb.z, vb.w, (__nv_bfloat162*)(sBh + so + jj + 2), (__nv_bfloat162*)(sBl + so + jj + 2));
            }
        }
        __syncthreads();
        #pragma unroll
        for (int ks = 0; ks < 4; ks++) {
            int kb = ks * 16;
            uint32_t ah[2][4], al[2][4];
            #pragma unroll
            for (int mi = 0; mi < 2; mi++) {
                int row = wm*32 + mi*16 + g;
                const __nv_bfloat16* p0 = sAh + row*HLP + kb + tg*2;
                const __nv_bfloat16* p1 = sAh + (row+8)*HLP + kb + tg*2;
                ah[mi][0] = *(const uint32_t*)(p0);
                ah[mi][1] = *(const uint32_t*)(p1);
                ah[mi][2] = *(const uint32_t*)(p0 + 8);
                ah[mi][3] = *(const uint32_t*)(p1 + 8);
                const __nv_bfloat16* q0 = sAl + row*HLP + kb + tg*2;
                const __nv_bfloat16* q1 = sAl + (row+8)*HLP + kb + tg*2;
                al[mi][0] = *(const uint32_t*)(q0);
                al[mi][1] = *(const uint32_t*)(q1);
                al[mi][2] = *(const uint32_t*)(q0 + 8);
                al[mi][3] = *(const uint32_t*)(q1 + 8);
            }
            #pragma unroll
            for (int nj = 0; nj < 3; nj++) {
                int col = wn*24 + nj*8 + g;
                const __nv_bfloat16* pb = sBh + col*HLP + kb + tg*2;
                const __nv_bfloat16* pl = sBl + col*HLP + kb + tg*2;
                uint32_t bh0 = *(const uint32_t*)(pb);
                uint32_t bh1 = *(const uint32_t*)(pb + 8);
                uint32_t bl0 = *(const uint32_t*)(pl);
                uint32_t bl1 = *(const uint32_t*)(pl + 8);
                #pragma unroll
                for (int mi = 0; mi < 2; mi++) {
                    mma16816(acc[mi][nj], ah[mi], bh0, bh1);
                    mma16816(acc[mi][nj], ah[mi], bl0, bl1);
                    mma16816(acc[mi][nj], al[mi], bh0, bh1);
                }
            }
        }
        __syncthreads();
    }

    #pragma unroll
    for (int mi = 0; mi < 2; mi++) {
        int e0 = wm*32 + mi*16 + g;
        #pragma unroll
        for (int nj = 0; nj < 3; nj++) {
            int r = wn*24 + nj*8 + tg*2;
            if (e0 < Ee) {
                g_F[(size_t)r*Nn*Ee + n*Ee + e0]     = acc[mi][nj][0];
                g_F[(size_t)(r+1)*Nn*Ee + n*Ee + e0] = acc[mi][nj][1];
            }
            if (e0 + 8 < Ee) {
                g_F[(size_t)r*Nn*Ee + n*Ee + e0 + 8]     = acc[mi][nj][2];
                g_F[(size_t)(r+1)*Nn*Ee + n*Ee + e0 + 8] = acc[mi][nj][3];
            }
        }
    }
}

// ---------------- K5a: repack W[:, T-1]^T into [N=1024][K=1024] bf16 hi/lo ----
__global__ void k_repack_bf(const float* __restrict__ W) {
    int idx = blockIdx.x * blockDim.x + threadIdx.x;
    if (idx >= Dd*Dd) return;
    int d = idx & 1023, col = idx >> 10;         // out[col][d]
    int h = col >> 7, k = col & 127;
    float v = W[((size_t)(h*Tt + (Tt-1))*Dd + d)*DHd + k];
    __nv_bfloat16 hi = __float2bfloat16(v);
    g_WBh[idx] = hi;
    g_WBl[idx] = __float2bfloat16(v - __bfloat162float(hi));
}

// ---------------- K5b: HL = X @ WB^T, active rows; A double-buf, B single-buf (2 blk/SM) --
__global__ __launch_bounds__(256) void k_hl_mma() {
    extern __shared__ char smraw[];
    int* ridx = (int*)smraw;
    __nv_bfloat16* smbuf = (__nv_bfloat16*)(smraw + HL_IDX_BYTES);
    // layout: bufA0 (hi,lo) | bufA1 (hi,lo) | B (hi,lo)  — 6 tiles
    int tid = threadIdx.x;
    int warp = tid >> 5, lane = tid & 31;
    int wm = warp & 3, wn = warp >> 2;
    int g = lane >> 2, tg = lane & 3;
    int n0 = blockIdx.x * 128;
    int mbase = blockIdx.y * 128;

    int count = g_nactive;
    if (mbase >= count) return;
    if (tid < 128) {
        int li = mbase + tid;
        ridx[tid] = g_rowidx[li < count ? li : (count-1)];
    }
    __syncthreads();

    const __nv_bfloat16* Bh0 = g_WBh + (size_t)n0 * Dd;
    const __nv_bfloat16* Bl0 = g_WBl + (size_t)n0 * Dd;
    __nv_bfloat16* sBh = smbuf + 4*HL_TILE_ELEMS;
    __nv_bfloat16* sBl = smbuf + 5*HL_TILE_ELEMS;

    float acc[2][8][4];
    #pragma unroll
    for (int i=0;i<2;i++)
        #pragma unroll
        for (int j=0;j<8;j++)
            #pragma unroll
            for (int q=0;q<4;q++) acc[i][j][q] = 0.f;

    int sr = tid >> 3;
    int sc = (tid & 7) * 8;

    #define HL_A_ISSUE(kc, b) do {                                                 \
        __nv_bfloat16* base = smbuf + (b)*(2*HL_TILE_ELEMS);                       \
        _Pragma("unroll")                                                          \
        for (int it = 0; it < 4; it++) {                                           \
            int r = sr + it*32;                                                    \
            size_t ga = (size_t)ridx[r] * Dd + (kc)*64 + sc;                       \
            int so = r * HLP + sc;                                                 \
            cp16(base + so,                 g_Xh + ga);                            \
            cp16(base + HL_TILE_ELEMS + so, g_Xl + ga);                            \
        }                                                                          \
        CP_COMMIT();                                                               \
    } while (0)

    #define HL_B_ISSUE(kc) do {                                                    \
        _Pragma("unroll")                                                          \
        for (int it = 0; it < 4; it++) {                                           \
            int r = sr + it*32;                                                    \
            size_t gb = (size_t)r * Dd + (kc)*64 + sc;                             \
            int so = r * HLP + sc;                                                 \
            cp16(sBh + so, Bh0 + gb);                                              \
            cp16(sBl + so, Bl0 + gb);                                              \
        }                                                                          \
        CP_COMMIT();                                                               \
    } while (0)

    HL_A_ISSUE(0, 0);
    for (int kc = 0; kc < 16; kc++) {
        // B buffer is free here (post-sync of previous iteration)
        HL_B_ISSUE(kc);
        if (kc < 15) { HL_A_ISSUE(kc+1, (kc+1)&1); CP_WAIT1(); }   // waits A(kc)+B(kc), leaves A(kc+1)
        else         { CP_WAIT0(); }
        __syncthreads();
        __nv_bfloat16* baseA = smbuf + (kc&1)*(2*HL_TILE_ELEMS);
        __nv_bfloat16* sAh = baseA;
        __nv_bfloat16* sAl = baseA + HL_TILE_ELEMS;
        #pragma unroll
        for (int ks = 0; ks < 4; ks++) {
            int kb = ks * 16;
            uint32_t ah[2][4], al[2][4];
            #pragma unroll
            for (int mi = 0; mi < 2; mi++) {
                int row = wm*32 + mi*16 + g;
                const __nv_bfloat16* p0 = sAh + row*HLP + kb + tg*2;
                const __nv_bfloat16* p1 = sAh + (row+8)*HLP + kb + tg*2;
                ah[mi][0] = *(const uint32_t*)(p0);
                ah[mi][1] = *(const uint32_t*)(p1);
                ah[mi][2] = *(const uint32_t*)(p0 + 8);
                ah[mi][3] = *(const uint32_t*)(p1 + 8);
                const __nv_bfloat16* q0 = sAl + row*HLP + kb + tg*2;
                const __nv_bfloat16* q1 = sAl + (row+8)*HLP + kb + tg*2;
                al[mi][0] = *(const uint32_t*)(q0);
                al[mi][1] = *(const uint32_t*)(q1);
                al[mi][2] = *(const uint32_t*)(q0 + 8);
                al[mi][3] = *(const uint32_t*)(q1 + 8);
            }
            #pragma unroll
            for (int nj = 0; nj < 8; nj++) {
                int col = wn*64 + nj*8 + g;
                const __nv_bfloat16* pb = sBh + col*HLP + kb + tg*2;
                const __nv_bfloat16* pl = sBl + col*HLP + kb + tg*2;
                uint32_t bh0 = *(const uint32_t*)(pb);
                uint32_t bh1 = *(const uint32_t*)(pb + 8);
                uint32_t bl0 = *(const uint32_t*)(pl);
                uint32_t bl1 = *(const uint32_t*)(pl + 8);
                #pragma unroll
                for (int mi = 0; mi < 2; mi++) {
                    mma16816(acc[mi][nj], ah[mi], bh0, bh1);
                    mma16816(acc[mi][nj], ah[mi], bl0, bl1);
                    mma16816(acc[mi][nj], al[mi], bh0, bh1);
                }
            }
        }
        __syncthreads();   // all warps done with B buffer before next overwrite
    }
    #undef HL_A_ISSUE
    #undef HL_B_ISSUE

    #pragma unroll
    for (int mi = 0; mi < 2; mi++) {
        int rl = wm*32 + mi*16 + g;
        size_t row0 = (size_t)ridx[rl];
        size_t row1 = (size_t)ridx[rl + 8];
        #pragma unroll
        for (int nj = 0; nj < 8; nj++) {
            int col = n0 + wn*64 + nj*8 + tg*2;
            *(float2*)(&g_HL[row0 * Dd + col]) = make_float2(acc[mi][nj][0], acc[mi][nj][1]);
            *(float2*)(&g_HL[row1 * Dd + col]) = make_float2(acc[mi][nj][2], acc[mi][nj][3]);
        }
    }
}

// ---------------- K6: score + softmax + TC aggregate, 2-phase B (round-14 proven) ----------
#define K6P 120
#define K6_A_TILE (128*K6P)
#define K6_B_TILE (64*K6P)
#define K6_F_OFF 0
#define K6_BF_OFF 2560
#define K6_SMEM_BYTES (K6_BF_OFF + (2*K6_A_TILE + 2*K6_B_TILE)*2)   // 94720

__device__ __forceinline__ float k6_score(int t, const float* f1s, const float* f2s, int i, int j) {
    if (t > 0) {
        float v = f1s[(t-1)*Ee + i] + f2s[(t-1)*Ee + j];
        return v > 0.f ? v : 0.2f*v;
    }
    return NEGV;
}

__global__ __launch_bounds__(256, 2) void k6_attn(const int* __restrict__ adj, float* __restrict__ out) {
    int h = blockIdx.x, n = blockIdx.y;
    extern __shared__ char smraw[];
    float* f1s = (float*)(smraw + K6_F_OFF);
    float* f2s = f1s + Tt*Ee;
    __nv_bfloat16* sAh = (__nv_bfloat16*)(smraw + K6_BF_OFF);
    __nv_bfloat16* sAl = sAh + K6_A_TILE;
    __nv_bfloat16* sBh = sAl + K6_A_TILE;
    __nv_bfloat16* sBl = sBh + K6_B_TILE;
    int tid = threadIdx.x;
    int w = tid >> 5, lane = tid & 31;

    {
        uint4 z = make_uint4(0,0,0,0);
        uint4* p = (uint4*)(smraw + K6_BF_OFF);
        for (int i = tid; i < ((2*K6_A_TILE + 2*K6_B_TILE)*2)/16; i += 256) p[i] = z;
    }
    for (int i = tid; i < Tt*Ee; i += 256) {
        int t = i / Ee, e = i % Ee;
        f1s[i] = g_F[(size_t)(h*Tt+t)*Nn*Ee + n*Ee + e];
        f2s[i] = g_F[(size_t)HT*Nn*Ee + (size_t)(h*Tt+t)*Nn*Ee + n*Ee + e];
    }
    __syncthreads();

    const int* adjn = adj + n*Ee*Ee;
    for (int ig = 0; ig < 14; ig++) {
        int i = ig*8 + w;
        if (i < Ee) {
            const int* arow = adjn + i*Ee;
            float s0 = k6_score(arow[lane],    f1s, f2s, i, lane);
            float s1 = k6_score(arow[lane+32], f1s, f2s, i, lane+32);
            float s2 = k6_score(arow[lane+64], f1s, f2s, i, lane+64);
            float s3 = (lane < 9) ? k6_score(arow[lane+96], f1s, f2s, i, lane+96) : -INFINITY;
            float m = fmaxf(fmaxf(s0, s1), fmaxf(s2, s3));
            #pragma unroll
            for (int o = 16; o > 0; o >>= 1) m = fmaxf(m, __shfl_xor_sync(0xffffffffu, m, o));
            float p0 = __expf(s0 - m), p1 = __expf(s1 - m), p2 = __expf(s2 - m);
            float p3 = (lane < 9) ? __expf(s3 - m) : 0.f;
            float sum = p0 + p1 + p2 + p3;
            #pragma unroll
            for (int o = 16; o > 0; o >>= 1) sum += __shfl_xor_sync(0xffffffffu, sum, o);
            float inv = 1.f / sum;
            float c0 = p0*inv, c1 = p1*inv, c2 = p2*inv;
            __nv_bfloat16 hi;
            hi = __float2bfloat16(c0);
            sAh[i*K6P + lane] = hi;      sAl[i*K6P + lane]      = __float2bfloat16(c0 - __bfloat162float(hi));
            hi = __float2bfloat16(c1);
            sAh[i*K6P + lane + 32] = hi; sAl[i*K6P + lane + 32] = __float2bfloat16(c1 - __bfloat162float(hi));
            hi = __float2bfloat16(c2);
            sAh[i*K6P + lane + 64] = hi; sAl[i*K6P + lane + 64] = __float2bfloat16(c2 - __bfloat162float(hi));
            if (lane < 9) {
                float c3 = p3*inv;
                hi = __float2bfloat16(c3);
                sAh[i*K6P + lane + 96] = hi; sAl[i*K6P + lane + 96] = __float2bfloat16(c3 - __bfloat162float(hi));
            }
        }
    }

    int g = lane >> 2, tg = lane & 3;
    float acc[16][4];
    #pragma unroll
    for (int j = 0; j < 16; j++)
        #pragma unroll
        for (int q = 0; q < 4; q++) acc[j][q] = 0.f;

    const float* mk = g_mask + n*Ee;
    #pragma unroll
    for (int p = 0; p < 2; p++) {
        {
            int d = tid & 63, quarter = tid >> 6;
            const float* hlb = g_HL + (size_t)n*Ee*Dd + h*DHd + p*64 + d;
            for (int j = quarter; j < Ee; j += 4) {
                float v = hlb[(size_t)j*Dd] * mk[j];
                __nv_bfloat16 hi = __float2bfloat16(v);
                sBh[d*K6P + j] = hi;
                sBl[d*K6P + j] = __float2bfloat16(v - __bfloat162float(hi));
            }
        }
        __syncthreads();
        for (int kc = 0; kc < 7; kc++) {
            int kb = kc*16;
            int row = w*16 + g;
            uint32_t ah[4], al[4];
            const __nv_bfloat16* p0 = sAh + row*K6P + kb + tg*2;
            const __nv_bfloat16* p1 = sAh + (row+8)*K6P + kb + tg*2;
            ah[0] = *(const uint32_t*)(p0);
            ah[1] = *(const uint32_t*)(p1);
            ah[2] = *(const uint32_t*)(p0 + 8);
            ah[3] = *(const uint32_t*)(p1 + 8);
            const __nv_bfloat16* q0 = sAl + row*K6P + kb + tg*2;
            const __nv_bfloat16* q1 = sAl + (row+8)*K6P + kb + tg*2;
            al[0] = *(const uint32_t*)(q0);
            al[1] = *(const uint32_t*)(q1);
            al[2] = *(const uint32_t*)(q0 + 8);
            al[3] = *(const uint32_t*)(q1 + 8);
            #pragma unroll
            for (int nj = 0; nj < 8; nj++) {
                int col = nj*8 + g;
                const __nv_bfloat16* pb = sBh + col*K6P + kb + tg*2;
                const __nv_bfloat16* pl = sBl + col*K6P + kb + tg*2;
                uint32_t bh0 = *(const uint32_t*)(pb);
                uint32_t bh1 = *(const uint32_t*)(pb + 8);
                uint32_t bl0 = *(const uint32_t*)(pl);
                uint32_t bl1 = *(const uint32_t*)(pl + 8);
                mma16816(acc[p*8+nj], ah, bh0, bh1);
                mma16816(acc[p*8+nj], ah, bl0, bl1);
                mma16816(acc[p*8+nj], al, bh0, bh1);
            }
        }
        __syncthreads();
    }

    #pragma unroll
    for (int rr = 0; rr < 2; rr++) {
        int i = w*16 + rr*8 + g;
        if (i < Ee) {
            size_t rowo = (size_t)(n*Ee + i)*Dd + h*DHd;
            #pragma unroll
            for (int nj = 0; nj < 16; nj++) {
                int col = nj*8 + tg*2;
                __nv_bfloat162 xh = *(const __nv_bfloat162*)(&g_Xh[rowo + col]);
                __nv_bfloat162 xl = *(const __nv_bfloat162*)(&g_Xl[rowo + col]);
                float x0 = __bfloat162float(xh.x) + __bfloat162float(xl.x);
                float x1 = __bfloat162float(xh.y) + __bfloat162float(xl.y);
                float v0 = fmaxf(acc[nj][rr*2+0], 0.f) + x0;
                float v1 = fmaxf(acc[nj][rr*2+1], 0.f) + x1;
                *(float2*)(&out[rowo + col]) = make_float2(v0, v1);
            }
        }
    }
}

// ---------------- launch (fork-join dual-stream graph) ----------------
extern "C" void kernel_launch(void* const* d_in, const int* in_sizes, int n_in,
                              void* d_out, int out_size) {
    const float* q    = (const float*)d_in[0];
    const float* para = (const float*)d_in[1];
    const float* sent = (const float*)d_in[2];
    const float* ent  = (const float*)d_in[3];
    const float* pm   = (const float*)d_in[4];
    const float* sm_  = (const float*)d_in[5];
    const float* em   = (const float*)d_in[6];
    const int*   adj  = (const int*)  d_in[7];
    const float* W    = (const float*)d_in[8];
    const float* a    = (const float*)d_in[9];
    const float* qW1  = (const float*)d_in[10];
    const float* qW2  = (const float*)d_in[11];
    float* out = (float*)d_out;

    static cudaStream_t sB = nullptr;
    static cudaEvent_t evFork = nullptr, evA1 = nullptr, evB1 = nullptr, evB2 = nullptr;
    if (sB == nullptr) {
        cudaStreamCreateWithFlags(&sB, cudaStreamNonBlocking);
        cudaEventCreateWithFlags(&evFork, cudaEventDisableTiming);
        cudaEventCreateWithFlags(&evA1,   cudaEventDisableTiming);
        cudaEventCreateWithFlags(&evB1,   cudaEventDisableTiming);
        cudaEventCreateWithFlags(&evB2,   cudaEventDisableTiming);
        cudaFuncSetAttribute(k6_attn,   cudaFuncAttributeMaxDynamicSharedMemorySize, K6_SMEM_BYTES);
        cudaFuncSetAttribute(k_hl_mma,  cudaFuncAttributeMaxDynamicSharedMemorySize, HL_DB_SMEM_BYTES);
        cudaFuncSetAttribute(k_u_mma,   cudaFuncAttributeMaxDynamicSharedMemorySize, HL_SMEM_BYTES);
        cudaFuncSetAttribute(k_qw1_mma, cudaFuncAttributeMaxDynamicSharedMemorySize, HL_SMEM_BYTES);
        cudaFuncSetAttribute(k_qw2_mma, cudaFuncAttributeMaxDynamicSharedMemorySize, HL_SMEM_BYTES);
        cudaFuncSetAttribute(k_f_mma,   cudaFuncAttributeMaxDynamicSharedMemorySize, HL_SMEM_BYTES);
    }

    cudaEventRecord(evFork, 0);
    cudaStreamWaitEvent(sB, evFork, 0);

    // ---- stream A (legacy): X-side chain ----
    k_concat<<<(Nn*Ee*Dd/4 + 255)/256, 256>>>(q, para, sent, ent);
    cudaEventRecord(evA1, 0);                       // X splits ready (for f_mma)
    k_mask<<<(Nn*Ee + 255)/256, 256>>>(pm, sm_, em);
    k_compact_reset<<<1, 1>>>();
    k_compact<<<(Nn*Ee + 255)/256, 256>>>();

    // ---- stream B: q-side chain ----
    k_repack_bf<<<(Dd*Dd + 255)/256, 256, 0, sB>>>(W);
    cudaEventRecord(evB1, sB);                      // WB ready (for hl)
    k_split_q<<<(Nn*Dd + 255)/256, 256, 0, sB>>>(q);
    k_tsplit_qw1<<<dim3(32, 8, HT), dim3(32, 8), 0, sB>>>(qW1);
    k_tsplit_qw2<<<dim3(8, 8, HT), dim3(32, 8), 0, sB>>>(qW2);
    k_qw1_mma<<<dim3(2,2,HT), 256, HL_SMEM_BYTES, sB>>>();
    k_qw2_mma<<<dim3(2,2,HT), 256, HL_SMEM_BYTES, sB>>>(a);
    k_u_mma<<<dim3(8,2,2*HT), 256, HL_SMEM_BYTES, sB>>>(W);
    cudaStreamWaitEvent(sB, evA1, 0);               // f needs X splits
    k_f_mma<<<Nn, 256, HL_SMEM_BYTES, sB>>>();
    cudaEventRecord(evB2, sB);

    // ---- stream A: hl (needs concat + compact + repack) then join + k6 ----
    cudaStreamWaitEvent(0, evB1, 0);
    k_hl_mma<<<dim3(8,210), 256, HL_DB_SMEM_BYTES>>>();
    cudaStreamWaitEvent(0, evB2, 0);
    k6_attn<<<dim3(Hh,Nn), 256, K6_SMEM_BYTES>>>(adj, out);
}